// round 2
// baseline (speedup 1.0000x reference)
#include <cuda_runtime.h>
#include <cstdint>

// ---------------- constants ----------------
#define MEANC 0.1307f
#define STDC  0.3081f
#define NIN   784
#define NH    2048
#define NOUT  10

// ---------------- scratch (device globals; no allocation allowed) ----------------
__device__ float g_bufh[2][NH * NH];
__device__ float g_bufl[2][NH * NH];
__device__ float g_xa[NH];
__device__ float g_xb[NH];
__device__ float g_low[NH];
__device__ float g_high[NH];
__device__ float g_wl[4 * NH];
__device__ float g_wh[4 * NH];
__device__ float g_bhr[4 * NH];
__device__ float g_bh[NH];
__device__ float g_bl[NH];
__device__ float g_x0[NIN];
__device__ float g_l0[NIN];
__device__ float g_h0[NIN];

// ---------------- helpers ----------------
__device__ __forceinline__ void blkred2(float& a, float& b) {
    const unsigned full = 0xffffffffu;
    #pragma unroll
    for (int o = 16; o > 0; o >>= 1) {
        a += __shfl_down_sync(full, a, o);
        b += __shfl_down_sync(full, b, o);
    }
    __shared__ float sa[8], sb[8];
    int w = threadIdx.x >> 5, lane = threadIdx.x & 31;
    if (lane == 0) { sa[w] = a; sb[w] = b; }
    __syncthreads();
    if (w == 0) {
        a = (lane < 8) ? sa[lane] : 0.f;
        b = (lane < 8) ? sb[lane] : 0.f;
        #pragma unroll
        for (int o = 4; o > 0; o >>= 1) {
            a += __shfl_down_sync(full, a, o);
            b += __shfl_down_sync(full, b, o);
        }
    }
}

// ---------------- kernels ----------------
__global__ void normalize_k(const float* __restrict__ x, const float* __restrict__ lo,
                            const float* __restrict__ hi,
                            float* __restrict__ x0, float* __restrict__ l0,
                            float* __restrict__ h0, int n) {
    int i = blockIdx.x * blockDim.x + threadIdx.x;
    if (i < n) {
        x0[i] = (x[i] - MEANC) / STDC;
        l0[i] = (lo[i] - MEANC) / STDC;
        h0[i] = (hi[i] - MEANC) / STDC;
    }
}

// x_out = W @ x_in + b ; one warp per row
__global__ void matvec_k(const float* __restrict__ W, const float* __restrict__ xin,
                         const float* __restrict__ b, float* __restrict__ xout,
                         int M, int K) {
    int row = blockIdx.x * (blockDim.x >> 5) + (threadIdx.x >> 5);
    if (row >= M) return;
    int lane = threadIdx.x & 31;
    float s = 0.f;
    const float* wr = W + (size_t)row * K;
    for (int k = lane; k < K; k += 32) s += wr[k] * xin[k];
    #pragma unroll
    for (int o = 16; o > 0; o >>= 1) s += __shfl_down_sync(0xffffffffu, s, o);
    if (lane == 0) xout[row] = s + b[row];
}

// Fused relu-backsub transform + relu bias + following-linear bias.
//   oh = (mh>0 ? mh*wh : mh*wl)*mask ; ol = (ml>0 ? ml*wl : ml*wh)*mask ; mask=(wh!=0)
//   bh[m] (+)= sum_k max(mh,0)*mask*bhr[k] + oh*bj[k]
//   bl[m] (+)= sum_k min(ml,0)*mask*bhr[k] + ol*bj[k]
// binit != nullptr -> initialize bh/bl = binit[m] + partial (first step of a chain)
// Safe with src == dst (pure elementwise on the matrices).
__global__ void relu_linear_backsub_k(const float* __restrict__ srch, const float* __restrict__ srcl,
                                      float* __restrict__ dsth, float* __restrict__ dstl,
                                      const float* __restrict__ wld, const float* __restrict__ whd,
                                      const float* __restrict__ bhrd, const float* __restrict__ bj,
                                      float* __restrict__ bh, float* __restrict__ bl,
                                      const float* __restrict__ binit, int K) {
    int m = blockIdx.x;
    size_t base = (size_t)m * K;
    float sh = 0.f, sl = 0.f;
    for (int k = threadIdx.x; k < K; k += blockDim.x) {
        float whk = whd[k], wlk = wld[k], brk = bhrd[k], bjk = bj[k];
        float mask = (whk != 0.f) ? 1.f : 0.f;
        float mh = srch[base + k], ml = srcl[base + k];
        float oh = (mh > 0.f ? mh * whk : mh * wlk) * mask;
        float ol = (ml > 0.f ? ml * wlk : ml * whk) * mask;
        dsth[base + k] = oh;
        dstl[base + k] = ol;
        sh += fmaxf(mh, 0.f) * mask * brk + oh * bjk;
        sl += fminf(ml, 0.f) * mask * brk + ol * bjk;
    }
    blkred2(sh, sl);
    if (threadIdx.x == 0) {
        if (binit) { bh[m] = binit[m] + sh; bl[m] = binit[m] + sl; }
        else       { bh[m] += sh;           bl[m] += sl; }
    }
}

// Final interval evaluation against the input box.
__global__ void box_k(const float* __restrict__ Ah, const float* __restrict__ Al,
                      const float* __restrict__ bh, const float* __restrict__ bl,
                      const float* __restrict__ l0, const float* __restrict__ h0,
                      float* __restrict__ lowv, float* __restrict__ highv, int K) {
    int m = blockIdx.x;
    size_t base = (size_t)m * K;
    float sh = 0.f, sl = 0.f;
    for (int k = threadIdx.x; k < K; k += blockDim.x) {
        float l0k = l0[k], h0k = h0[k];
        float ah = Ah[base + k];
        sh += (ah >= 0.f) ? ah * h0k : ah * l0k;
        float al = Al[base + k];
        sl += (al >= 0.f) ? al * l0k : al * h0k;
    }
    blkred2(sh, sl);
    if (threadIdx.x == 0) {
        highv[m] = bh[m] + sh;
        lowv[m]  = bl[m] + sl;
    }
}

// DeepPoly relu relaxation -> per-neuron diagonals; x <- max(x,0) in place.
__global__ void relu_abs_k(float* __restrict__ x, const float* __restrict__ lowv,
                           const float* __restrict__ highv,
                           float* __restrict__ wl, float* __restrict__ wh,
                           float* __restrict__ bhr, int n) {
    int i = blockIdx.x * blockDim.x + threadIdx.x;
    if (i >= n) return;
    float l = lowv[i], h = highv[i];
    bool crossing = (l < 0.f) && (h > 0.f);
    float denom = crossing ? (h - l) : 1.f;
    float ubs = crossing ? h / denom : 0.f;
    float ubi = crossing ? -(l * h) / denom : 0.f;
    float lam = (l * l > h * h) ? 0.f : 1.f;
    float keep = (h <= 0.f) ? 0.f : 1.f;
    wh[i]  = crossing ? ubs : keep;
    wl[i]  = crossing ? lam : keep;
    bhr[i] = ubi;
    x[i] = fmaxf(x[i], 0.f);
}

__global__ void write_out_k(const float* __restrict__ x5, const float* __restrict__ lowv,
                            const float* __restrict__ highv, float* __restrict__ out) {
    int i = threadIdx.x;
    if (i < NOUT) {
        out[i]          = x5[i];
        out[NOUT + i]   = lowv[i];
        out[2*NOUT + i] = highv[i];
    }
}

// ---------------- SGEMM: C = A(MxK) @ B(KxN), all row-major, K % 8 == 0, N % 4 == 0
__global__ void __launch_bounds__(256) sgemm_k(int M, int N, int K,
                                               const float* __restrict__ A,
                                               const float* __restrict__ B,
                                               float* __restrict__ C) {
    __shared__ float As[8][128];
    __shared__ float Bs[8][128];
    const int tid = threadIdx.x;
    const int tx = tid & 15;
    const int ty = tid >> 4;
    const int row0 = blockIdx.y * 128;
    const int col0 = blockIdx.x * 128;

    const int a_row = tid >> 1;
    const int a_col = (tid & 1) << 2;
    const int b_row = tid >> 5;
    const int b_colo = (tid & 31) << 2;

    const int gArow = row0 + a_row;
    const bool aValid = gArow < M;
    const int gBcol = col0 + b_colo;
    const bool bValid = gBcol < N;

    float acc[8][8];
    #pragma unroll
    for (int i = 0; i < 8; ++i)
        #pragma unroll
        for (int j = 0; j < 8; ++j) acc[i][j] = 0.f;

    for (int k0 = 0; k0 < K; k0 += 8) {
        float4 av = aValid ? *reinterpret_cast<const float4*>(A + (size_t)gArow * K + k0 + a_col)
                           : make_float4(0.f, 0.f, 0.f, 0.f);
        As[a_col + 0][a_row] = av.x;
        As[a_col + 1][a_row] = av.y;
        As[a_col + 2][a_row] = av.z;
        As[a_col + 3][a_row] = av.w;
        float4 bv = bValid ? *reinterpret_cast<const float4*>(B + (size_t)(k0 + b_row) * N + gBcol)
                           : make_float4(0.f, 0.f, 0.f, 0.f);
        *reinterpret_cast<float4*>(&Bs[b_row][b_colo]) = bv;
        __syncthreads();
        #pragma unroll
        for (int kk = 0; kk < 8; ++kk) {
            float4 a0 = *reinterpret_cast<const float4*>(&As[kk][ty * 8]);
            float4 a1 = *reinterpret_cast<const float4*>(&As[kk][ty * 8 + 4]);
            float4 b0 = *reinterpret_cast<const float4*>(&Bs[kk][tx * 8]);
            float4 b1 = *reinterpret_cast<const float4*>(&Bs[kk][tx * 8 + 4]);
            float ar[8] = {a0.x, a0.y, a0.z, a0.w, a1.x, a1.y, a1.z, a1.w};
            float br[8] = {b0.x, b0.y, b0.z, b0.w, b1.x, b1.y, b1.z, b1.w};
            #pragma unroll
            for (int i = 0; i < 8; ++i)
                #pragma unroll
                for (int j = 0; j < 8; ++j)
                    acc[i][j] += ar[i] * br[j];
        }
        __syncthreads();
    }

    #pragma unroll
    for (int i = 0; i < 8; ++i) {
        int r = row0 + ty * 8 + i;
        if (r >= M) continue;
        #pragma unroll
        for (int j = 0; j < 8; j += 4) {
            int c = col0 + tx * 8 + j;
            if (c < N) {
                float4 v = make_float4(acc[i][j], acc[i][j + 1], acc[i][j + 2], acc[i][j + 3]);
                *reinterpret_cast<float4*>(C + (size_t)r * N + c) = v;
            }
        }
    }
}

// ---------------- driver ----------------
extern "C" void kernel_launch(void* const* d_in, const int* in_sizes, int n_in,
                              void* d_out, int out_size) {
    const float* x  = (const float*)d_in[0];
    const float* lo = (const float*)d_in[1];
    const float* hi = (const float*)d_in[2];
    const float* W[5];
    const float* b[5];
    for (int i = 0; i < 5; ++i) {
        W[i] = (const float*)d_in[3 + 2 * i];
        b[i] = (const float*)d_in[4 + 2 * i];
    }
    float* out = (float*)d_out;

    void* p;
    float *bufh[2], *bufl[2];
    cudaGetSymbolAddress(&p, g_bufh); bufh[0] = (float*)p; bufh[1] = bufh[0] + (size_t)NH * NH;
    cudaGetSymbolAddress(&p, g_bufl); bufl[0] = (float*)p; bufl[1] = bufl[0] + (size_t)NH * NH;
    float *xa, *xb, *lowv, *highv, *wl, *wh, *bhr, *bh, *bl, *x0, *l0, *h0;
    cudaGetSymbolAddress(&p, g_xa);   xa = (float*)p;
    cudaGetSymbolAddress(&p, g_xb);   xb = (float*)p;
    cudaGetSymbolAddress(&p, g_low);  lowv = (float*)p;
    cudaGetSymbolAddress(&p, g_high); highv = (float*)p;
    cudaGetSymbolAddress(&p, g_wl);   wl = (float*)p;
    cudaGetSymbolAddress(&p, g_wh);   wh = (float*)p;
    cudaGetSymbolAddress(&p, g_bhr);  bhr = (float*)p;
    cudaGetSymbolAddress(&p, g_bh);   bh = (float*)p;
    cudaGetSymbolAddress(&p, g_bl);   bl = (float*)p;
    cudaGetSymbolAddress(&p, g_x0);   x0 = (float*)p;
    cudaGetSymbolAddress(&p, g_l0);   l0 = (float*)p;
    cudaGetSymbolAddress(&p, g_h0);   h0 = (float*)p;

    normalize_k<<<(NIN + 255) / 256, 256>>>(x, lo, hi, x0, l0, h0, NIN);

    // ---- layer 1 (index 0): backsub chain is just W1 itself ----
    matvec_k<<<NH / 8, 256>>>(W[0], x0, b[0], xa, NH, NIN);
    box_k<<<NH, 256>>>(W[0], W[0], b[0], b[0], l0, h0, lowv, highv, NIN);
    relu_abs_k<<<NH / 256, 256>>>(xa, lowv, highv, wl + 0 * NH, wh + 0 * NH, bhr + 0 * NH, NH);

    float* xin = xa;
    float* xout = xb;
    for (int i = 1; i < 5; ++i) {
        int M = (i == 4) ? NOUT : NH;
        matvec_k<<<(M + 7) / 8, 256>>>(W[i], xin, b[i], xout, M, NH);

        const float* srch = W[i];
        const float* srcl = W[i];
        int cur = 0;
        bool first = true;
        for (int j = i - 1; j >= 0; --j) {
            float* th = bufh[cur];
            float* tl = bufl[cur];
            relu_linear_backsub_k<<<M, 256>>>(srch, srcl, th, tl,
                                              wl + j * NH, wh + j * NH, bhr + j * NH, b[j],
                                              bh, bl, first ? b[i] : nullptr, NH);
            int Ng = (j == 0) ? NIN : NH;
            dim3 grid((Ng + 127) / 128, (M + 127) / 128);
            float* oh = bufh[cur ^ 1];
            float* ol = bufl[cur ^ 1];
            sgemm_k<<<grid, 256>>>(M, Ng, NH, th, W[j], oh);
            sgemm_k<<<grid, 256>>>(M, Ng, NH, tl, W[j], ol);
            srch = oh;
            srcl = ol;
            cur ^= 1;
            first = false;
        }
        box_k<<<M, 256>>>(srch, srcl, bh, bl, l0, h0, lowv, highv, NIN);
        if (i < 4) {
            relu_abs_k<<<NH / 256, 256>>>(xout, lowv, highv,
                                          wl + i * NH, wh + i * NH, bhr + i * NH, NH);
            float* t = xin; xin = xout; xout = t;
        } else {
            write_out_k<<<1, 32>>>(xout, lowv, highv, out);
        }
    }
    (void)in_sizes; (void)n_in; (void)out_size;
}

// round 4
// speedup vs baseline: 3.8129x; 3.8129x over previous
#include <cuda_runtime.h>
#include <cuda_bf16.h>
#include <cstdint>

#define MEANC 0.1307f
#define STDC  0.3081f
#define NIN   784
#define NH    2048
#define NOUT  10
#define NHNH  (NH * NH)

// ---------------- device scratch ----------------
__device__ __nv_bfloat16 g_Abf[4][NHNH];   // AHhi, AHlo, ALhi, ALlo
__device__ __nv_bfloat16 g_WTh[4][NHNH];
__device__ __nv_bfloat16 g_WTl[4][NHNH];
__device__ float g_CH[NHNH];
__device__ float g_CL[NHNH];
__device__ float g_sA[2][NOUT * NH];
__device__ float g_sC[2][NOUT * NH];
__device__ float g_part[2][8 * NOUT * NH];
__device__ float g_xa[NH], g_xb[NH], g_low[NH], g_high[NH];
__device__ float g_wl[4 * NH], g_wh[4 * NH], g_bhr[4 * NH];
__device__ float g_bh[NH], g_bl[NH];
__device__ float g_x0[NIN], g_l0[NIN], g_h0[NIN];

// ---------------- helpers ----------------
__device__ __forceinline__ uint32_t smem_u32(const void* p) {
    uint32_t a;
    asm("{ .reg .u64 t; cvta.to.shared.u64 t, %1; cvt.u32.u64 %0, t; }" : "=r"(a) : "l"(p));
    return a;
}

__device__ __forceinline__ void blkred2(float& a, float& b) {
    const unsigned F = 0xffffffffu;
    #pragma unroll
    for (int o = 16; o > 0; o >>= 1) { a += __shfl_down_sync(F, a, o); b += __shfl_down_sync(F, b, o); }
    __shared__ float sa[8], sb[8];
    int w = threadIdx.x >> 5, lane = threadIdx.x & 31;
    if (lane == 0) { sa[w] = a; sb[w] = b; }
    __syncthreads();
    if (w == 0) {
        a = (lane < 8) ? sa[lane] : 0.f;
        b = (lane < 8) ? sb[lane] : 0.f;
        #pragma unroll
        for (int o = 4; o > 0; o >>= 1) { a += __shfl_down_sync(F, a, o); b += __shfl_down_sync(F, b, o); }
    }
}

// ---------------- small kernels ----------------
__global__ void normalize_k(const float* x, const float* lo, const float* hi,
                            float* x0, float* l0, float* h0, int n) {
    int i = blockIdx.x * blockDim.x + threadIdx.x;
    if (i < n) {
        x0[i] = (x[i] - MEANC) / STDC;
        l0[i] = (lo[i] - MEANC) / STDC;
        h0[i] = (hi[i] - MEANC) / STDC;
    }
}

__global__ void matvec_k(const float* __restrict__ W, const float* __restrict__ xin,
                         const float* __restrict__ b, float* __restrict__ xout, int M, int K) {
    int row = blockIdx.x * (blockDim.x >> 5) + (threadIdx.x >> 5);
    if (row >= M) return;
    int lane = threadIdx.x & 31;
    float s = 0.f;
    const float* wr = W + (size_t)row * K;
    for (int k = lane; k < K; k += 32) s += wr[k] * xin[k];
    #pragma unroll
    for (int o = 16; o > 0; o >>= 1) s += __shfl_down_sync(0xffffffffu, s, o);
    if (lane == 0) xout[row] = s + b[row];
}

__global__ void relu_bs_f32_k(const float* __restrict__ srch, const float* __restrict__ srcl,
                              float* __restrict__ dsth, float* __restrict__ dstl,
                              const float* __restrict__ wld, const float* __restrict__ whd,
                              const float* __restrict__ bhrd, const float* __restrict__ bj,
                              float* __restrict__ bh, float* __restrict__ bl,
                              const float* __restrict__ binit, int K) {
    int m = blockIdx.x;
    size_t base = (size_t)m * K;
    float sh = 0.f, sl = 0.f;
    for (int k = threadIdx.x; k < K; k += blockDim.x) {
        float whk = whd[k], wlk = wld[k], brk = bhrd[k], bjk = bj[k];
        float mask = (whk != 0.f) ? 1.f : 0.f;
        float mh = srch[base + k], ml = srcl[base + k];
        float oh = (mh > 0.f ? mh * whk : mh * wlk) * mask;
        float ol = (ml > 0.f ? ml * wlk : ml * whk) * mask;
        dsth[base + k] = oh;
        dstl[base + k] = ol;
        sh += fmaxf(mh, 0.f) * mask * brk + oh * bjk;
        sl += fminf(ml, 0.f) * mask * brk + ol * bjk;
    }
    blkred2(sh, sl);
    if (threadIdx.x == 0) {
        if (binit) { bh[m] = binit[m] + sh; bl[m] = binit[m] + sl; }
        else       { bh[m] += sh;           bl[m] += sl; }
    }
}

// relu-backsub transform emitting split bf16 A operands
__global__ void relu_bs_split_k(const float* __restrict__ srch, const float* __restrict__ srcl,
                                __nv_bfloat16* __restrict__ Ab,
                                const float* __restrict__ wld, const float* __restrict__ whd,
                                const float* __restrict__ bhrd, const float* __restrict__ bj,
                                float* __restrict__ bh, float* __restrict__ bl,
                                const float* __restrict__ binit) {
    int m = blockIdx.x;
    size_t base = (size_t)m * NH;
    __nv_bfloat16* ahh = Ab;
    __nv_bfloat16* ahl = Ab + (size_t)NHNH;
    __nv_bfloat16* alh = Ab + (size_t)2 * NHNH;
    __nv_bfloat16* all_ = Ab + (size_t)3 * NHNH;
    float sh = 0.f, sl = 0.f;
    for (int k = threadIdx.x; k < NH; k += blockDim.x) {
        float whk = whd[k], wlk = wld[k], brk = bhrd[k], bjk = bj[k];
        float mask = (whk != 0.f) ? 1.f : 0.f;
        float mh = srch[base + k], ml = srcl[base + k];
        float oh = (mh > 0.f ? mh * whk : mh * wlk) * mask;
        float ol = (ml > 0.f ? ml * wlk : ml * whk) * mask;
        __nv_bfloat16 h1 = __float2bfloat16(oh);
        ahh[base + k] = h1;
        ahl[base + k] = __float2bfloat16(oh - __bfloat162float(h1));
        __nv_bfloat16 h2 = __float2bfloat16(ol);
        alh[base + k] = h2;
        all_[base + k] = __float2bfloat16(ol - __bfloat162float(h2));
        sh += fmaxf(mh, 0.f) * mask * brk + oh * bjk;
        sl += fminf(ml, 0.f) * mask * brk + ol * bjk;
    }
    blkred2(sh, sl);
    if (threadIdx.x == 0) {
        if (binit) { bh[m] = binit[m] + sh; bl[m] = binit[m] + sl; }
        else       { bh[m] += sh;           bl[m] += sl; }
    }
}

__global__ void box_k(const float* __restrict__ Ah, const float* __restrict__ Al,
                      const float* __restrict__ bh, const float* __restrict__ bl,
                      const float* __restrict__ l0, const float* __restrict__ h0,
                      float* __restrict__ lowv, float* __restrict__ highv, int K, int ld) {
    int m = blockIdx.x;
    size_t base = (size_t)m * ld;
    float sh = 0.f, sl = 0.f;
    for (int k = threadIdx.x; k < K; k += blockDim.x) {
        float l0k = l0[k], h0k = h0[k];
        float ah = Ah[base + k];
        sh += (ah >= 0.f) ? ah * h0k : ah * l0k;
        float al = Al[base + k];
        sl += (al >= 0.f) ? al * l0k : al * h0k;
    }
    blkred2(sh, sl);
    if (threadIdx.x == 0) { highv[m] = bh[m] + sh; lowv[m] = bl[m] + sl; }
}

__global__ void relu_abs_k(float* __restrict__ x, const float* __restrict__ lowv,
                           const float* __restrict__ highv, float* __restrict__ wl,
                           float* __restrict__ wh, float* __restrict__ bhr, int n) {
    int i = blockIdx.x * blockDim.x + threadIdx.x;
    if (i >= n) return;
    float l = lowv[i], h = highv[i];
    bool cr = (l < 0.f) && (h > 0.f);
    float denom = cr ? (h - l) : 1.f;
    float ubs = cr ? h / denom : 0.f;
    float ubi = cr ? -(l * h) / denom : 0.f;
    float lam = (l * l > h * h) ? 0.f : 1.f;
    float keep = (h <= 0.f) ? 0.f : 1.f;
    wh[i] = cr ? ubs : keep;
    wl[i] = cr ? lam : keep;
    bhr[i] = ubi;
    x[i] = fmaxf(x[i], 0.f);
}

__global__ void write_out_k(const float* x5, const float* lowv, const float* highv, float* out) {
    int i = threadIdx.x;
    if (i < NOUT) { out[i] = x5[i]; out[NOUT + i] = lowv[i]; out[2 * NOUT + i] = highv[i]; }
}

// transpose + bf16 split: WT[n,k] = W[k*fi+n], zero-padded rows n>=fi
__global__ void wsplit_k(const float* __restrict__ W, __nv_bfloat16* __restrict__ Th,
                         __nv_bfloat16* __restrict__ Tl, int fi) {
    __shared__ float t[32][33];
    int tx = threadIdx.x, ty = threadIdx.y;
    int kb = blockIdx.y * 32, nb = blockIdx.x * 32;
    #pragma unroll
    for (int i = 0; i < 4; ++i) {
        int k = kb + ty + i * 8, n = nb + tx;
        t[ty + i * 8][tx] = (n < fi) ? W[(size_t)k * fi + n] : 0.f;
    }
    __syncthreads();
    #pragma unroll
    for (int i = 0; i < 4; ++i) {
        int n = nb + ty + i * 8, k = kb + tx;
        float v = t[tx][ty + i * 8];
        __nv_bfloat16 h = __float2bfloat16(v);
        Th[(size_t)n * NH + k] = h;
        Tl[(size_t)n * NH + k] = __float2bfloat16(v - __bfloat162float(h));
    }
}

// skinny fp32 GEMM partials for the M=10 chain
__global__ void __launch_bounds__(128) skinny_k(const float* __restrict__ AH, const float* __restrict__ AL,
                                                const float* __restrict__ W,
                                                float* __restrict__ PH, float* __restrict__ PL, int Ng) {
    __shared__ float sH[NOUT][128], sL[NOUT][128];
    int t = threadIdx.x;
    int n = blockIdx.x * 128 + t;
    int seg = blockIdx.y;
    float aH[NOUT], aL[NOUT];
    #pragma unroll
    for (int m = 0; m < NOUT; ++m) { aH[m] = 0.f; aL[m] = 0.f; }
    for (int k0 = seg * 256; k0 < seg * 256 + 256; k0 += 128) {
        __syncthreads();
        #pragma unroll
        for (int m = 0; m < NOUT; ++m) {
            sH[m][t] = AH[m * NH + k0 + t];
            sL[m][t] = AL[m * NH + k0 + t];
        }
        __syncthreads();
        if (n < Ng) {
            for (int kk = 0; kk < 128; ++kk) {
                float w = W[(size_t)(k0 + kk) * Ng + n];
                #pragma unroll
                for (int m = 0; m < NOUT; ++m) { aH[m] += sH[m][kk] * w; aL[m] += sL[m][kk] * w; }
            }
        }
    }
    if (n < Ng) {
        size_t pb = (size_t)seg * NOUT * NH;
        #pragma unroll
        for (int m = 0; m < NOUT; ++m) { PH[pb + m * NH + n] = aH[m]; PL[pb + m * NH + n] = aL[m]; }
    }
}

__global__ void sreduce_k(const float* __restrict__ PH, const float* __restrict__ PL,
                          float* __restrict__ CH, float* __restrict__ CL, int Ng) {
    int idx = blockIdx.x * blockDim.x + threadIdx.x;
    if (idx >= NOUT * Ng) return;
    int m = idx / Ng, n = idx % Ng;
    float sh = 0.f, sl = 0.f;
    #pragma unroll
    for (int s = 0; s < 8; ++s) {
        sh += PH[((size_t)s * NOUT + m) * NH + n];
        sl += PL[((size_t)s * NOUT + m) * NH + n];
    }
    CH[m * NH + n] = sh;
    CL[m * NH + n] = sl;
}

// ---------------- fused H/L bf16 split-2 GEMM via mma.sync (HMMA) ----------------
// C{H,L}[2048 x Ng] = A{H,L}[2048 x 2048] @ WT^T.  CTA tile 128x128 (both H and L),
// 8 warps: 0-3 -> H (2x2 of 64x64), 4-7 -> L. k-chunk 32, 3-stage cp.async pipeline.
#define ROWB  80                     // 32 bf16 = 64B data + 16B pad
#define MATB  (128 * ROWB)           // 10240
#define STAGE (6 * MATB)             // 61440
#define GSMEM (3 * STAGE)            // 184320

__device__ __forceinline__ void ldsm4(uint32_t* r, uint32_t addr) {
    asm volatile("ldmatrix.sync.aligned.m8n8.x4.shared.b16 {%0,%1,%2,%3}, [%4];"
                 : "=r"(r[0]), "=r"(r[1]), "=r"(r[2]), "=r"(r[3]) : "r"(addr));
}
__device__ __forceinline__ void mma16816(float* c, const uint32_t* a, const uint32_t* b) {
    asm volatile(
        "mma.sync.aligned.m16n8k16.row.col.f32.bf16.bf16.f32 "
        "{%0,%1,%2,%3}, {%4,%5,%6,%7}, {%8,%9}, {%0,%1,%2,%3};"
        : "+f"(c[0]), "+f"(c[1]), "+f"(c[2]), "+f"(c[3])
        : "r"(a[0]), "r"(a[1]), "r"(a[2]), "r"(a[3]), "r"(b[0]), "r"(b[1]));
}

__device__ __forceinline__ void issue_chunk(uint32_t sb, int slot,
                                            const __nv_bfloat16* Ab, const __nv_bfloat16* Bh,
                                            const __nv_bfloat16* Bl, int row0, int col0,
                                            int k0, int tid) {
    uint32_t sbase = sb + slot * STAGE;
    #pragma unroll
    for (int i = 0; i < 12; ++i) {
        int q = tid + (i << 8);
        int mat = q >> 9;            // 0..5
        int r = (q >> 2) & 127;      // row within tile
        int g = q & 3;               // 16B chunk within 64B row
        const __nv_bfloat16* src;
        int grow;
        if (mat < 4) { src = Ab + ((size_t)mat << 22); grow = row0 + r; }
        else         { src = (mat == 4) ? Bh : Bl;     grow = col0 + r; }
        const void* gp = src + (size_t)grow * NH + k0 + (g << 3);
        uint32_t sp = sbase + mat * MATB + r * ROWB + (g << 4);
        asm volatile("cp.async.cg.shared.global [%0], [%1], 16;" :: "r"(sp), "l"(gp));
    }
    asm volatile("cp.async.commit_group;" ::: "memory");
}

__global__ void __launch_bounds__(256) hgemm_k(const __nv_bfloat16* __restrict__ Ab,
                                               const __nv_bfloat16* __restrict__ Bh,
                                               const __nv_bfloat16* __restrict__ Bl,
                                               float* __restrict__ CH, float* __restrict__ CL,
                                               int Ng) {
    extern __shared__ char smem[];
    const uint32_t sb = smem_u32(smem);
    const int tid = threadIdx.x, lane = tid & 31, wid = tid >> 5;
    const int row0 = blockIdx.y * 128, col0 = blockIdx.x * 128;
    const int half = wid >> 2, wq = wid & 3;
    const int warpM = (wq & 1) << 6, warpN = (wq >> 1) << 6;

    float acc[4][8][4];
    #pragma unroll
    for (int mi = 0; mi < 4; ++mi)
        #pragma unroll
        for (int ni = 0; ni < 8; ++ni)
            #pragma unroll
            for (int e = 0; e < 4; ++e) acc[mi][ni][e] = 0.f;

    issue_chunk(sb, 0, Ab, Bh, Bl, row0, col0, 0, tid);
    issue_chunk(sb, 1, Ab, Bh, Bl, row0, col0, 32, tid);

    // precomputed lane address offsets (within a matrix tile, for k16-step 0)
    const uint32_t aoff = (uint32_t)((lane & 15) * ROWB + ((lane >> 4) << 4));
    const uint32_t boff = (uint32_t)(((((lane >> 4) & 1) << 3) + (lane & 7)) * ROWB + (((lane >> 3) & 1) << 4));

    const int CHUNKS = 64;
    for (int c = 0; c < CHUNKS; ++c) {
        asm volatile("cp.async.wait_group 1;" ::: "memory");
        __syncthreads();
        if (c + 2 < CHUNKS)
            issue_chunk(sb, (c + 2) % 3, Ab, Bh, Bl, row0, col0, (c + 2) * 32, tid);

        uint32_t st = sb + (c % 3) * STAGE;
        uint32_t sAh = st + (half * 2) * MATB + warpM * ROWB + aoff;
        uint32_t sAl = sAh + MATB;
        uint32_t sBh = st + 4 * MATB + warpN * ROWB + boff;
        uint32_t sBl = sBh + MATB;

        #pragma unroll
        for (int ks = 0; ks < 2; ++ks) {
            uint32_t ko = ks * 32;
            uint32_t aH[4][4], aL[4][4], bH[4][4], bL[4][4];
            #pragma unroll
            for (int mi = 0; mi < 4; ++mi) {
                ldsm4(aH[mi], sAh + mi * (16 * ROWB) + ko);
                ldsm4(aL[mi], sAl + mi * (16 * ROWB) + ko);
            }
            #pragma unroll
            for (int pi = 0; pi < 4; ++pi) {
                ldsm4(bH[pi], sBh + pi * (16 * ROWB) + ko);
                ldsm4(bL[pi], sBl + pi * (16 * ROWB) + ko);
            }
            #pragma unroll
            for (int mi = 0; mi < 4; ++mi) {
                #pragma unroll
                for (int ni = 0; ni < 8; ++ni) {
                    const uint32_t* bh = &bH[ni >> 1][(ni & 1) << 1];
                    const uint32_t* bl = &bL[ni >> 1][(ni & 1) << 1];
                    mma16816(acc[mi][ni], aH[mi], bh);
                    mma16816(acc[mi][ni], aL[mi], bh);
                    mma16816(acc[mi][ni], aH[mi], bl);
                }
            }
        }
    }

    float* C = half ? CL : CH;
    #pragma unroll
    for (int mi = 0; mi < 4; ++mi) {
        int gr = row0 + warpM + mi * 16 + (lane >> 2);
        #pragma unroll
        for (int ni = 0; ni < 8; ++ni) {
            int gc = col0 + warpN + ni * 8 + ((lane & 3) << 1);
            if (gc < Ng) {
                float2 v0 = make_float2(acc[mi][ni][0], acc[mi][ni][1]);
                float2 v1 = make_float2(acc[mi][ni][2], acc[mi][ni][3]);
                *reinterpret_cast<float2*>(C + (size_t)gr * Ng + gc) = v0;
                *reinterpret_cast<float2*>(C + (size_t)(gr + 8) * Ng + gc) = v1;
            }
        }
    }
}

// ---------------- driver ----------------
extern "C" void kernel_launch(void* const* d_in, const int* in_sizes, int n_in,
                              void* d_out, int out_size) {
    const float* x  = (const float*)d_in[0];
    const float* lo = (const float*)d_in[1];
    const float* hi = (const float*)d_in[2];
    const float* W[5];
    const float* b[5];
    for (int i = 0; i < 5; ++i) { W[i] = (const float*)d_in[3 + 2 * i]; b[i] = (const float*)d_in[4 + 2 * i]; }
    float* out = (float*)d_out;

    cudaFuncSetAttribute(hgemm_k, cudaFuncAttributeMaxDynamicSharedMemorySize, GSMEM);

    void* p;
    __nv_bfloat16 *Abf, *WTh, *WTl;
    cudaGetSymbolAddress(&p, g_Abf); Abf = (__nv_bfloat16*)p;
    cudaGetSymbolAddress(&p, g_WTh); WTh = (__nv_bfloat16*)p;
    cudaGetSymbolAddress(&p, g_WTl); WTl = (__nv_bfloat16*)p;
    float *CH, *CL, *sAH, *sAL, *sCH, *sCL, *PH, *PL;
    cudaGetSymbolAddress(&p, g_CH);   CH = (float*)p;
    cudaGetSymbolAddress(&p, g_CL);   CL = (float*)p;
    cudaGetSymbolAddress(&p, g_sA);   sAH = (float*)p; sAL = sAH + NOUT * NH;
    cudaGetSymbolAddress(&p, g_sC);   sCH = (float*)p; sCL = sCH + NOUT * NH;
    cudaGetSymbolAddress(&p, g_part); PH = (float*)p; PL = PH + 8 * NOUT * NH;
    float *xa, *xb, *lowv, *highv, *wl, *wh, *bhr, *bh, *bl, *x0, *l0, *h0;
    cudaGetSymbolAddress(&p, g_xa);   xa = (float*)p;
    cudaGetSymbolAddress(&p, g_xb);   xb = (float*)p;
    cudaGetSymbolAddress(&p, g_low);  lowv = (float*)p;
    cudaGetSymbolAddress(&p, g_high); highv = (float*)p;
    cudaGetSymbolAddress(&p, g_wl);   wl = (float*)p;
    cudaGetSymbolAddress(&p, g_wh);   wh = (float*)p;
    cudaGetSymbolAddress(&p, g_bhr);  bhr = (float*)p;
    cudaGetSymbolAddress(&p, g_bh);   bh = (float*)p;
    cudaGetSymbolAddress(&p, g_bl);   bl = (float*)p;
    cudaGetSymbolAddress(&p, g_x0);   x0 = (float*)p;
    cudaGetSymbolAddress(&p, g_l0);   l0 = (float*)p;
    cudaGetSymbolAddress(&p, g_h0);   h0 = (float*)p;

    normalize_k<<<(NIN + 255) / 256, 256>>>(x, lo, hi, x0, l0, h0, NIN);

    // transpose + split weights W0..W3 (B operands), W0 padded to 896 rows
    {
        dim3 blk(32, 8);
        wsplit_k<<<dim3(28, 64), blk>>>(W[0], WTh, WTl, NIN);
        for (int j = 1; j < 4; ++j)
            wsplit_k<<<dim3(64, 64), blk>>>(W[j], WTh + (size_t)j * NHNH, WTl + (size_t)j * NHNH, NH);
    }

    // layer 0
    matvec_k<<<NH / 8, 256>>>(W[0], x0, b[0], xa, NH, NIN);
    box_k<<<NH, 256>>>(W[0], W[0], b[0], b[0], l0, h0, lowv, highv, NIN, NIN);
    relu_abs_k<<<NH / 256, 256>>>(xa, lowv, highv, wl, wh, bhr, NH);

    float* xin = xa;
    float* xout = xb;
    // layers 1..3: tensor-core chains
    for (int i = 1; i < 4; ++i) {
        matvec_k<<<NH / 8, 256>>>(W[i], xin, b[i], xout, NH, NH);
        const float* srch = W[i];
        const float* srcl = W[i];
        bool first = true;
        for (int j = i - 1; j >= 0; --j) {
            relu_bs_split_k<<<NH, 256>>>(srch, srcl, Abf, wl + j * NH, wh + j * NH,
                                         bhr + j * NH, b[j], bh, bl, first ? b[i] : nullptr);
            int Ng = (j == 0) ? NIN : NH;
            int Nt = (j == 0) ? 7 : 16;
            hgemm_k<<<dim3(Nt, 16), 256, GSMEM>>>(Abf, WTh + (size_t)j * NHNH,
                                                  WTl + (size_t)j * NHNH, CH, CL, Ng);
            srch = CH; srcl = CL; first = false;
        }
        box_k<<<NH, 256>>>(CH, CL, bh, bl, l0, h0, lowv, highv, NIN, NIN);
        relu_abs_k<<<NH / 256, 256>>>(xout, lowv, highv, wl + i * NH, wh + i * NH, bhr + i * NH, NH);
        float* t = xin; xin = xout; xout = t;
    }

    // layer 4 (M=10): fp32 skinny chain
    matvec_k<<<2, 256>>>(W[4], xin, b[4], xout, NOUT, NH);
    {
        const float* srch = W[4];
        const float* srcl = W[4];
        bool first = true;
        for (int j = 3; j >= 0; --j) {
            relu_bs_f32_k<<<NOUT, 256>>>(srch, srcl, sAH, sAL, wl + j * NH, wh + j * NH,
                                         bhr + j * NH, b[j], bh, bl, first ? b[4] : nullptr, NH);
            int Ng = (j == 0) ? NIN : NH;
            skinny_k<<<dim3((Ng + 127) / 128, 8), 128>>>(sAH, sAL, W[j], PH, PL, Ng);
            sreduce_k<<<(NOUT * Ng + 255) / 256, 256>>>(PH, PL, sCH, sCL, Ng);
            srch = sCH; srcl = sCL; first = false;
        }
        box_k<<<NOUT, 256>>>(sCH, sCL, bh, bl, l0, h0, lowv, highv, NIN, NH);
        write_out_k<<<1, 32>>>(xout, lowv, highv, out);
    }
    (void)in_sizes; (void)n_in; (void)out_size;
}

// round 5
// speedup vs baseline: 4.9219x; 1.2908x over previous
#include <cuda_runtime.h>
#include <cuda_fp16.h>
#include <cstdint>

#define MEANC 0.1307f
#define STDC  0.3081f
#define NIN   784
#define NH    2048
#define NOUT  10
#define NHNH  (NH * NH)

// ---------------- device scratch ----------------
__device__ __half g_Af[2][NHNH];     // AH, AL (fp16, unsplit)
__device__ __half g_WTh[4][NHNH];    // weight^T hi
__device__ __half g_WTl[4][NHNH];    // weight^T residual
__device__ float g_CH[NHNH];
__device__ float g_CL[NHNH];
__device__ float g_sA[2][NOUT * NH];
__device__ float g_sC[2][NOUT * NH];
__device__ float g_part[2][8 * NOUT * NH];
__device__ float g_xa[NH], g_xb[NH], g_low[NH], g_high[NH];
__device__ float g_wl[4 * NH], g_wh[4 * NH], g_bhr[4 * NH];
__device__ float g_bh[NH], g_bl[NH];
__device__ float g_x0[NIN], g_l0[NIN], g_h0[NIN];

// ---------------- helpers ----------------
__device__ __forceinline__ uint32_t smem_u32(const void* p) {
    uint32_t a;
    asm("{ .reg .u64 t; cvta.to.shared.u64 t, %1; cvt.u32.u64 %0, t; }" : "=r"(a) : "l"(p));
    return a;
}

__device__ __forceinline__ void blkred2(float& a, float& b) {
    const unsigned F = 0xffffffffu;
    #pragma unroll
    for (int o = 16; o > 0; o >>= 1) { a += __shfl_down_sync(F, a, o); b += __shfl_down_sync(F, b, o); }
    __shared__ float sa[8], sb[8];
    int w = threadIdx.x >> 5, lane = threadIdx.x & 31;
    if (lane == 0) { sa[w] = a; sb[w] = b; }
    __syncthreads();
    if (w == 0) {
        a = (lane < 8) ? sa[lane] : 0.f;
        b = (lane < 8) ? sb[lane] : 0.f;
        #pragma unroll
        for (int o = 4; o > 0; o >>= 1) { a += __shfl_down_sync(F, a, o); b += __shfl_down_sync(F, b, o); }
    }
}

// ---------------- small kernels ----------------
__global__ void normalize_k(const float* x, const float* lo, const float* hi,
                            float* x0, float* l0, float* h0, int n) {
    int i = blockIdx.x * blockDim.x + threadIdx.x;
    if (i < n) {
        x0[i] = (x[i] - MEANC) / STDC;
        l0[i] = (lo[i] - MEANC) / STDC;
        h0[i] = (hi[i] - MEANC) / STDC;
    }
}

__global__ void matvec_k(const float* __restrict__ W, const float* __restrict__ xin,
                         const float* __restrict__ b, float* __restrict__ xout, int M, int K) {
    int row = blockIdx.x * (blockDim.x >> 5) + (threadIdx.x >> 5);
    if (row >= M) return;
    int lane = threadIdx.x & 31;
    float s = 0.f;
    const float* wr = W + (size_t)row * K;
    for (int k = lane; k < K; k += 32) s += wr[k] * xin[k];
    #pragma unroll
    for (int o = 16; o > 0; o >>= 1) s += __shfl_down_sync(0xffffffffu, s, o);
    if (lane == 0) xout[row] = s + b[row];
}

__global__ void relu_bs_f32_k(const float* __restrict__ srch, const float* __restrict__ srcl,
                              float* __restrict__ dsth, float* __restrict__ dstl,
                              const float* __restrict__ wld, const float* __restrict__ whd,
                              const float* __restrict__ bhrd, const float* __restrict__ bj,
                              float* __restrict__ bh, float* __restrict__ bl,
                              const float* __restrict__ binit, int K) {
    int m = blockIdx.x;
    size_t base = (size_t)m * K;
    float sh = 0.f, sl = 0.f;
    for (int k = threadIdx.x; k < K; k += blockDim.x) {
        float whk = whd[k], wlk = wld[k], brk = bhrd[k], bjk = bj[k];
        float mask = (whk != 0.f) ? 1.f : 0.f;
        float mh = srch[base + k], ml = srcl[base + k];
        float oh = (mh > 0.f ? mh * whk : mh * wlk) * mask;
        float ol = (ml > 0.f ? ml * wlk : ml * whk) * mask;
        dsth[base + k] = oh;
        dstl[base + k] = ol;
        sh += fmaxf(mh, 0.f) * mask * brk + oh * bjk;
        sl += fminf(ml, 0.f) * mask * brk + ol * bjk;
    }
    blkred2(sh, sl);
    if (threadIdx.x == 0) {
        if (binit) { bh[m] = binit[m] + sh; bl[m] = binit[m] + sl; }
        else       { bh[m] += sh;           bl[m] += sl; }
    }
}

// relu-backsub transform emitting fp16 A operands (unsplit)
__global__ void relu_bs_f16_k(const float* __restrict__ srch, const float* __restrict__ srcl,
                              __half* __restrict__ AH, __half* __restrict__ AL,
                              const float* __restrict__ wld, const float* __restrict__ whd,
                              const float* __restrict__ bhrd, const float* __restrict__ bj,
                              float* __restrict__ bh, float* __restrict__ bl,
                              const float* __restrict__ binit) {
    int m = blockIdx.x;
    size_t base = (size_t)m * NH;
    float sh = 0.f, sl = 0.f;
    for (int k = threadIdx.x; k < NH; k += blockDim.x) {
        float whk = whd[k], wlk = wld[k], brk = bhrd[k], bjk = bj[k];
        float mask = (whk != 0.f) ? 1.f : 0.f;
        float mh = srch[base + k], ml = srcl[base + k];
        float oh = (mh > 0.f ? mh * whk : mh * wlk) * mask;
        float ol = (ml > 0.f ? ml * wlk : ml * whk) * mask;
        AH[base + k] = __float2half(oh);
        AL[base + k] = __float2half(ol);
        sh += fmaxf(mh, 0.f) * mask * brk + oh * bjk;
        sl += fminf(ml, 0.f) * mask * brk + ol * bjk;
    }
    blkred2(sh, sl);
    if (threadIdx.x == 0) {
        if (binit) { bh[m] = binit[m] + sh; bl[m] = binit[m] + sl; }
        else       { bh[m] += sh;           bl[m] += sl; }
    }
}

__global__ void box_k(const float* __restrict__ Ah, const float* __restrict__ Al,
                      const float* __restrict__ bh, const float* __restrict__ bl,
                      const float* __restrict__ l0, const float* __restrict__ h0,
                      float* __restrict__ lowv, float* __restrict__ highv, int K, int ld) {
    int m = blockIdx.x;
    size_t base = (size_t)m * ld;
    float sh = 0.f, sl = 0.f;
    for (int k = threadIdx.x; k < K; k += blockDim.x) {
        float l0k = l0[k], h0k = h0[k];
        float ah = Ah[base + k];
        sh += (ah >= 0.f) ? ah * h0k : ah * l0k;
        float al = Al[base + k];
        sl += (al >= 0.f) ? al * l0k : al * h0k;
    }
    blkred2(sh, sl);
    if (threadIdx.x == 0) { highv[m] = bh[m] + sh; lowv[m] = bl[m] + sl; }
}

__global__ void relu_abs_k(float* __restrict__ x, const float* __restrict__ lowv,
                           const float* __restrict__ highv, float* __restrict__ wl,
                           float* __restrict__ wh, float* __restrict__ bhr, int n) {
    int i = blockIdx.x * blockDim.x + threadIdx.x;
    if (i >= n) return;
    float l = lowv[i], h = highv[i];
    bool cr = (l < 0.f) && (h > 0.f);
    float denom = cr ? (h - l) : 1.f;
    float ubs = cr ? h / denom : 0.f;
    float ubi = cr ? -(l * h) / denom : 0.f;
    float lam = (l * l > h * h) ? 0.f : 1.f;
    float keep = (h <= 0.f) ? 0.f : 1.f;
    wh[i] = cr ? ubs : keep;
    wl[i] = cr ? lam : keep;
    bhr[i] = ubi;
    x[i] = fmaxf(x[i], 0.f);
}

__global__ void write_out_k(const float* x5, const float* lowv, const float* highv, float* out) {
    int i = threadIdx.x;
    if (i < NOUT) { out[i] = x5[i]; out[NOUT + i] = lowv[i]; out[2 * NOUT + i] = highv[i]; }
}

// transpose + fp16 split: WT[n,k] = W[k*fi+n], zero-padded rows n>=fi
__global__ void wsplit_k(const float* __restrict__ W, __half* __restrict__ Th,
                         __half* __restrict__ Tl, int fi) {
    __shared__ float t[32][33];
    int tx = threadIdx.x, ty = threadIdx.y;
    int kb = blockIdx.y * 32, nb = blockIdx.x * 32;
    #pragma unroll
    for (int i = 0; i < 4; ++i) {
        int k = kb + ty + i * 8, n = nb + tx;
        t[ty + i * 8][tx] = (n < fi) ? W[(size_t)k * fi + n] : 0.f;
    }
    __syncthreads();
    #pragma unroll
    for (int i = 0; i < 4; ++i) {
        int n = nb + ty + i * 8, k = kb + tx;
        float v = t[tx][ty + i * 8];
        __half h = __float2half(v);
        Th[(size_t)n * NH + k] = h;
        Tl[(size_t)n * NH + k] = __float2half(v - __half2float(h));
    }
}

// skinny fp32 GEMM partials for the M=10 chain
__global__ void __launch_bounds__(128) skinny_k(const float* __restrict__ AH, const float* __restrict__ AL,
                                                const float* __restrict__ W,
                                                float* __restrict__ PH, float* __restrict__ PL, int Ng) {
    __shared__ float sH[NOUT][128], sL[NOUT][128];
    int t = threadIdx.x;
    int n = blockIdx.x * 128 + t;
    int seg = blockIdx.y;
    float aH[NOUT], aL[NOUT];
    #pragma unroll
    for (int m = 0; m < NOUT; ++m) { aH[m] = 0.f; aL[m] = 0.f; }
    for (int k0 = seg * 256; k0 < seg * 256 + 256; k0 += 128) {
        __syncthreads();
        #pragma unroll
        for (int m = 0; m < NOUT; ++m) {
            sH[m][t] = AH[m * NH + k0 + t];
            sL[m][t] = AL[m * NH + k0 + t];
        }
        __syncthreads();
        if (n < Ng) {
            for (int kk = 0; kk < 128; ++kk) {
                float w = W[(size_t)(k0 + kk) * Ng + n];
                #pragma unroll
                for (int m = 0; m < NOUT; ++m) { aH[m] += sH[m][kk] * w; aL[m] += sL[m][kk] * w; }
            }
        }
    }
    if (n < Ng) {
        size_t pb = (size_t)seg * NOUT * NH;
        #pragma unroll
        for (int m = 0; m < NOUT; ++m) { PH[pb + m * NH + n] = aH[m]; PL[pb + m * NH + n] = aL[m]; }
    }
}

__global__ void sreduce_k(const float* __restrict__ PH, const float* __restrict__ PL,
                          float* __restrict__ CH, float* __restrict__ CL, int Ng) {
    int idx = blockIdx.x * blockDim.x + threadIdx.x;
    if (idx >= NOUT * Ng) return;
    int m = idx / Ng, n = idx % Ng;
    float sh = 0.f, sl = 0.f;
    #pragma unroll
    for (int s = 0; s < 8; ++s) {
        sh += PH[((size_t)s * NOUT + m) * NH + n];
        sl += PL[((size_t)s * NOUT + m) * NH + n];
    }
    CH[m * NH + n] = sh;
    CL[m * NH + n] = sl;
}

// ---------------- fused H/L fp16 GEMM via mma.sync ----------------
// C{H,L}[2048 x Ng] = A{H,L}(fp16) @ (Bh+Bl)^T.  CTA 128x128 per output,
// warps 0-3 -> H, 4-7 -> L (2x2 of 64x64 each). k-chunk 32, 3-stage cp.async.
#define ROWB  80                     // 32 fp16 = 64B data + 16B pad
#define MATB  (128 * ROWB)           // 10240
#define STAGE (4 * MATB)             // 40960 (AH, AL, Bh, Bl)
#define GSMEM (3 * STAGE)            // 122880

__device__ __forceinline__ void ldsm4(uint32_t* r, uint32_t addr) {
    asm volatile("ldmatrix.sync.aligned.m8n8.x4.shared.b16 {%0,%1,%2,%3}, [%4];"
                 : "=r"(r[0]), "=r"(r[1]), "=r"(r[2]), "=r"(r[3]) : "r"(addr));
}
__device__ __forceinline__ void mma16816(float* c, const uint32_t* a, const uint32_t* b) {
    asm volatile(
        "mma.sync.aligned.m16n8k16.row.col.f32.f16.f16.f32 "
        "{%0,%1,%2,%3}, {%4,%5,%6,%7}, {%8,%9}, {%0,%1,%2,%3};"
        : "+f"(c[0]), "+f"(c[1]), "+f"(c[2]), "+f"(c[3])
        : "r"(a[0]), "r"(a[1]), "r"(a[2]), "r"(a[3]), "r"(b[0]), "r"(b[1]));
}

__device__ __forceinline__ void issue_chunk(uint32_t sb, int slot,
                                            const __half* Af, const __half* Bh,
                                            const __half* Bl, int row0, int col0,
                                            int k0, int tid) {
    uint32_t sbase = sb + slot * STAGE;
    #pragma unroll
    for (int i = 0; i < 8; ++i) {
        int q = tid + (i << 8);
        int mat = q >> 9;            // 0..3 : AH, AL, Bh, Bl
        int r = (q >> 2) & 127;
        int g = q & 3;
        const __half* src;
        int grow;
        if (mat < 2) { src = Af + ((size_t)mat << 22); grow = row0 + r; }
        else         { src = (mat == 2) ? Bh : Bl;     grow = col0 + r; }
        const void* gp = src + (size_t)grow * NH + k0 + (g << 3);
        uint32_t sp = sbase + mat * MATB + r * ROWB + (g << 4);
        asm volatile("cp.async.cg.shared.global [%0], [%1], 16;" :: "r"(sp), "l"(gp));
    }
    asm volatile("cp.async.commit_group;" ::: "memory");
}

__global__ void __launch_bounds__(256) hgemm_k(const __half* __restrict__ Af,
                                               const __half* __restrict__ Bh,
                                               const __half* __restrict__ Bl,
                                               float* __restrict__ CH, float* __restrict__ CL,
                                               int Ng) {
    extern __shared__ char smem[];
    const uint32_t sb = smem_u32(smem);
    const int tid = threadIdx.x, lane = tid & 31, wid = tid >> 5;
    const int row0 = blockIdx.y * 128, col0 = blockIdx.x * 128;
    const int half = wid >> 2, wq = wid & 3;
    const int warpM = (wq & 1) << 6, warpN = (wq >> 1) << 6;

    float acc[4][8][4];
    #pragma unroll
    for (int mi = 0; mi < 4; ++mi)
        #pragma unroll
        for (int ni = 0; ni < 8; ++ni)
            #pragma unroll
            for (int e = 0; e < 4; ++e) acc[mi][ni][e] = 0.f;

    issue_chunk(sb, 0, Af, Bh, Bl, row0, col0, 0, tid);
    issue_chunk(sb, 1, Af, Bh, Bl, row0, col0, 32, tid);

    const uint32_t aoff = (uint32_t)((lane & 15) * ROWB + ((lane >> 4) << 4));
    const uint32_t boff = (uint32_t)(((((lane >> 4) & 1) << 3) + (lane & 7)) * ROWB + (((lane >> 3) & 1) << 4));

    const int CHUNKS = 64;
    for (int c = 0; c < CHUNKS; ++c) {
        asm volatile("cp.async.wait_group 1;" ::: "memory");
        __syncthreads();
        if (c + 2 < CHUNKS)
            issue_chunk(sb, (c + 2) % 3, Af, Bh, Bl, row0, col0, (c + 2) * 32, tid);

        uint32_t st = sb + (c % 3) * STAGE;
        uint32_t sA  = st + half * MATB + warpM * ROWB + aoff;
        uint32_t sBh = st + 2 * MATB + warpN * ROWB + boff;
        uint32_t sBl = sBh + MATB;

        #pragma unroll
        for (int ks = 0; ks < 2; ++ks) {
            uint32_t ko = ks * 32;
            uint32_t a[4][4], b1[4][4], b2[4][4];
            #pragma unroll
            for (int mi = 0; mi < 4; ++mi) ldsm4(a[mi], sA + mi * (16 * ROWB) + ko);
            #pragma unroll
            for (int pi = 0; pi < 4; ++pi) {
                ldsm4(b1[pi], sBh + pi * (16 * ROWB) + ko);
                ldsm4(b2[pi], sBl + pi * (16 * ROWB) + ko);
            }
            #pragma unroll
            for (int mi = 0; mi < 4; ++mi) {
                #pragma unroll
                for (int ni = 0; ni < 8; ++ni) {
                    mma16816(acc[mi][ni], a[mi], &b1[ni >> 1][(ni & 1) << 1]);
                    mma16816(acc[mi][ni], a[mi], &b2[ni >> 1][(ni & 1) << 1]);
                }
            }
        }
    }

    float* C = half ? CL : CH;
    #pragma unroll
    for (int mi = 0; mi < 4; ++mi) {
        int gr = row0 + warpM + mi * 16 + (lane >> 2);
        #pragma unroll
        for (int ni = 0; ni < 8; ++ni) {
            int gc = col0 + warpN + ni * 8 + ((lane & 3) << 1);
            if (gc < Ng) {
                float2 v0 = make_float2(acc[mi][ni][0], acc[mi][ni][1]);
                float2 v1 = make_float2(acc[mi][ni][2], acc[mi][ni][3]);
                *reinterpret_cast<float2*>(C + (size_t)gr * Ng + gc) = v0;
                *reinterpret_cast<float2*>(C + (size_t)(gr + 8) * Ng + gc) = v1;
            }
        }
    }
}

// ---------------- driver ----------------
extern "C" void kernel_launch(void* const* d_in, const int* in_sizes, int n_in,
                              void* d_out, int out_size) {
    const float* x  = (const float*)d_in[0];
    const float* lo = (const float*)d_in[1];
    const float* hi = (const float*)d_in[2];
    const float* W[5];
    const float* b[5];
    for (int i = 0; i < 5; ++i) { W[i] = (const float*)d_in[3 + 2 * i]; b[i] = (const float*)d_in[4 + 2 * i]; }
    float* out = (float*)d_out;

    cudaFuncSetAttribute(hgemm_k, cudaFuncAttributeMaxDynamicSharedMemorySize, GSMEM);

    void* p;
    __half *Af, *WTh, *WTl;
    cudaGetSymbolAddress(&p, g_Af);  Af = (__half*)p;
    cudaGetSymbolAddress(&p, g_WTh); WTh = (__half*)p;
    cudaGetSymbolAddress(&p, g_WTl); WTl = (__half*)p;
    float *CH, *CL, *sAH, *sAL, *sCH, *sCL, *PH, *PL;
    cudaGetSymbolAddress(&p, g_CH);   CH = (float*)p;
    cudaGetSymbolAddress(&p, g_CL);   CL = (float*)p;
    cudaGetSymbolAddress(&p, g_sA);   sAH = (float*)p; sAL = sAH + NOUT * NH;
    cudaGetSymbolAddress(&p, g_sC);   sCH = (float*)p; sCL = sCH + NOUT * NH;
    cudaGetSymbolAddress(&p, g_part); PH = (float*)p; PL = PH + 8 * NOUT * NH;
    float *xa, *xb, *lowv, *highv, *wl, *wh, *bhr, *bh, *bl, *x0, *l0, *h0;
    cudaGetSymbolAddress(&p, g_xa);   xa = (float*)p;
    cudaGetSymbolAddress(&p, g_xb);   xb = (float*)p;
    cudaGetSymbolAddress(&p, g_low);  lowv = (float*)p;
    cudaGetSymbolAddress(&p, g_high); highv = (float*)p;
    cudaGetSymbolAddress(&p, g_wl);   wl = (float*)p;
    cudaGetSymbolAddress(&p, g_wh);   wh = (float*)p;
    cudaGetSymbolAddress(&p, g_bhr);  bhr = (float*)p;
    cudaGetSymbolAddress(&p, g_bh);   bh = (float*)p;
    cudaGetSymbolAddress(&p, g_bl);   bl = (float*)p;
    cudaGetSymbolAddress(&p, g_x0);   x0 = (float*)p;
    cudaGetSymbolAddress(&p, g_l0);   l0 = (float*)p;
    cudaGetSymbolAddress(&p, g_h0);   h0 = (float*)p;

    normalize_k<<<(NIN + 255) / 256, 256>>>(x, lo, hi, x0, l0, h0, NIN);

    // transpose + split weights W0..W3 (B operands), W0 padded to 896 rows
    {
        dim3 blk(32, 8);
        wsplit_k<<<dim3(28, 64), blk>>>(W[0], WTh, WTl, NIN);
        for (int j = 1; j < 4; ++j)
            wsplit_k<<<dim3(64, 64), blk>>>(W[j], WTh + (size_t)j * NHNH, WTl + (size_t)j * NHNH, NH);
    }

    // layer 0
    matvec_k<<<NH / 8, 256>>>(W[0], x0, b[0], xa, NH, NIN);
    box_k<<<NH, 256>>>(W[0], W[0], b[0], b[0], l0, h0, lowv, highv, NIN, NIN);
    relu_abs_k<<<NH / 256, 256>>>(xa, lowv, highv, wl, wh, bhr, NH);

    float* xin = xa;
    float* xout = xb;
    // layers 1..3: tensor-core chains
    for (int i = 1; i < 4; ++i) {
        matvec_k<<<NH / 8, 256>>>(W[i], xin, b[i], xout, NH, NH);
        const float* srch = W[i];
        const float* srcl = W[i];
        bool first = true;
        for (int j = i - 1; j >= 0; --j) {
            relu_bs_f16_k<<<NH, 256>>>(srch, srcl, Af, Af + (size_t)NHNH,
                                       wl + j * NH, wh + j * NH, bhr + j * NH, b[j],
                                       bh, bl, first ? b[i] : nullptr);
            int Ng = (j == 0) ? NIN : NH;
            int Nt = (j == 0) ? 7 : 16;
            hgemm_k<<<dim3(Nt, 16), 256, GSMEM>>>(Af, WTh + (size_t)j * NHNH,
                                                  WTl + (size_t)j * NHNH, CH, CL, Ng);
            srch = CH; srcl = CL; first = false;
        }
        box_k<<<NH, 256>>>(CH, CL, bh, bl, l0, h0, lowv, highv, NIN, NIN);
        relu_abs_k<<<NH / 256, 256>>>(xout, lowv, highv, wl + i * NH, wh + i * NH, bhr + i * NH, NH);
        float* t = xin; xin = xout; xout = t;
    }

    // layer 4 (M=10): fp32 skinny chain
    matvec_k<<<2, 256>>>(W[4], xin, b[4], xout, NOUT, NH);
    {
        const float* srch = W[4];
        const float* srcl = W[4];
        bool first = true;
        for (int j = 3; j >= 0; --j) {
            relu_bs_f32_k<<<NOUT, 256>>>(srch, srcl, sAH, sAL, wl + j * NH, wh + j * NH,
                                         bhr + j * NH, b[j], bh, bl, first ? b[4] : nullptr, NH);
            int Ng = (j == 0) ? NIN : NH;
            skinny_k<<<dim3((Ng + 127) / 128, 8), 128>>>(sAH, sAL, W[j], PH, PL, Ng);
            sreduce_k<<<(NOUT * Ng + 255) / 256, 256>>>(PH, PL, sCH, sCL, Ng);
            srch = sCH; srcl = sCL; first = false;
        }
        box_k<<<NOUT, 256>>>(sCH, sCL, bh, bl, l0, h0, lowv, highv, NIN, NH);
        write_out_k<<<1, 32>>>(xout, lowv, highv, out);
    }
    (void)in_sizes; (void)n_in; (void)out_size;
}

// round 6
// speedup vs baseline: 6.5532x; 1.3314x over previous
#include <cuda_runtime.h>
#include <cuda_fp16.h>
#include <cstdint>

#define MEANC 0.1307f
#define STDC  0.3081f
#define NIN   784
#define NH    2048
#define NOUT  10
#define NHNH  (NH * NH)

// ---------------- device scratch ----------------
__device__ __half g_Af[2][NHNH];     // AH, AL (fp16)
__device__ __half g_WT[4][NHNH];     // weight^T fp16
__device__ float g_CH[NHNH];
__device__ float g_CL[NHNH];
__device__ float g_sA[2][NOUT * NH];
__device__ float g_sC[2][NOUT * NH];
__device__ float g_part[2][8 * NOUT * NH];
__device__ float g_xa[NH], g_xb[NH], g_low[NH], g_high[NH];
__device__ float g_wl[4 * NH], g_wh[4 * NH], g_bhr[4 * NH];
__device__ float g_bh[NH], g_bl[NH];
__device__ float g_x0[NIN], g_l0[NIN], g_h0[NIN];

// ---------------- helpers ----------------
__device__ __forceinline__ uint32_t smem_u32(const void* p) {
    uint32_t a;
    asm("{ .reg .u64 t; cvta.to.shared.u64 t, %1; cvt.u32.u64 %0, t; }" : "=r"(a) : "l"(p));
    return a;
}

__device__ __forceinline__ void blkred2(float& a, float& b) {
    const unsigned F = 0xffffffffu;
    #pragma unroll
    for (int o = 16; o > 0; o >>= 1) { a += __shfl_down_sync(F, a, o); b += __shfl_down_sync(F, b, o); }
    __shared__ float sa[8], sb[8];
    int w = threadIdx.x >> 5, lane = threadIdx.x & 31;
    if (lane == 0) { sa[w] = a; sb[w] = b; }
    __syncthreads();
    if (w == 0) {
        a = (lane < 8) ? sa[lane] : 0.f;
        b = (lane < 8) ? sb[lane] : 0.f;
        #pragma unroll
        for (int o = 4; o > 0; o >>= 1) { a += __shfl_down_sync(F, a, o); b += __shfl_down_sync(F, b, o); }
    }
}

// ---------------- small kernels ----------------
__global__ void normalize_k(const float* x, const float* lo, const float* hi,
                            float* x0, float* l0, float* h0, int n) {
    int i = blockIdx.x * blockDim.x + threadIdx.x;
    if (i < n) {
        x0[i] = (x[i] - MEANC) / STDC;
        l0[i] = (lo[i] - MEANC) / STDC;
        h0[i] = (hi[i] - MEANC) / STDC;
    }
}

__global__ void matvec_k(const float* __restrict__ W, const float* __restrict__ xin,
                         const float* __restrict__ b, float* __restrict__ xout, int M, int K) {
    int row = blockIdx.x * (blockDim.x >> 5) + (threadIdx.x >> 5);
    if (row >= M) return;
    int lane = threadIdx.x & 31;
    float s = 0.f;
    const float* wr = W + (size_t)row * K;
    for (int k = lane; k < K; k += 32) s += wr[k] * xin[k];
    #pragma unroll
    for (int o = 16; o > 0; o >>= 1) s += __shfl_down_sync(0xffffffffu, s, o);
    if (lane == 0) xout[row] = s + b[row];
}

__global__ void relu_bs_f32_k(const float* __restrict__ srch, const float* __restrict__ srcl,
                              float* __restrict__ dsth, float* __restrict__ dstl,
                              const float* __restrict__ wld, const float* __restrict__ whd,
                              const float* __restrict__ bhrd, const float* __restrict__ bj,
                              float* __restrict__ bh, float* __restrict__ bl,
                              const float* __restrict__ binit, int K) {
    int m = blockIdx.x;
    size_t base = (size_t)m * K;
    float sh = 0.f, sl = 0.f;
    for (int k = threadIdx.x; k < K; k += blockDim.x) {
        float whk = whd[k], wlk = wld[k], brk = bhrd[k], bjk = bj[k];
        float mask = (whk != 0.f) ? 1.f : 0.f;
        float mh = srch[base + k], ml = srcl[base + k];
        float oh = (mh > 0.f ? mh * whk : mh * wlk) * mask;
        float ol = (ml > 0.f ? ml * wlk : ml * whk) * mask;
        dsth[base + k] = oh;
        dstl[base + k] = ol;
        sh += fmaxf(mh, 0.f) * mask * brk + oh * bjk;
        sl += fminf(ml, 0.f) * mask * brk + ol * bjk;
    }
    blkred2(sh, sl);
    if (threadIdx.x == 0) {
        if (binit) { bh[m] = binit[m] + sh; bl[m] = binit[m] + sl; }
        else       { bh[m] += sh;           bl[m] += sl; }
    }
}

// relu-backsub transform emitting fp16 A operands
__global__ void relu_bs_f16_k(const float* __restrict__ srch, const float* __restrict__ srcl,
                              __half* __restrict__ AH, __half* __restrict__ AL,
                              const float* __restrict__ wld, const float* __restrict__ whd,
                              const float* __restrict__ bhrd, const float* __restrict__ bj,
                              float* __restrict__ bh, float* __restrict__ bl,
                              const float* __restrict__ binit) {
    int m = blockIdx.x;
    size_t base = (size_t)m * NH;
    float sh = 0.f, sl = 0.f;
    for (int k = threadIdx.x; k < NH; k += blockDim.x) {
        float whk = whd[k], wlk = wld[k], brk = bhrd[k], bjk = bj[k];
        float mask = (whk != 0.f) ? 1.f : 0.f;
        float mh = srch[base + k], ml = srcl[base + k];
        float oh = (mh > 0.f ? mh * whk : mh * wlk) * mask;
        float ol = (ml > 0.f ? ml * wlk : ml * whk) * mask;
        AH[base + k] = __float2half(oh);
        AL[base + k] = __float2half(ol);
        sh += fmaxf(mh, 0.f) * mask * brk + oh * bjk;
        sl += fminf(ml, 0.f) * mask * brk + ol * bjk;
    }
    blkred2(sh, sl);
    if (threadIdx.x == 0) {
        if (binit) { bh[m] = binit[m] + sh; bl[m] = binit[m] + sl; }
        else       { bh[m] += sh;           bl[m] += sl; }
    }
}

__global__ void box_k(const float* __restrict__ Ah, const float* __restrict__ Al,
                      const float* __restrict__ bh, const float* __restrict__ bl,
                      const float* __restrict__ l0, const float* __restrict__ h0,
                      float* __restrict__ lowv, float* __restrict__ highv, int K, int ld) {
    int m = blockIdx.x;
    size_t base = (size_t)m * ld;
    float sh = 0.f, sl = 0.f;
    for (int k = threadIdx.x; k < K; k += blockDim.x) {
        float l0k = l0[k], h0k = h0[k];
        float ah = Ah[base + k];
        sh += (ah >= 0.f) ? ah * h0k : ah * l0k;
        float al = Al[base + k];
        sl += (al >= 0.f) ? al * l0k : al * h0k;
    }
    blkred2(sh, sl);
    if (threadIdx.x == 0) { highv[m] = bh[m] + sh; lowv[m] = bl[m] + sl; }
}

__global__ void relu_abs_k(float* __restrict__ x, const float* __restrict__ lowv,
                           const float* __restrict__ highv, float* __restrict__ wl,
                           float* __restrict__ wh, float* __restrict__ bhr, int n) {
    int i = blockIdx.x * blockDim.x + threadIdx.x;
    if (i >= n) return;
    float l = lowv[i], h = highv[i];
    bool cr = (l < 0.f) && (h > 0.f);
    float denom = cr ? (h - l) : 1.f;
    float ubs = cr ? h / denom : 0.f;
    float ubi = cr ? -(l * h) / denom : 0.f;
    float lam = (l * l > h * h) ? 0.f : 1.f;
    float keep = (h <= 0.f) ? 0.f : 1.f;
    wh[i] = cr ? ubs : keep;
    wl[i] = cr ? lam : keep;
    bhr[i] = ubi;
    x[i] = fmaxf(x[i], 0.f);
}

__global__ void write_out_k(const float* x5, const float* lowv, const float* highv, float* out) {
    int i = threadIdx.x;
    if (i < NOUT) { out[i] = x5[i]; out[NOUT + i] = lowv[i]; out[2 * NOUT + i] = highv[i]; }
}

// transpose to fp16: WT[n,k] = fp16(W[k*fi+n]), zero-padded rows n>=fi
__global__ void wsplit_k(const float* __restrict__ W, __half* __restrict__ Th, int fi) {
    __shared__ float t[32][33];
    int tx = threadIdx.x, ty = threadIdx.y;
    int kb = blockIdx.y * 32, nb = blockIdx.x * 32;
    #pragma unroll
    for (int i = 0; i < 4; ++i) {
        int k = kb + ty + i * 8, n = nb + tx;
        t[ty + i * 8][tx] = (n < fi) ? W[(size_t)k * fi + n] : 0.f;
    }
    __syncthreads();
    #pragma unroll
    for (int i = 0; i < 4; ++i) {
        int n = nb + ty + i * 8, k = kb + tx;
        Th[(size_t)n * NH + k] = __float2half(t[tx][ty + i * 8]);
    }
}

// skinny fp32 GEMM partials for the M=10 chain
__global__ void __launch_bounds__(128) skinny_k(const float* __restrict__ AH, const float* __restrict__ AL,
                                                const float* __restrict__ W,
                                                float* __restrict__ PH, float* __restrict__ PL, int Ng) {
    __shared__ float sH[NOUT][128], sL[NOUT][128];
    int t = threadIdx.x;
    int n = blockIdx.x * 128 + t;
    int seg = blockIdx.y;
    float aH[NOUT], aL[NOUT];
    #pragma unroll
    for (int m = 0; m < NOUT; ++m) { aH[m] = 0.f; aL[m] = 0.f; }
    for (int k0 = seg * 256; k0 < seg * 256 + 256; k0 += 128) {
        __syncthreads();
        #pragma unroll
        for (int m = 0; m < NOUT; ++m) {
            sH[m][t] = AH[m * NH + k0 + t];
            sL[m][t] = AL[m * NH + k0 + t];
        }
        __syncthreads();
        if (n < Ng) {
            for (int kk = 0; kk < 128; ++kk) {
                float w = W[(size_t)(k0 + kk) * Ng + n];
                #pragma unroll
                for (int m = 0; m < NOUT; ++m) { aH[m] += sH[m][kk] * w; aL[m] += sL[m][kk] * w; }
            }
        }
    }
    if (n < Ng) {
        size_t pb = (size_t)seg * NOUT * NH;
        #pragma unroll
        for (int m = 0; m < NOUT; ++m) { PH[pb + m * NH + n] = aH[m]; PL[pb + m * NH + n] = aL[m]; }
    }
}

__global__ void sreduce_k(const float* __restrict__ PH, const float* __restrict__ PL,
                          float* __restrict__ CH, float* __restrict__ CL, int Ng) {
    int idx = blockIdx.x * blockDim.x + threadIdx.x;
    if (idx >= NOUT * Ng) return;
    int m = idx / Ng, n = idx % Ng;
    float sh = 0.f, sl = 0.f;
    #pragma unroll
    for (int s = 0; s < 8; ++s) {
        sh += PH[((size_t)s * NOUT + m) * NH + n];
        sl += PL[((size_t)s * NOUT + m) * NH + n];
    }
    CH[m * NH + n] = sh;
    CL[m * NH + n] = sl;
}

// ---------------- fused H/L fp16 GEMM via mma.sync ----------------
// C{H,L}[2048 x Ng] = A{H,L}(fp16) @ B^T(fp16).  CTA 128x128 per output,
// warps 0-3 -> H, 4-7 -> L (2x2 of 64x64 each). B tile shared by both halves.
// k-chunk 32, 3-stage cp.async pipeline. 3 matrices per stage: AH, AL, B.
#define ROWB  80                     // 32 fp16 = 64B data + 16B pad
#define MATB  (128 * ROWB)           // 10240
#define STAGE (3 * MATB)             // 30720
#define GSMEM (3 * STAGE)            // 92160

__device__ __forceinline__ void ldsm4(uint32_t* r, uint32_t addr) {
    asm volatile("ldmatrix.sync.aligned.m8n8.x4.shared.b16 {%0,%1,%2,%3}, [%4];"
                 : "=r"(r[0]), "=r"(r[1]), "=r"(r[2]), "=r"(r[3]) : "r"(addr));
}
__device__ __forceinline__ void mma16816(float* c, const uint32_t* a, const uint32_t* b) {
    asm volatile(
        "mma.sync.aligned.m16n8k16.row.col.f32.f16.f16.f32 "
        "{%0,%1,%2,%3}, {%4,%5,%6,%7}, {%8,%9}, {%0,%1,%2,%3};"
        : "+f"(c[0]), "+f"(c[1]), "+f"(c[2]), "+f"(c[3])
        : "r"(a[0]), "r"(a[1]), "r"(a[2]), "r"(a[3]), "r"(b[0]), "r"(b[1]));
}

__device__ __forceinline__ void issue_chunk(uint32_t sb, int slot,
                                            const __half* Af, const __half* B,
                                            int row0, int col0, int k0, int tid) {
    uint32_t sbase = sb + slot * STAGE;
    #pragma unroll
    for (int i = 0; i < 6; ++i) {
        int q = tid + (i << 8);
        int mat = q >> 9;            // 0: AH, 1: AL, 2: B
        int r = (q >> 2) & 127;
        int g = q & 3;
        const __half* src;
        int grow;
        if (mat < 2) { src = Af + ((size_t)mat << 22); grow = row0 + r; }
        else         { src = B;                        grow = col0 + r; }
        const void* gp = src + (size_t)grow * NH + k0 + (g << 3);
        uint32_t sp = sbase + mat * MATB + r * ROWB + (g << 4);
        asm volatile("cp.async.cg.shared.global [%0], [%1], 16;" :: "r"(sp), "l"(gp));
    }
    asm volatile("cp.async.commit_group;" ::: "memory");
}

__global__ void __launch_bounds__(256) hgemm_k(const __half* __restrict__ Af,
                                               const __half* __restrict__ B,
                                               float* __restrict__ CH, float* __restrict__ CL,
                                               int Ng) {
    extern __shared__ char smem[];
    const uint32_t sb = smem_u32(smem);
    const int tid = threadIdx.x, lane = tid & 31, wid = tid >> 5;
    const int row0 = blockIdx.y * 128, col0 = blockIdx.x * 128;
    const int half = wid >> 2, wq = wid & 3;
    const int warpM = (wq & 1) << 6, warpN = (wq >> 1) << 6;

    float acc[4][8][4];
    #pragma unroll
    for (int mi = 0; mi < 4; ++mi)
        #pragma unroll
        for (int ni = 0; ni < 8; ++ni)
            #pragma unroll
            for (int e = 0; e < 4; ++e) acc[mi][ni][e] = 0.f;

    issue_chunk(sb, 0, Af, B, row0, col0, 0, tid);
    issue_chunk(sb, 1, Af, B, row0, col0, 32, tid);

    const uint32_t aoff = (uint32_t)((lane & 15) * ROWB + ((lane >> 4) << 4));
    const uint32_t boff = (uint32_t)(((((lane >> 4) & 1) << 3) + (lane & 7)) * ROWB + (((lane >> 3) & 1) << 4));

    const int CHUNKS = 64;
    for (int c = 0; c < CHUNKS; ++c) {
        asm volatile("cp.async.wait_group 1;" ::: "memory");
        __syncthreads();
        if (c + 2 < CHUNKS)
            issue_chunk(sb, (c + 2) % 3, Af, B, row0, col0, (c + 2) * 32, tid);

        uint32_t st = sb + (c % 3) * STAGE;
        uint32_t sA = st + half * MATB + warpM * ROWB + aoff;
        uint32_t sB = st + 2 * MATB + warpN * ROWB + boff;

        #pragma unroll
        for (int ks = 0; ks < 2; ++ks) {
            uint32_t ko = ks * 32;
            uint32_t a[4][4], bb[4][4];
            #pragma unroll
            for (int mi = 0; mi < 4; ++mi) ldsm4(a[mi], sA + mi * (16 * ROWB) + ko);
            #pragma unroll
            for (int pi = 0; pi < 4; ++pi) ldsm4(bb[pi], sB + pi * (16 * ROWB) + ko);
            #pragma unroll
            for (int mi = 0; mi < 4; ++mi)
                #pragma unroll
                for (int ni = 0; ni < 8; ++ni)
                    mma16816(acc[mi][ni], a[mi], &bb[ni >> 1][(ni & 1) << 1]);
        }
    }

    float* C = half ? CL : CH;
    #pragma unroll
    for (int mi = 0; mi < 4; ++mi) {
        int gr = row0 + warpM + mi * 16 + (lane >> 2);
        #pragma unroll
        for (int ni = 0; ni < 8; ++ni) {
            int gc = col0 + warpN + ni * 8 + ((lane & 3) << 1);
            if (gc < Ng) {
                float2 v0 = make_float2(acc[mi][ni][0], acc[mi][ni][1]);
                float2 v1 = make_float2(acc[mi][ni][2], acc[mi][ni][3]);
                *reinterpret_cast<float2*>(C + (size_t)gr * Ng + gc) = v0;
                *reinterpret_cast<float2*>(C + (size_t)(gr + 8) * Ng + gc) = v1;
            }
        }
    }
}

// ---------------- driver ----------------
extern "C" void kernel_launch(void* const* d_in, const int* in_sizes, int n_in,
                              void* d_out, int out_size) {
    const float* x  = (const float*)d_in[0];
    const float* lo = (const float*)d_in[1];
    const float* hi = (const float*)d_in[2];
    const float* W[5];
    const float* b[5];
    for (int i = 0; i < 5; ++i) { W[i] = (const float*)d_in[3 + 2 * i]; b[i] = (const float*)d_in[4 + 2 * i]; }
    float* out = (float*)d_out;

    cudaFuncSetAttribute(hgemm_k, cudaFuncAttributeMaxDynamicSharedMemorySize, GSMEM);

    void* p;
    __half *Af, *WT;
    cudaGetSymbolAddress(&p, g_Af); Af = (__half*)p;
    cudaGetSymbolAddress(&p, g_WT); WT = (__half*)p;
    float *CH, *CL, *sAH, *sAL, *sCH, *sCL, *PH, *PL;
    cudaGetSymbolAddress(&p, g_CH);   CH = (float*)p;
    cudaGetSymbolAddress(&p, g_CL);   CL = (float*)p;
    cudaGetSymbolAddress(&p, g_sA);   sAH = (float*)p; sAL = sAH + NOUT * NH;
    cudaGetSymbolAddress(&p, g_sC);   sCH = (float*)p; sCL = sCH + NOUT * NH;
    cudaGetSymbolAddress(&p, g_part); PH = (float*)p; PL = PH + 8 * NOUT * NH;
    float *xa, *xb, *lowv, *highv, *wl, *wh, *bhr, *bh, *bl, *x0, *l0, *h0;
    cudaGetSymbolAddress(&p, g_xa);   xa = (float*)p;
    cudaGetSymbolAddress(&p, g_xb);   xb = (float*)p;
    cudaGetSymbolAddress(&p, g_low);  lowv = (float*)p;
    cudaGetSymbolAddress(&p, g_high); highv = (float*)p;
    cudaGetSymbolAddress(&p, g_wl);   wl = (float*)p;
    cudaGetSymbolAddress(&p, g_wh);   wh = (float*)p;
    cudaGetSymbolAddress(&p, g_bhr);  bhr = (float*)p;
    cudaGetSymbolAddress(&p, g_bh);   bh = (float*)p;
    cudaGetSymbolAddress(&p, g_bl);   bl = (float*)p;
    cudaGetSymbolAddress(&p, g_x0);   x0 = (float*)p;
    cudaGetSymbolAddress(&p, g_l0);   l0 = (float*)p;
    cudaGetSymbolAddress(&p, g_h0);   h0 = (float*)p;

    normalize_k<<<(NIN + 255) / 256, 256>>>(x, lo, hi, x0, l0, h0, NIN);

    // transpose weights W0..W3 to fp16 (B operands), W0 padded to 896 rows
    {
        dim3 blk(32, 8);
        wsplit_k<<<dim3(28, 64), blk>>>(W[0], WT, NIN);
        for (int j = 1; j < 4; ++j)
            wsplit_k<<<dim3(64, 64), blk>>>(W[j], WT + (size_t)j * NHNH, NH);
    }

    // layer 0
    matvec_k<<<NH / 8, 256>>>(W[0], x0, b[0], xa, NH, NIN);
    box_k<<<NH, 256>>>(W[0], W[0], b[0], b[0], l0, h0, lowv, highv, NIN, NIN);
    relu_abs_k<<<NH / 256, 256>>>(xa, lowv, highv, wl, wh, bhr, NH);

    float* xin = xa;
    float* xout = xb;
    // layers 1..3: tensor-core chains
    for (int i = 1; i < 4; ++i) {
        matvec_k<<<NH / 8, 256>>>(W[i], xin, b[i], xout, NH, NH);
        const float* srch = W[i];
        const float* srcl = W[i];
        bool first = true;
        for (int j = i - 1; j >= 0; --j) {
            relu_bs_f16_k<<<NH, 256>>>(srch, srcl, Af, Af + (size_t)NHNH,
                                       wl + j * NH, wh + j * NH, bhr + j * NH, b[j],
                                       bh, bl, first ? b[i] : nullptr);
            int Ng = (j == 0) ? NIN : NH;
            int Nt = (j == 0) ? 7 : 16;
            hgemm_k<<<dim3(Nt, 16), 256, GSMEM>>>(Af, WT + (size_t)j * NHNH, CH, CL, Ng);
            srch = CH; srcl = CL; first = false;
        }
        box_k<<<NH, 256>>>(CH, CL, bh, bl, l0, h0, lowv, highv, NIN, NIN);
        relu_abs_k<<<NH / 256, 256>>>(xout, lowv, highv, wl + i * NH, wh + i * NH, bhr + i * NH, NH);
        float* t = xin; xin = xout; xout = t;
    }

    // layer 4 (M=10): fp32 skinny chain
    matvec_k<<<2, 256>>>(W[4], xin, b[4], xout, NOUT, NH);
    {
        const float* srch = W[4];
        const float* srcl = W[4];
        bool first = true;
        for (int j = 3; j >= 0; --j) {
            relu_bs_f32_k<<<NOUT, 256>>>(srch, srcl, sAH, sAL, wl + j * NH, wh + j * NH,
                                         bhr + j * NH, b[j], bh, bl, first ? b[4] : nullptr, NH);
            int Ng = (j == 0) ? NIN : NH;
            skinny_k<<<dim3((Ng + 127) / 128, 8), 128>>>(sAH, sAL, W[j], PH, PL, Ng);
            sreduce_k<<<(NOUT * Ng + 255) / 256, 256>>>(PH, PL, sCH, sCL, Ng);
            srch = sCH; srcl = sCL; first = false;
        }
        box_k<<<NOUT, 256>>>(sCH, sCL, bh, bl, l0, h0, lowv, highv, NIN, NH);
        write_out_k<<<1, 32>>>(xout, lowv, highv, out);
    }
    (void)in_sizes; (void)n_in; (void)out_size;
}

// round 7
// speedup vs baseline: 7.1257x; 1.0874x over previous
#include <cuda_runtime.h>
#include <cuda_fp16.h>
#include <cstdint>

#define MEANC 0.1307f
#define STDC  0.3081f
#define NIN   784
#define NH    2048
#define NOUT  10
#define NHNH  (NH * NH)

// ---------------- device scratch ----------------
__device__ __half g_Af[4][NHNH];     // buf0: AH,AL ; buf1: AH,AL
__device__ __half g_WT[4][NHNH];     // weight^T fp16
__device__ float g_sA[2][NOUT * NH];
__device__ float g_sC[2][NOUT * NH];
__device__ float g_part[2][8 * NOUT * NH];
__device__ float g_xa[NH], g_xb[NH], g_low[NH], g_high[NH];
__device__ float g_wl[4 * NH], g_wh[4 * NH], g_bhr[4 * NH];
__device__ float g_bh[NH], g_bl[NH];
__device__ float g_x0[NIN], g_l0[NIN], g_h0[NIN];

// ---------------- helpers ----------------
__device__ __forceinline__ uint32_t smem_u32(const void* p) {
    uint32_t a;
    asm("{ .reg .u64 t; cvta.to.shared.u64 t, %1; cvt.u32.u64 %0, t; }" : "=r"(a) : "l"(p));
    return a;
}

__device__ __forceinline__ void blkred3(float& a, float& b, float& c) {
    const unsigned F = 0xffffffffu;
    #pragma unroll
    for (int o = 16; o > 0; o >>= 1) {
        a += __shfl_down_sync(F, a, o);
        b += __shfl_down_sync(F, b, o);
        c += __shfl_down_sync(F, c, o);
    }
    __shared__ float sa[8], sb[8], sc[8];
    int w = threadIdx.x >> 5, lane = threadIdx.x & 31;
    if (lane == 0) { sa[w] = a; sb[w] = b; sc[w] = c; }
    __syncthreads();
    if (w == 0) {
        a = (lane < 8) ? sa[lane] : 0.f;
        b = (lane < 8) ? sb[lane] : 0.f;
        c = (lane < 8) ? sc[lane] : 0.f;
        #pragma unroll
        for (int o = 4; o > 0; o >>= 1) {
            a += __shfl_down_sync(F, a, o);
            b += __shfl_down_sync(F, b, o);
            c += __shfl_down_sync(F, c, o);
        }
    }
}

// ---------------- small kernels ----------------
__global__ void normalize_k(const float* x, const float* lo, const float* hi,
                            float* x0, float* l0, float* h0, int n) {
    int i = blockIdx.x * blockDim.x + threadIdx.x;
    if (i < n) {
        x0[i] = (x[i] - MEANC) / STDC;
        l0[i] = (lo[i] - MEANC) / STDC;
        h0[i] = (hi[i] - MEANC) / STDC;
    }
}

__global__ void zero2_k(float* a, float* b, int n) {
    int i = blockIdx.x * blockDim.x + threadIdx.x;
    if (i < n) { a[i] = 0.f; b[i] = 0.f; }
}

__global__ void matvec_k(const float* __restrict__ W, const float* __restrict__ xin,
                         const float* __restrict__ b, float* __restrict__ xout, int M, int K) {
    int row = blockIdx.x * (blockDim.x >> 5) + (threadIdx.x >> 5);
    if (row >= M) return;
    int lane = threadIdx.x & 31;
    float s = 0.f;
    const float* wr = W + (size_t)row * K;
    for (int k = lane; k < K; k += 32) s += wr[k] * xin[k];
    #pragma unroll
    for (int o = 16; o > 0; o >>= 1) s += __shfl_down_sync(0xffffffffu, s, o);
    if (lane == 0) xout[row] = s + b[row];
}

// chain start: fused matvec + relu-backsub transform of W[i], fp16 A emission
__global__ void relu_bs_first_k(const float* __restrict__ W, const float* __restrict__ xin,
                                const float* __restrict__ bi,
                                const float* __restrict__ wld, const float* __restrict__ whd,
                                const float* __restrict__ bhrd, const float* __restrict__ bj,
                                __half* __restrict__ AH, __half* __restrict__ AL,
                                float* __restrict__ bh, float* __restrict__ bl,
                                float* __restrict__ xout) {
    int m = blockIdx.x;
    size_t base = (size_t)m * NH;
    float sh = 0.f, sl = 0.f, sx = 0.f;
    for (int k = threadIdx.x; k < NH; k += blockDim.x) {
        float whk = whd[k], wlk = wld[k], brk = bhrd[k], bjk = bj[k];
        float mask = (whk != 0.f) ? 1.f : 0.f;
        float w = W[base + k];
        float oh = (w > 0.f ? w * whk : w * wlk) * mask;
        float ol = (w > 0.f ? w * wlk : w * whk) * mask;
        AH[base + k] = __float2half(oh);
        AL[base + k] = __float2half(ol);
        sh += fmaxf(w, 0.f) * mask * brk + oh * bjk;
        sl += fminf(w, 0.f) * mask * brk + ol * bjk;
        sx += w * xin[k];
    }
    blkred3(sh, sl, sx);
    if (threadIdx.x == 0) {
        bh[m] = bi[m] + sh;
        bl[m] = bi[m] + sl;
        xout[m] = sx + bi[m];
    }
}

// fp32 relu-backsub transform (skinny path, M=10)
__global__ void relu_bs_f32_k(const float* __restrict__ srch, const float* __restrict__ srcl,
                              float* __restrict__ dsth, float* __restrict__ dstl,
                              const float* __restrict__ wld, const float* __restrict__ whd,
                              const float* __restrict__ bhrd, const float* __restrict__ bj,
                              float* __restrict__ bh, float* __restrict__ bl,
                              const float* __restrict__ binit, int K) {
    int m = blockIdx.x;
    size_t base = (size_t)m * K;
    float sh = 0.f, sl = 0.f, dummy = 0.f;
    for (int k = threadIdx.x; k < K; k += blockDim.x) {
        float whk = whd[k], wlk = wld[k], brk = bhrd[k], bjk = bj[k];
        float mask = (whk != 0.f) ? 1.f : 0.f;
        float mh = srch[base + k], ml = srcl[base + k];
        float oh = (mh > 0.f ? mh * whk : mh * wlk) * mask;
        float ol = (ml > 0.f ? ml * wlk : ml * whk) * mask;
        dsth[base + k] = oh;
        dstl[base + k] = ol;
        sh += fmaxf(mh, 0.f) * mask * brk + oh * bjk;
        sl += fminf(ml, 0.f) * mask * brk + ol * bjk;
    }
    blkred3(sh, sl, dummy);
    if (threadIdx.x == 0) {
        if (binit) { bh[m] = binit[m] + sh; bl[m] = binit[m] + sl; }
        else       { bh[m] += sh;           bl[m] += sl; }
    }
}

__global__ void box_k(const float* __restrict__ Ah, const float* __restrict__ Al,
                      const float* __restrict__ bh, const float* __restrict__ bl,
                      const float* __restrict__ l0, const float* __restrict__ h0,
                      float* __restrict__ lowv, float* __restrict__ highv, int K, int ld) {
    int m = blockIdx.x;
    size_t base = (size_t)m * ld;
    float sh = 0.f, sl = 0.f, dummy = 0.f;
    for (int k = threadIdx.x; k < K; k += blockDim.x) {
        float l0k = l0[k], h0k = h0[k];
        float ah = Ah[base + k];
        sh += (ah >= 0.f) ? ah * h0k : ah * l0k;
        float al = Al[base + k];
        sl += (al >= 0.f) ? al * l0k : al * h0k;
    }
    blkred3(sh, sl, dummy);
    if (threadIdx.x == 0) { highv[m] = bh[m] + sh; lowv[m] = bl[m] + sl; }
}

// relu relaxation; optionally adds bias terms (addbh/addbl) to raw box sums
__global__ void relu_abs_k(float* __restrict__ x, const float* __restrict__ lowv,
                           const float* __restrict__ highv,
                           const float* __restrict__ addbh, const float* __restrict__ addbl,
                           float* __restrict__ wl, float* __restrict__ wh,
                           float* __restrict__ bhr, int n) {
    int i = blockIdx.x * blockDim.x + threadIdx.x;
    if (i >= n) return;
    float l = lowv[i] + (addbl ? addbl[i] : 0.f);
    float h = highv[i] + (addbh ? addbh[i] : 0.f);
    bool cr = (l < 0.f) && (h > 0.f);
    float denom = cr ? (h - l) : 1.f;
    float ubs = cr ? h / denom : 0.f;
    float ubi = cr ? -(l * h) / denom : 0.f;
    float lam = (l * l > h * h) ? 0.f : 1.f;
    float keep = (h <= 0.f) ? 0.f : 1.f;
    wh[i] = cr ? ubs : keep;
    wl[i] = cr ? lam : keep;
    bhr[i] = ubi;
    x[i] = fmaxf(x[i], 0.f);
}

__global__ void write_out_k(const float* x5, const float* lowv, const float* highv, float* out) {
    int i = threadIdx.x;
    if (i < NOUT) { out[i] = x5[i]; out[NOUT + i] = lowv[i]; out[2 * NOUT + i] = highv[i]; }
}

// transpose to fp16: WT[n,k] = fp16(W[k*fi+n]), zero-padded rows n>=fi
__global__ void wsplit_k(const float* __restrict__ W, __half* __restrict__ Th, int fi) {
    __shared__ float t[32][33];
    int tx = threadIdx.x, ty = threadIdx.y;
    int kb = blockIdx.y * 32, nb = blockIdx.x * 32;
    #pragma unroll
    for (int i = 0; i < 4; ++i) {
        int k = kb + ty + i * 8, n = nb + tx;
        t[ty + i * 8][tx] = (n < fi) ? W[(size_t)k * fi + n] : 0.f;
    }
    __syncthreads();
    #pragma unroll
    for (int i = 0; i < 4; ++i) {
        int n = nb + ty + i * 8, k = kb + tx;
        Th[(size_t)n * NH + k] = __float2half(t[tx][ty + i * 8]);
    }
}

// skinny fp32 GEMM partials for the M=10 chain
__global__ void __launch_bounds__(128) skinny_k(const float* __restrict__ AH, const float* __restrict__ AL,
                                                const float* __restrict__ W,
                                                float* __restrict__ PH, float* __restrict__ PL, int Ng) {
    __shared__ float sH[NOUT][128], sL[NOUT][128];
    int t = threadIdx.x;
    int n = blockIdx.x * 128 + t;
    int seg = blockIdx.y;
    float aH[NOUT], aL[NOUT];
    #pragma unroll
    for (int m = 0; m < NOUT; ++m) { aH[m] = 0.f; aL[m] = 0.f; }
    for (int k0 = seg * 256; k0 < seg * 256 + 256; k0 += 128) {
        __syncthreads();
        #pragma unroll
        for (int m = 0; m < NOUT; ++m) {
            sH[m][t] = AH[m * NH + k0 + t];
            sL[m][t] = AL[m * NH + k0 + t];
        }
        __syncthreads();
        if (n < Ng) {
            for (int kk = 0; kk < 128; ++kk) {
                float w = W[(size_t)(k0 + kk) * Ng + n];
                #pragma unroll
                for (int m = 0; m < NOUT; ++m) { aH[m] += sH[m][kk] * w; aL[m] += sL[m][kk] * w; }
            }
        }
    }
    if (n < Ng) {
        size_t pb = (size_t)seg * NOUT * NH;
        #pragma unroll
        for (int m = 0; m < NOUT; ++m) { PH[pb + m * NH + n] = aH[m]; PL[pb + m * NH + n] = aL[m]; }
    }
}

__global__ void sreduce_k(const float* __restrict__ PH, const float* __restrict__ PL,
                          float* __restrict__ CH, float* __restrict__ CL, int Ng) {
    int idx = blockIdx.x * blockDim.x + threadIdx.x;
    if (idx >= NOUT * Ng) return;
    int m = idx / Ng, n = idx % Ng;
    float sh = 0.f, sl = 0.f;
    #pragma unroll
    for (int s = 0; s < 8; ++s) {
        sh += PH[((size_t)s * NOUT + m) * NH + n];
        sl += PL[((size_t)s * NOUT + m) * NH + n];
    }
    CH[m * NH + n] = sh;
    CL[m * NH + n] = sl;
}

// ---------------- fused H/L fp16 GEMM with transform/box epilogue ----------------
#define ROWB  80
#define MATB  (128 * ROWB)
#define STAGE (3 * MATB)
#define GSMEM (3 * STAGE)

__device__ __forceinline__ void ldsm4(uint32_t* r, uint32_t addr) {
    asm volatile("ldmatrix.sync.aligned.m8n8.x4.shared.b16 {%0,%1,%2,%3}, [%4];"
                 : "=r"(r[0]), "=r"(r[1]), "=r"(r[2]), "=r"(r[3]) : "r"(addr));
}
__device__ __forceinline__ void mma16816(float* c, const uint32_t* a, const uint32_t* b) {
    asm volatile(
        "mma.sync.aligned.m16n8k16.row.col.f32.f16.f16.f32 "
        "{%0,%1,%2,%3}, {%4,%5,%6,%7}, {%8,%9}, {%0,%1,%2,%3};"
        : "+f"(c[0]), "+f"(c[1]), "+f"(c[2]), "+f"(c[3])
        : "r"(a[0]), "r"(a[1]), "r"(a[2]), "r"(a[3]), "r"(b[0]), "r"(b[1]));
}

__device__ __forceinline__ void issue_chunk(uint32_t sb, int slot,
                                            const __half* Af, const __half* B,
                                            int row0, int col0, int k0, int tid) {
    uint32_t sbase = sb + slot * STAGE;
    #pragma unroll
    for (int i = 0; i < 6; ++i) {
        int q = tid + (i << 8);
        int mat = q >> 9;
        int r = (q >> 2) & 127;
        int g = q & 3;
        const __half* src;
        int grow;
        if (mat < 2) { src = Af + ((size_t)mat << 22); grow = row0 + r; }
        else         { src = B;                        grow = col0 + r; }
        const void* gp = src + (size_t)grow * NH + k0 + (g << 3);
        uint32_t sp = sbase + mat * MATB + r * ROWB + (g << 4);
        asm volatile("cp.async.cg.shared.global [%0], [%1], 16;" :: "r"(sp), "l"(gp));
    }
    asm volatile("cp.async.commit_group;" ::: "memory");
}

// mode 1: TRANSFORM epilogue (diag arrays = layer j-1, bj = b[j-1]) -> fp16 Aout + bias atomics
// mode 2: BOX epilogue -> atomicAdd row dots into lowv/highv (Ng = NIN guard)
__global__ void __launch_bounds__(256) hgemm_k(const __half* __restrict__ Af,
                                               const __half* __restrict__ B,
                                               __half* __restrict__ AoutH, __half* __restrict__ AoutL,
                                               const float* __restrict__ wld, const float* __restrict__ whd,
                                               const float* __restrict__ bhrd, const float* __restrict__ bjv,
                                               float* __restrict__ bh, float* __restrict__ bl,
                                               const float* __restrict__ l0, const float* __restrict__ h0,
                                               float* __restrict__ lowv, float* __restrict__ highv,
                                               int Ng, int mode) {
    extern __shared__ char smem[];
    const uint32_t sb = smem_u32(smem);
    const int tid = threadIdx.x, lane = tid & 31, wid = tid >> 5;
    const int row0 = blockIdx.y * 128, col0 = blockIdx.x * 128;
    const int half = wid >> 2, wq = wid & 3;
    const int warpM = (wq & 1) << 6, warpN = (wq >> 1) << 6;

    float acc[4][8][4];
    #pragma unroll
    for (int mi = 0; mi < 4; ++mi)
        #pragma unroll
        for (int ni = 0; ni < 8; ++ni)
            #pragma unroll
            for (int e = 0; e < 4; ++e) acc[mi][ni][e] = 0.f;

    issue_chunk(sb, 0, Af, B, row0, col0, 0, tid);
    issue_chunk(sb, 1, Af, B, row0, col0, 32, tid);

    const uint32_t aoff = (uint32_t)((lane & 15) * ROWB + ((lane >> 4) << 4));
    const uint32_t boff = (uint32_t)(((((lane >> 4) & 1) << 3) + (lane & 7)) * ROWB + (((lane >> 3) & 1) << 4));

    const int CHUNKS = 64;
    for (int c = 0; c < CHUNKS; ++c) {
        asm volatile("cp.async.wait_group 1;" ::: "memory");
        __syncthreads();
        if (c + 2 < CHUNKS)
            issue_chunk(sb, (c + 2) % 3, Af, B, row0, col0, (c + 2) * 32, tid);

        uint32_t st = sb + (c % 3) * STAGE;
        uint32_t sA = st + half * MATB + warpM * ROWB + aoff;
        uint32_t sB = st + 2 * MATB + warpN * ROWB + boff;

        #pragma unroll
        for (int ks = 0; ks < 2; ++ks) {
            uint32_t ko = ks * 32;
            uint32_t a[4][4], bb[4][4];
            #pragma unroll
            for (int mi = 0; mi < 4; ++mi) ldsm4(a[mi], sA + mi * (16 * ROWB) + ko);
            #pragma unroll
            for (int pi = 0; pi < 4; ++pi) ldsm4(bb[pi], sB + pi * (16 * ROWB) + ko);
            #pragma unroll
            for (int mi = 0; mi < 4; ++mi)
                #pragma unroll
                for (int ni = 0; ni < 8; ++ni)
                    mma16816(acc[mi][ni], a[mi], &bb[ni >> 1][(ni & 1) << 1]);
        }
    }

    float rowsum[4][2];
    #pragma unroll
    for (int mi = 0; mi < 4; ++mi) { rowsum[mi][0] = 0.f; rowsum[mi][1] = 0.f; }

    if (mode == 1) {
        __half* Aout = half ? AoutL : AoutH;
        #pragma unroll
        for (int ni = 0; ni < 8; ++ni) {
            int gc = col0 + warpN + ni * 8 + ((lane & 3) << 1);
            float wh0 = whd[gc], wh1 = whd[gc + 1];
            float wl0 = wld[gc], wl1 = wld[gc + 1];
            float br0 = bhrd[gc], br1 = bhrd[gc + 1];
            float bj0 = bjv[gc], bj1 = bjv[gc + 1];
            float m0 = (wh0 != 0.f) ? 1.f : 0.f, m1 = (wh1 != 0.f) ? 1.f : 0.f;
            #pragma unroll
            for (int mi = 0; mi < 4; ++mi)
                #pragma unroll
                for (int e = 0; e < 2; ++e) {
                    float v0 = acc[mi][ni][2 * e], v1 = acc[mi][ni][2 * e + 1];
                    float t0, t1, s;
                    if (half == 0) {
                        t0 = (v0 > 0.f ? v0 * wh0 : v0 * wl0) * m0;
                        t1 = (v1 > 0.f ? v1 * wh1 : v1 * wl1) * m1;
                        s = fmaxf(v0, 0.f) * m0 * br0 + t0 * bj0 + fmaxf(v1, 0.f) * m1 * br1 + t1 * bj1;
                    } else {
                        t0 = (v0 > 0.f ? v0 * wl0 : v0 * wh0) * m0;
                        t1 = (v1 > 0.f ? v1 * wl1 : v1 * wh1) * m1;
                        s = fminf(v0, 0.f) * m0 * br0 + t0 * bj0 + fminf(v1, 0.f) * m1 * br1 + t1 * bj1;
                    }
                    rowsum[mi][e] += s;
                    int gr = row0 + warpM + mi * 16 + (lane >> 2) + e * 8;
                    *reinterpret_cast<__half2*>(Aout + (size_t)gr * NH + gc) = __floats2half2_rn(t0, t1);
                }
        }
        float* bacc = half ? bl : bh;
        #pragma unroll
        for (int mi = 0; mi < 4; ++mi)
            #pragma unroll
            for (int e = 0; e < 2; ++e) {
                float s = rowsum[mi][e];
                s += __shfl_xor_sync(0xffffffffu, s, 1);
                s += __shfl_xor_sync(0xffffffffu, s, 2);
                if ((lane & 3) == 0) {
                    int gr = row0 + warpM + mi * 16 + (lane >> 2) + e * 8;
                    atomicAdd(&bacc[gr], s);
                }
            }
    } else {
        #pragma unroll
        for (int ni = 0; ni < 8; ++ni) {
            int gc = col0 + warpN + ni * 8 + ((lane & 3) << 1);
            float L0 = (gc < Ng) ? l0[gc] : 0.f;
            float H0 = (gc < Ng) ? h0[gc] : 0.f;
            float L1 = (gc + 1 < Ng) ? l0[gc + 1] : 0.f;
            float H1 = (gc + 1 < Ng) ? h0[gc + 1] : 0.f;
            #pragma unroll
            for (int mi = 0; mi < 4; ++mi)
                #pragma unroll
                for (int e = 0; e < 2; ++e) {
                    float v0 = acc[mi][ni][2 * e], v1 = acc[mi][ni][2 * e + 1];
                    float s;
                    if (half == 0)
                        s = (v0 >= 0.f ? v0 * H0 : v0 * L0) + (v1 >= 0.f ? v1 * H1 : v1 * L1);
                    else
                        s = (v0 >= 0.f ? v0 * L0 : v0 * H0) + (v1 >= 0.f ? v1 * L1 : v1 * H1);
                    rowsum[mi][e] += s;
                }
        }
        float* outv = half ? lowv : highv;
        #pragma unroll
        for (int mi = 0; mi < 4; ++mi)
            #pragma unroll
            for (int e = 0; e < 2; ++e) {
                float s = rowsum[mi][e];
                s += __shfl_xor_sync(0xffffffffu, s, 1);
                s += __shfl_xor_sync(0xffffffffu, s, 2);
                if ((lane & 3) == 0) {
                    int gr = row0 + warpM + mi * 16 + (lane >> 2) + e * 8;
                    atomicAdd(&outv[gr], s);
                }
            }
    }
}

// ---------------- driver ----------------
extern "C" void kernel_launch(void* const* d_in, const int* in_sizes, int n_in,
                              void* d_out, int out_size) {
    const float* x  = (const float*)d_in[0];
    const float* lo = (const float*)d_in[1];
    const float* hi = (const float*)d_in[2];
    const float* W[5];
    const float* b[5];
    for (int i = 0; i < 5; ++i) { W[i] = (const float*)d_in[3 + 2 * i]; b[i] = (const float*)d_in[4 + 2 * i]; }
    float* out = (float*)d_out;

    cudaFuncSetAttribute(hgemm_k, cudaFuncAttributeMaxDynamicSharedMemorySize, GSMEM);

    void* p;
    __half *Af, *WT;
    cudaGetSymbolAddress(&p, g_Af); Af = (__half*)p;
    cudaGetSymbolAddress(&p, g_WT); WT = (__half*)p;
    float *sAH, *sAL, *sCH, *sCL, *PH, *PL;
    cudaGetSymbolAddress(&p, g_sA);   sAH = (float*)p; sAL = sAH + NOUT * NH;
    cudaGetSymbolAddress(&p, g_sC);   sCH = (float*)p; sCL = sCH + NOUT * NH;
    cudaGetSymbolAddress(&p, g_part); PH = (float*)p; PL = PH + 8 * NOUT * NH;
    float *xa, *xb, *lowv, *highv, *wl, *wh, *bhr, *bh, *bl, *x0, *l0, *h0;
    cudaGetSymbolAddress(&p, g_xa);   xa = (float*)p;
    cudaGetSymbolAddress(&p, g_xb);   xb = (float*)p;
    cudaGetSymbolAddress(&p, g_low);  lowv = (float*)p;
    cudaGetSymbolAddress(&p, g_high); highv = (float*)p;
    cudaGetSymbolAddress(&p, g_wl);   wl = (float*)p;
    cudaGetSymbolAddress(&p, g_wh);   wh = (float*)p;
    cudaGetSymbolAddress(&p, g_bhr);  bhr = (float*)p;
    cudaGetSymbolAddress(&p, g_bh);   bh = (float*)p;
    cudaGetSymbolAddress(&p, g_bl);   bl = (float*)p;
    cudaGetSymbolAddress(&p, g_x0);   x0 = (float*)p;
    cudaGetSymbolAddress(&p, g_l0);   l0 = (float*)p;
    cudaGetSymbolAddress(&p, g_h0);   h0 = (float*)p;

    normalize_k<<<(NIN + 255) / 256, 256>>>(x, lo, hi, x0, l0, h0, NIN);

    // transpose weights W0..W3 to fp16 (B operands), W0 padded to 896 rows
    {
        dim3 blk(32, 8);
        wsplit_k<<<dim3(28, 64), blk>>>(W[0], WT, NIN);
        for (int j = 1; j < 4; ++j)
            wsplit_k<<<dim3(64, 64), blk>>>(W[j], WT + (size_t)j * NHNH, NH);
    }

    // layer 0
    matvec_k<<<NH / 8, 256>>>(W[0], x0, b[0], xa, NH, NIN);
    box_k<<<NH, 256>>>(W[0], W[0], b[0], b[0], l0, h0, lowv, highv, NIN, NIN);
    relu_abs_k<<<NH / 256, 256>>>(xa, lowv, highv, nullptr, nullptr, wl, wh, bhr, NH);

    float* xin = xa;
    float* xout = xb;
    // layers 1..3: fused tensor-core chains
    for (int i = 1; i < 4; ++i) {
        zero2_k<<<NH / 256, 256>>>(lowv, highv, NH);
        int cur = 0;
        relu_bs_first_k<<<NH, 256>>>(W[i], xin, b[i],
                                     wl + (i - 1) * NH, wh + (i - 1) * NH, bhr + (i - 1) * NH, b[i - 1],
                                     Af, Af + (size_t)NHNH, bh, bl, xout);
        for (int j = i - 1; j >= 1; --j) {
            __half* Ain  = Af + (size_t)cur * 2 * NHNH;
            __half* AoH  = Af + (size_t)(cur ^ 1) * 2 * NHNH;
            hgemm_k<<<dim3(16, 16), 256, GSMEM>>>(Ain, WT + (size_t)j * NHNH,
                                                  AoH, AoH + (size_t)NHNH,
                                                  wl + (j - 1) * NH, wh + (j - 1) * NH,
                                                  bhr + (j - 1) * NH, b[j - 1],
                                                  bh, bl, nullptr, nullptr, nullptr, nullptr,
                                                  NH, 1);
            cur ^= 1;
        }
        {
            __half* Ain = Af + (size_t)cur * 2 * NHNH;
            hgemm_k<<<dim3(7, 16), 256, GSMEM>>>(Ain, WT,
                                                 nullptr, nullptr,
                                                 nullptr, nullptr, nullptr, nullptr,
                                                 nullptr, nullptr, l0, h0, lowv, highv,
                                                 NIN, 2);
        }
        relu_abs_k<<<NH / 256, 256>>>(xout, lowv, highv, bh, bl,
                                      wl + i * NH, wh + i * NH, bhr + i * NH, NH);
        float* t = xin; xin = xout; xout = t;
    }

    // layer 4 (M=10): fp32 skinny chain
    matvec_k<<<2, 256>>>(W[4], xin, b[4], xout, NOUT, NH);
    {
        const float* srch = W[4];
        const float* srcl = W[4];
        bool first = true;
        for (int j = 3; j >= 0; --j) {
            relu_bs_f32_k<<<NOUT, 256>>>(srch, srcl, sAH, sAL, wl + j * NH, wh + j * NH,
                                         bhr + j * NH, b[j], bh, bl, first ? b[4] : nullptr, NH);
            int Ng = (j == 0) ? NIN : NH;
            skinny_k<<<dim3((Ng + 127) / 128, 8), 128>>>(sAH, sAL, W[j], PH, PL, Ng);
            sreduce_k<<<(NOUT * Ng + 255) / 256, 256>>>(PH, PL, sCH, sCL, Ng);
            srch = sCH; srcl = sCL; first = false;
        }
        box_k<<<NOUT, 256>>>(sCH, sCL, bh, bl, l0, h0, lowv, highv, NIN, NH);
        write_out_k<<<1, 32>>>(xout, lowv, highv, out);
    }
    (void)in_sizes; (void)n_in; (void)out_size;
}

// round 8
// speedup vs baseline: 7.1655x; 1.0056x over previous
#include <cuda_runtime.h>
#include <cuda_fp16.h>
#include <cstdint>

#define MEANC 0.1307f
#define STDC  0.3081f
#define NIN   784
#define NH    2048
#define NOUT  10
#define NHNH  (NH * NH)

// ---------------- device scratch ----------------
__device__ __half g_Af[4][NHNH];     // buf0: AH,AL ; buf1: AH,AL
__device__ __half g_WT[4][NHNH];     // weight^T fp16
__device__ float g_part[4][8 * NOUT * NH];   // 2 ping-pong sets of (PH, PL)
__device__ float g_xa[NH], g_xb[NH], g_low[NH], g_high[NH];
__device__ float g_wl[4 * NH], g_wh[4 * NH], g_bhr[4 * NH];
__device__ float g_bh[NH], g_bl[NH];
__device__ float g_x0[NIN], g_l0[NIN], g_h0[NIN];

// ---------------- helpers ----------------
__device__ __forceinline__ uint32_t smem_u32(const void* p) {
    uint32_t a;
    asm("{ .reg .u64 t; cvta.to.shared.u64 t, %1; cvt.u32.u64 %0, t; }" : "=r"(a) : "l"(p));
    return a;
}

__device__ __forceinline__ void blkred3(float& a, float& b, float& c) {
    const unsigned F = 0xffffffffu;
    #pragma unroll
    for (int o = 16; o > 0; o >>= 1) {
        a += __shfl_down_sync(F, a, o);
        b += __shfl_down_sync(F, b, o);
        c += __shfl_down_sync(F, c, o);
    }
    __shared__ float sa[8], sb[8], sc[8];
    int w = threadIdx.x >> 5, lane = threadIdx.x & 31;
    if (lane == 0) { sa[w] = a; sb[w] = b; sc[w] = c; }
    __syncthreads();
    if (w == 0) {
        a = (lane < 8) ? sa[lane] : 0.f;
        b = (lane < 8) ? sb[lane] : 0.f;
        c = (lane < 8) ? sc[lane] : 0.f;
        #pragma unroll
        for (int o = 4; o > 0; o >>= 1) {
            a += __shfl_down_sync(F, a, o);
            b += __shfl_down_sync(F, b, o);
            c += __shfl_down_sync(F, c, o);
        }
    }
}

// ---------------- small kernels ----------------
__global__ void normalize_k(const float* x, const float* lo, const float* hi,
                            float* x0, float* l0, float* h0, int n) {
    int i = blockIdx.x * blockDim.x + threadIdx.x;
    if (i < n) {
        x0[i] = (x[i] - MEANC) / STDC;
        l0[i] = (lo[i] - MEANC) / STDC;
        h0[i] = (hi[i] - MEANC) / STDC;
    }
}

__global__ void matvec_k(const float* __restrict__ W, const float* __restrict__ xin,
                         const float* __restrict__ b, float* __restrict__ xout, int M, int K) {
    int row = blockIdx.x * (blockDim.x >> 5) + (threadIdx.x >> 5);
    if (row >= M) return;
    int lane = threadIdx.x & 31;
    float s = 0.f;
    const float* wr = W + (size_t)row * K;
    for (int k = lane; k < K; k += 32) s += wr[k] * xin[k];
    #pragma unroll
    for (int o = 16; o > 0; o >>= 1) s += __shfl_down_sync(0xffffffffu, s, o);
    if (lane == 0) xout[row] = s + b[row];
}

// layer 0 fused: matvec + interval box over W0 (single W0 read)
__global__ void box0_k(const float* __restrict__ W0, const float* __restrict__ x0,
                       const float* __restrict__ b0, const float* __restrict__ l0,
                       const float* __restrict__ h0, float* __restrict__ xa,
                       float* __restrict__ lowv, float* __restrict__ highv) {
    int m = blockIdx.x;
    size_t base = (size_t)m * NIN;
    float sx = 0.f, sh = 0.f, sl = 0.f;
    for (int k = threadIdx.x; k < NIN; k += blockDim.x) {
        float w = W0[base + k];
        float l = l0[k], h = h0[k];
        sx += w * x0[k];
        sh += (w >= 0.f) ? w * h : w * l;
        sl += (w >= 0.f) ? w * l : w * h;
    }
    blkred3(sx, sh, sl);
    if (threadIdx.x == 0) {
        float bb = b0[m];
        xa[m] = sx + bb;
        highv[m] = sh + bb;
        lowv[m] = sl + bb;
    }
}

// chain start: fused matvec + relu-backsub transform of W[i], fp16 A emission.
// Also zeroes lowv/highv for the upcoming box-GEMM atomics.
__global__ void relu_bs_first_k(const float* __restrict__ W, const float* __restrict__ xin,
                                const float* __restrict__ bi,
                                const float* __restrict__ wld, const float* __restrict__ whd,
                                const float* __restrict__ bhrd, const float* __restrict__ bj,
                                __half* __restrict__ AH, __half* __restrict__ AL,
                                float* __restrict__ bh, float* __restrict__ bl,
                                float* __restrict__ xout,
                                float* __restrict__ lowv, float* __restrict__ highv) {
    int m = blockIdx.x;
    size_t base = (size_t)m * NH;
    float sh = 0.f, sl = 0.f, sx = 0.f;
    for (int k = threadIdx.x; k < NH; k += blockDim.x) {
        float whk = whd[k], wlk = wld[k], brk = bhrd[k], bjk = bj[k];
        float mask = (whk != 0.f) ? 1.f : 0.f;
        float w = W[base + k];
        float oh = (w > 0.f ? w * whk : w * wlk) * mask;
        float ol = (w > 0.f ? w * wlk : w * whk) * mask;
        AH[base + k] = __float2half(oh);
        AL[base + k] = __float2half(ol);
        sh += fmaxf(w, 0.f) * mask * brk + oh * bjk;
        sl += fminf(w, 0.f) * mask * brk + ol * bjk;
        sx += w * xin[k];
    }
    blkred3(sh, sl, sx);
    if (threadIdx.x == 0) {
        float bb = bi[m];
        bh[m] = bb + sh;
        bl[m] = bb + sl;
        xout[m] = sx + bb;
        lowv[m] = 0.f;
        highv[m] = 0.f;
    }
}

// relu relaxation; optionally adds bias terms (addbh/addbl) to raw box sums
__global__ void relu_abs_k(float* __restrict__ x, const float* __restrict__ lowv,
                           const float* __restrict__ highv,
                           const float* __restrict__ addbh, const float* __restrict__ addbl,
                           float* __restrict__ wl, float* __restrict__ wh,
                           float* __restrict__ bhr, int n) {
    int i = blockIdx.x * blockDim.x + threadIdx.x;
    if (i >= n) return;
    float l = lowv[i] + (addbl ? addbl[i] : 0.f);
    float h = highv[i] + (addbh ? addbh[i] : 0.f);
    bool cr = (l < 0.f) && (h > 0.f);
    float denom = cr ? (h - l) : 1.f;
    float ubs = cr ? h / denom : 0.f;
    float ubi = cr ? -(l * h) / denom : 0.f;
    float lam = (l * l > h * h) ? 0.f : 1.f;
    float keep = (h <= 0.f) ? 0.f : 1.f;
    wh[i] = cr ? ubs : keep;
    wl[i] = cr ? lam : keep;
    bhr[i] = ubi;
    x[i] = fmaxf(x[i], 0.f);
}

__global__ void write_out_k(const float* x5, const float* lowv, const float* highv, float* out) {
    int i = threadIdx.x;
    if (i < NOUT) { out[i] = x5[i]; out[NOUT + i] = lowv[i]; out[2 * NOUT + i] = highv[i]; }
}

// single-launch transpose of all 4 weights to fp16 (z = weight index)
__global__ void wsplit4_k(const float* __restrict__ W0, const float* __restrict__ W1,
                          const float* __restrict__ W2, const float* __restrict__ W3,
                          __half* __restrict__ WT) {
    int z = blockIdx.z;
    const float* W = (z == 0) ? W0 : (z == 1) ? W1 : (z == 2) ? W2 : W3;
    int fi = (z == 0) ? NIN : NH;
    __half* Th = WT + (size_t)z * NHNH;
    int nb = blockIdx.x * 32;
    if (z == 0 && nb >= 896) return;   // only pad to 896 rows for W0
    __shared__ float t[32][33];
    int tx = threadIdx.x, ty = threadIdx.y;
    int kb = blockIdx.y * 32;
    #pragma unroll
    for (int i = 0; i < 4; ++i) {
        int k = kb + ty + i * 8, n = nb + tx;
        t[ty + i * 8][tx] = (n < fi) ? W[(size_t)k * fi + n] : 0.f;
    }
    __syncthreads();
    #pragma unroll
    for (int i = 0; i < 4; ++i) {
        int n = nb + ty + i * 8, k = kb + tx;
        Th[(size_t)n * NH + k] = __float2half(t[tx][ty + i * 8]);
    }
}

// ---------------- layer-4 fused skinny chain ----------------
__global__ void initb4_k(const float* __restrict__ b4, float* __restrict__ bh, float* __restrict__ bl) {
    int i = threadIdx.x;
    if (i < NOUT) { bh[i] = b4[i]; bl[i] = b4[i]; }
}

// One backsub step for the M=10 chain, fully fused:
// reads prev 8-seg partials (or W4 direct), applies relu transform for layer diag,
// accumulates bias atomics (blockIdx.x==0), GEMM vs W[j], writes new partials.
__global__ void __launch_bounds__(128) skfuse_k(
    const float* __restrict__ PinH, const float* __restrict__ PinL,
    const float* __restrict__ Wfirst,
    const float* __restrict__ wld, const float* __restrict__ whd,
    const float* __restrict__ bhrd, const float* __restrict__ bj,
    const float* __restrict__ Wj,
    float* __restrict__ PoutH, float* __restrict__ PoutL,
    float* __restrict__ bh, float* __restrict__ bl, int Ng)
{
    __shared__ float sH[NOUT][256], sL[NOUT][256];
    const int t = threadIdx.x;
    const int seg = blockIdx.y;
    const int k0 = seg * 256;
    const bool dobias = (blockIdx.x == 0);
    float bHp[NOUT], bLp[NOUT];
    #pragma unroll
    for (int m = 0; m < NOUT; ++m) { bHp[m] = 0.f; bLp[m] = 0.f; }

    #pragma unroll
    for (int h = 0; h < 2; ++h) {
        int kk = t + h * 128;
        int k = k0 + kk;
        float whk = whd[k], wlk = wld[k], brk = bhrd[k], bjk = bj[k];
        float mask = (whk != 0.f) ? 1.f : 0.f;
        #pragma unroll
        for (int m = 0; m < NOUT; ++m) {
            float aH, aL;
            if (Wfirst) {
                aH = Wfirst[(size_t)m * NH + k];
                aL = aH;
            } else {
                aH = 0.f; aL = 0.f;
                #pragma unroll
                for (int s = 0; s < 8; ++s) {
                    aH += PinH[(size_t)(s * NOUT + m) * NH + k];
                    aL += PinL[(size_t)(s * NOUT + m) * NH + k];
                }
            }
            float oh = (aH > 0.f ? aH * whk : aH * wlk) * mask;
            float ol = (aL > 0.f ? aL * wlk : aL * whk) * mask;
            sH[m][kk] = oh;
            sL[m][kk] = ol;
            if (dobias) {
                bHp[m] += fmaxf(aH, 0.f) * mask * brk + oh * bjk;
                bLp[m] += fminf(aL, 0.f) * mask * brk + ol * bjk;
            }
        }
    }
    __syncthreads();

    if (dobias) {
        #pragma unroll
        for (int m = 0; m < NOUT; ++m) {
            float vH = bHp[m], vL = bLp[m];
            #pragma unroll
            for (int o = 16; o > 0; o >>= 1) {
                vH += __shfl_down_sync(0xffffffffu, vH, o);
                vL += __shfl_down_sync(0xffffffffu, vL, o);
            }
            if ((t & 31) == 0) { atomicAdd(&bh[m], vH); atomicAdd(&bl[m], vL); }
        }
    }

    int n = blockIdx.x * 128 + t;
    if (n < Ng) {
        float aH[NOUT], aL[NOUT];
        #pragma unroll
        for (int m = 0; m < NOUT; ++m) { aH[m] = 0.f; aL[m] = 0.f; }
        for (int kk = 0; kk < 256; ++kk) {
            float w = Wj[(size_t)(k0 + kk) * Ng + n];
            #pragma unroll
            for (int m = 0; m < NOUT; ++m) { aH[m] += sH[m][kk] * w; aL[m] += sL[m][kk] * w; }
        }
        #pragma unroll
        for (int m = 0; m < NOUT; ++m) {
            PoutH[(size_t)(seg * NOUT + m) * NH + n] = aH[m];
            PoutL[(size_t)(seg * NOUT + m) * NH + n] = aL[m];
        }
    }
}

// final interval box over the 8-seg partials of the layer-4 chain
__global__ void boxp_k(const float* __restrict__ PH, const float* __restrict__ PL,
                       const float* __restrict__ bh, const float* __restrict__ bl,
                       const float* __restrict__ l0, const float* __restrict__ h0,
                       float* __restrict__ lowv, float* __restrict__ highv) {
    int m = blockIdx.x;
    float sh = 0.f, sl = 0.f, d = 0.f;
    for (int n = threadIdx.x; n < NIN; n += blockDim.x) {
        float ah = 0.f, al = 0.f;
        #pragma unroll
        for (int s = 0; s < 8; ++s) {
            ah += PH[(size_t)(s * NOUT + m) * NH + n];
            al += PL[(size_t)(s * NOUT + m) * NH + n];
        }
        float l = l0[n], h = h0[n];
        sh += (ah >= 0.f) ? ah * h : ah * l;
        sl += (al >= 0.f) ? al * l : al * h;
    }
    blkred3(sh, sl, d);
    if (threadIdx.x == 0) { highv[m] = bh[m] + sh; lowv[m] = bl[m] + sl; }
}

// ---------------- fused H/L fp16 GEMM with transform/box epilogue ----------------
#define ROWB  80
#define MATB  (128 * ROWB)
#define STAGE (3 * MATB)
#define GSMEM (3 * STAGE)

__device__ __forceinline__ void ldsm4(uint32_t* r, uint32_t addr) {
    asm volatile("ldmatrix.sync.aligned.m8n8.x4.shared.b16 {%0,%1,%2,%3}, [%4];"
                 : "=r"(r[0]), "=r"(r[1]), "=r"(r[2]), "=r"(r[3]) : "r"(addr));
}
__device__ __forceinline__ void mma16816(float* c, const uint32_t* a, const uint32_t* b) {
    asm volatile(
        "mma.sync.aligned.m16n8k16.row.col.f32.f16.f16.f32 "
        "{%0,%1,%2,%3}, {%4,%5,%6,%7}, {%8,%9}, {%0,%1,%2,%3};"
        : "+f"(c[0]), "+f"(c[1]), "+f"(c[2]), "+f"(c[3])
        : "r"(a[0]), "r"(a[1]), "r"(a[2]), "r"(a[3]), "r"(b[0]), "r"(b[1]));
}

__device__ __forceinline__ void issue_chunk(uint32_t sb, int slot,
                                            const __half* Af, const __half* B,
                                            int row0, int col0, int k0, int tid) {
    uint32_t sbase = sb + slot * STAGE;
    #pragma unroll
    for (int i = 0; i < 6; ++i) {
        int q = tid + (i << 8);
        int mat = q >> 9;
        int r = (q >> 2) & 127;
        int g = q & 3;
        const __half* src;
        int grow;
        if (mat < 2) { src = Af + ((size_t)mat << 22); grow = row0 + r; }
        else         { src = B;                        grow = col0 + r; }
        const void* gp = src + (size_t)grow * NH + k0 + (g << 3);
        uint32_t sp = sbase + mat * MATB + r * ROWB + (g << 4);
        asm volatile("cp.async.cg.shared.global [%0], [%1], 16;" :: "r"(sp), "l"(gp));
    }
    asm volatile("cp.async.commit_group;" ::: "memory");
}

__global__ void __launch_bounds__(256) hgemm_k(const __half* __restrict__ Af,
                                               const __half* __restrict__ B,
                                               __half* __restrict__ AoutH, __half* __restrict__ AoutL,
                                               const float* __restrict__ wld, const float* __restrict__ whd,
                                               const float* __restrict__ bhrd, const float* __restrict__ bjv,
                                               float* __restrict__ bh, float* __restrict__ bl,
                                               const float* __restrict__ l0, const float* __restrict__ h0,
                                               float* __restrict__ lowv, float* __restrict__ highv,
                                               int Ng, int mode) {
    extern __shared__ char smem[];
    const uint32_t sb = smem_u32(smem);
    const int tid = threadIdx.x, lane = tid & 31, wid = tid >> 5;
    const int row0 = blockIdx.y * 128, col0 = blockIdx.x * 128;
    const int half = wid >> 2, wq = wid & 3;
    const int warpM = (wq & 1) << 6, warpN = (wq >> 1) << 6;

    float acc[4][8][4];
    #pragma unroll
    for (int mi = 0; mi < 4; ++mi)
        #pragma unroll
        for (int ni = 0; ni < 8; ++ni)
            #pragma unroll
            for (int e = 0; e < 4; ++e) acc[mi][ni][e] = 0.f;

    issue_chunk(sb, 0, Af, B, row0, col0, 0, tid);
    issue_chunk(sb, 1, Af, B, row0, col0, 32, tid);

    const uint32_t aoff = (uint32_t)((lane & 15) * ROWB + ((lane >> 4) << 4));
    const uint32_t boff = (uint32_t)(((((lane >> 4) & 1) << 3) + (lane & 7)) * ROWB + (((lane >> 3) & 1) << 4));

    const int CHUNKS = 64;
    for (int c = 0; c < CHUNKS; ++c) {
        asm volatile("cp.async.wait_group 1;" ::: "memory");
        __syncthreads();
        if (c + 2 < CHUNKS)
            issue_chunk(sb, (c + 2) % 3, Af, B, row0, col0, (c + 2) * 32, tid);

        uint32_t st = sb + (c % 3) * STAGE;
        uint32_t sA = st + half * MATB + warpM * ROWB + aoff;
        uint32_t sB = st + 2 * MATB + warpN * ROWB + boff;

        #pragma unroll
        for (int ks = 0; ks < 2; ++ks) {
            uint32_t ko = ks * 32;
            uint32_t a[4][4], bb[4][4];
            #pragma unroll
            for (int mi = 0; mi < 4; ++mi) ldsm4(a[mi], sA + mi * (16 * ROWB) + ko);
            #pragma unroll
            for (int pi = 0; pi < 4; ++pi) ldsm4(bb[pi], sB + pi * (16 * ROWB) + ko);
            #pragma unroll
            for (int mi = 0; mi < 4; ++mi)
                #pragma unroll
                for (int ni = 0; ni < 8; ++ni)
                    mma16816(acc[mi][ni], a[mi], &bb[ni >> 1][(ni & 1) << 1]);
        }
    }

    float rowsum[4][2];
    #pragma unroll
    for (int mi = 0; mi < 4; ++mi) { rowsum[mi][0] = 0.f; rowsum[mi][1] = 0.f; }

    if (mode == 1) {
        __half* Aout = half ? AoutL : AoutH;
        #pragma unroll
        for (int ni = 0; ni < 8; ++ni) {
            int gc = col0 + warpN + ni * 8 + ((lane & 3) << 1);
            float wh0 = whd[gc], wh1 = whd[gc + 1];
            float wl0 = wld[gc], wl1 = wld[gc + 1];
            float br0 = bhrd[gc], br1 = bhrd[gc + 1];
            float bj0 = bjv[gc], bj1 = bjv[gc + 1];
            float m0 = (wh0 != 0.f) ? 1.f : 0.f, m1 = (wh1 != 0.f) ? 1.f : 0.f;
            #pragma unroll
            for (int mi = 0; mi < 4; ++mi)
                #pragma unroll
                for (int e = 0; e < 2; ++e) {
                    float v0 = acc[mi][ni][2 * e], v1 = acc[mi][ni][2 * e + 1];
                    float t0, t1, s;
                    if (half == 0) {
                        t0 = (v0 > 0.f ? v0 * wh0 : v0 * wl0) * m0;
                        t1 = (v1 > 0.f ? v1 * wh1 : v1 * wl1) * m1;
                        s = fmaxf(v0, 0.f) * m0 * br0 + t0 * bj0 + fmaxf(v1, 0.f) * m1 * br1 + t1 * bj1;
                    } else {
                        t0 = (v0 > 0.f ? v0 * wl0 : v0 * wh0) * m0;
                        t1 = (v1 > 0.f ? v1 * wl1 : v1 * wh1) * m1;
                        s = fminf(v0, 0.f) * m0 * br0 + t0 * bj0 + fminf(v1, 0.f) * m1 * br1 + t1 * bj1;
                    }
                    rowsum[mi][e] += s;
                    int gr = row0 + warpM + mi * 16 + (lane >> 2) + e * 8;
                    *reinterpret_cast<__half2*>(Aout + (size_t)gr * NH + gc) = __floats2half2_rn(t0, t1);
                }
        }
        float* bacc = half ? bl : bh;
        #pragma unroll
        for (int mi = 0; mi < 4; ++mi)
            #pragma unroll
            for (int e = 0; e < 2; ++e) {
                float s = rowsum[mi][e];
                s += __shfl_xor_sync(0xffffffffu, s, 1);
                s += __shfl_xor_sync(0xffffffffu, s, 2);
                if ((lane & 3) == 0) {
                    int gr = row0 + warpM + mi * 16 + (lane >> 2) + e * 8;
                    atomicAdd(&bacc[gr], s);
                }
            }
    } else {
        #pragma unroll
        for (int ni = 0; ni < 8; ++ni) {
            int gc = col0 + warpN + ni * 8 + ((lane & 3) << 1);
            float L0 = (gc < Ng) ? l0[gc] : 0.f;
            float H0 = (gc < Ng) ? h0[gc] : 0.f;
            float L1 = (gc + 1 < Ng) ? l0[gc + 1] : 0.f;
            float H1 = (gc + 1 < Ng) ? h0[gc + 1] : 0.f;
            #pragma unroll
            for (int mi = 0; mi < 4; ++mi)
                #pragma unroll
                for (int e = 0; e < 2; ++e) {
                    float v0 = acc[mi][ni][2 * e], v1 = acc[mi][ni][2 * e + 1];
                    float s;
                    if (half == 0)
                        s = (v0 >= 0.f ? v0 * H0 : v0 * L0) + (v1 >= 0.f ? v1 * H1 : v1 * L1);
                    else
                        s = (v0 >= 0.f ? v0 * L0 : v0 * H0) + (v1 >= 0.f ? v1 * L1 : v1 * H1);
                    rowsum[mi][e] += s;
                }
        }
        float* outv = half ? lowv : highv;
        #pragma unroll
        for (int mi = 0; mi < 4; ++mi)
            #pragma unroll
            for (int e = 0; e < 2; ++e) {
                float s = rowsum[mi][e];
                s += __shfl_xor_sync(0xffffffffu, s, 1);
                s += __shfl_xor_sync(0xffffffffu, s, 2);
                if ((lane & 3) == 0) {
                    int gr = row0 + warpM + mi * 16 + (lane >> 2) + e * 8;
                    atomicAdd(&outv[gr], s);
                }
            }
    }
}

// ---------------- driver ----------------
extern "C" void kernel_launch(void* const* d_in, const int* in_sizes, int n_in,
                              void* d_out, int out_size) {
    const float* x  = (const float*)d_in[0];
    const float* lo = (const float*)d_in[1];
    const float* hi = (const float*)d_in[2];
    const float* W[5];
    const float* b[5];
    for (int i = 0; i < 5; ++i) { W[i] = (const float*)d_in[3 + 2 * i]; b[i] = (const float*)d_in[4 + 2 * i]; }
    float* out = (float*)d_out;

    cudaFuncSetAttribute(hgemm_k, cudaFuncAttributeMaxDynamicSharedMemorySize, GSMEM);

    void* p;
    __half *Af, *WT;
    cudaGetSymbolAddress(&p, g_Af); Af = (__half*)p;
    cudaGetSymbolAddress(&p, g_WT); WT = (__half*)p;
    float* P0;
    cudaGetSymbolAddress(&p, g_part); P0 = (float*)p;
    float* PH[2] = { P0,                      P0 + 2 * 8 * NOUT * NH };
    float* PL[2] = { P0 + 8 * NOUT * NH,      P0 + 3 * 8 * NOUT * NH };
    float *xa, *xb, *lowv, *highv, *wl, *wh, *bhr, *bh, *bl, *x0, *l0, *h0;
    cudaGetSymbolAddress(&p, g_xa);   xa = (float*)p;
    cudaGetSymbolAddress(&p, g_xb);   xb = (float*)p;
    cudaGetSymbolAddress(&p, g_low);  lowv = (float*)p;
    cudaGetSymbolAddress(&p, g_high); highv = (float*)p;
    cudaGetSymbolAddress(&p, g_wl);   wl = (float*)p;
    cudaGetSymbolAddress(&p, g_wh);   wh = (float*)p;
    cudaGetSymbolAddress(&p, g_bhr);  bhr = (float*)p;
    cudaGetSymbolAddress(&p, g_bh);   bh = (float*)p;
    cudaGetSymbolAddress(&p, g_bl);   bl = (float*)p;
    cudaGetSymbolAddress(&p, g_x0);   x0 = (float*)p;
    cudaGetSymbolAddress(&p, g_l0);   l0 = (float*)p;
    cudaGetSymbolAddress(&p, g_h0);   h0 = (float*)p;

    normalize_k<<<(NIN + 255) / 256, 256>>>(x, lo, hi, x0, l0, h0, NIN);

    // all weight transposes in one launch
    wsplit4_k<<<dim3(64, 64, 4), dim3(32, 8)>>>(W[0], W[1], W[2], W[3], WT);

    // layer 0: fused matvec + box
    box0_k<<<NH, 256>>>(W[0], x0, b[0], l0, h0, xa, lowv, highv);
    relu_abs_k<<<NH / 256, 256>>>(xa, lowv, highv, nullptr, nullptr, wl, wh, bhr, NH);

    float* xin = xa;
    float* xout = xb;
    // layers 1..3: fused tensor-core chains
    for (int i = 1; i < 4; ++i) {
        int cur = 0;
        relu_bs_first_k<<<NH, 256>>>(W[i], xin, b[i],
                                     wl + (i - 1) * NH, wh + (i - 1) * NH, bhr + (i - 1) * NH, b[i - 1],
                                     Af, Af + (size_t)NHNH, bh, bl, xout, lowv, highv);
        for (int j = i - 1; j >= 1; --j) {
            __half* Ain = Af + (size_t)cur * 2 * NHNH;
            __half* AoH = Af + (size_t)(cur ^ 1) * 2 * NHNH;
            hgemm_k<<<dim3(16, 16), 256, GSMEM>>>(Ain, WT + (size_t)j * NHNH,
                                                  AoH, AoH + (size_t)NHNH,
                                                  wl + (j - 1) * NH, wh + (j - 1) * NH,
                                                  bhr + (j - 1) * NH, b[j - 1],
                                                  bh, bl, nullptr, nullptr, nullptr, nullptr,
                                                  NH, 1);
            cur ^= 1;
        }
        {
            __half* Ain = Af + (size_t)cur * 2 * NHNH;
            hgemm_k<<<dim3(7, 16), 256, GSMEM>>>(Ain, WT,
                                                 nullptr, nullptr,
                                                 nullptr, nullptr, nullptr, nullptr,
                                                 nullptr, nullptr, l0, h0, lowv, highv,
                                                 NIN, 2);
        }
        relu_abs_k<<<NH / 256, 256>>>(xout, lowv, highv, bh, bl,
                                      wl + i * NH, wh + i * NH, bhr + i * NH, NH);
        float* t = xin; xin = xout; xout = t;
    }

    // layer 4 (M=10): fused fp32 skinny chain
    matvec_k<<<2, 256>>>(W[4], xin, b[4], xout, NOUT, NH);
    initb4_k<<<1, 32>>>(b[4], bh, bl);
    {
        int cur = 0;
        // j = 3 (first step, A = W4 direct)
        skfuse_k<<<dim3(16, 8), 128>>>(nullptr, nullptr, W[4],
                                       wl + 3 * NH, wh + 3 * NH, bhr + 3 * NH, b[3],
                                       W[3], PH[cur], PL[cur], bh, bl, NH);
        // j = 2, 1
        for (int j = 2; j >= 1; --j) {
            skfuse_k<<<dim3(16, 8), 128>>>(PH[cur], PL[cur], nullptr,
                                           wl + j * NH, wh + j * NH, bhr + j * NH, b[j],
                                           W[j], PH[cur ^ 1], PL[cur ^ 1], bh, bl, NH);
            cur ^= 1;
        }
        // j = 0 (Ng = NIN)
        skfuse_k<<<dim3(7, 8), 128>>>(PH[cur], PL[cur], nullptr,
                                      wl, wh, bhr, b[0],
                                      W[0], PH[cur ^ 1], PL[cur ^ 1], bh, bl, NIN);
        cur ^= 1;
        boxp_k<<<NOUT, 256>>>(PH[cur], PL[cur], bh, bl, l0, h0, lowv, highv);
        write_out_k<<<1, 32>>>(xout, lowv, highv, out);
    }
    (void)in_sizes; (void)n_in; (void)out_size;
}

// round 9
// speedup vs baseline: 7.8683x; 1.0981x over previous
#include <cuda_runtime.h>
#include <cuda_fp16.h>
#include <cstdint>

#define MEANC 0.1307f
#define STDC  0.3081f
#define NIN   784
#define NH    2048
#define NOUT  10
#define NHNH  (NH * NH)

// ---------------- device scratch ----------------
__device__ __half g_Af[4][NHNH];     // buf0: AH,AL ; buf1: AH,AL
__device__ __half g_WT[4][NHNH];     // weight^T fp16
__device__ float g_part[4][8 * NOUT * NH];   // 2 ping-pong sets of (PH, PL)
__device__ float g_xa[NH], g_xb[NH], g_low[NH], g_high[NH];
__device__ float g_wl[4 * NH], g_wh[4 * NH], g_bhr[4 * NH];
__device__ float g_bh[NH], g_bl[NH];
__device__ float g_x0[NIN], g_l0[NIN], g_h0[NIN];

// ---------------- helpers ----------------
__device__ __forceinline__ uint32_t smem_u32(const void* p) {
    uint32_t a;
    asm("{ .reg .u64 t; cvta.to.shared.u64 t, %1; cvt.u32.u64 %0, t; }" : "=r"(a) : "l"(p));
    return a;
}

__device__ __forceinline__ void blkred3(float& a, float& b, float& c) {
    const unsigned F = 0xffffffffu;
    #pragma unroll
    for (int o = 16; o > 0; o >>= 1) {
        a += __shfl_down_sync(F, a, o);
        b += __shfl_down_sync(F, b, o);
        c += __shfl_down_sync(F, c, o);
    }
    __shared__ float sa[8], sb[8], sc[8];
    int w = threadIdx.x >> 5, lane = threadIdx.x & 31;
    if (lane == 0) { sa[w] = a; sb[w] = b; sc[w] = c; }
    __syncthreads();
    if (w == 0) {
        a = (lane < 8) ? sa[lane] : 0.f;
        b = (lane < 8) ? sb[lane] : 0.f;
        c = (lane < 8) ? sc[lane] : 0.f;
        #pragma unroll
        for (int o = 4; o > 0; o >>= 1) {
            a += __shfl_down_sync(F, a, o);
            b += __shfl_down_sync(F, b, o);
            c += __shfl_down_sync(F, c, o);
        }
    }
}

// ---------------- small kernels ----------------
__global__ void normalize_k(const float* x, const float* lo, const float* hi,
                            float* x0, float* l0, float* h0, int n) {
    int i = blockIdx.x * blockDim.x + threadIdx.x;
    if (i < n) {
        x0[i] = (x[i] - MEANC) / STDC;
        l0[i] = (lo[i] - MEANC) / STDC;
        h0[i] = (hi[i] - MEANC) / STDC;
    }
}

__global__ void matvec_k(const float* __restrict__ W, const float* __restrict__ xin,
                         const float* __restrict__ b, float* __restrict__ xout, int M, int K) {
    int row = blockIdx.x * (blockDim.x >> 5) + (threadIdx.x >> 5);
    if (row >= M) return;
    int lane = threadIdx.x & 31;
    float s = 0.f;
    const float* wr = W + (size_t)row * K;
    for (int k = lane; k < K; k += 32) s += wr[k] * xin[k];
    #pragma unroll
    for (int o = 16; o > 0; o >>= 1) s += __shfl_down_sync(0xffffffffu, s, o);
    if (lane == 0) xout[row] = s + b[row];
}

// layer 0 fused: matvec + interval box over W0 (single W0 read)
__global__ void box0_k(const float* __restrict__ W0, const float* __restrict__ x0,
                       const float* __restrict__ b0, const float* __restrict__ l0,
                       const float* __restrict__ h0, float* __restrict__ xa,
                       float* __restrict__ lowv, float* __restrict__ highv) {
    int m = blockIdx.x;
    size_t base = (size_t)m * NIN;
    float sx = 0.f, sh = 0.f, sl = 0.f;
    for (int k = threadIdx.x; k < NIN; k += blockDim.x) {
        float w = W0[base + k];
        float l = l0[k], h = h0[k];
        sx += w * x0[k];
        sh += (w >= 0.f) ? w * h : w * l;
        sl += (w >= 0.f) ? w * l : w * h;
    }
    blkred3(sx, sh, sl);
    if (threadIdx.x == 0) {
        float bb = b0[m];
        xa[m] = sx + bb;
        highv[m] = sh + bb;
        lowv[m] = sl + bb;
    }
}

// chain start: fused matvec + relu-backsub transform of W[i], fp16 A emission.
// Also zeroes lowv/highv for the upcoming box-GEMM atomics.
__global__ void relu_bs_first_k(const float* __restrict__ W, const float* __restrict__ xin,
                                const float* __restrict__ bi,
                                const float* __restrict__ wld, const float* __restrict__ whd,
                                const float* __restrict__ bhrd, const float* __restrict__ bj,
                                __half* __restrict__ AH, __half* __restrict__ AL,
                                float* __restrict__ bh, float* __restrict__ bl,
                                float* __restrict__ xout,
                                float* __restrict__ lowv, float* __restrict__ highv) {
    int m = blockIdx.x;
    size_t base = (size_t)m * NH;
    float sh = 0.f, sl = 0.f, sx = 0.f;
    for (int k = threadIdx.x; k < NH; k += blockDim.x) {
        float whk = whd[k], wlk = wld[k], brk = bhrd[k], bjk = bj[k];
        float mask = (whk != 0.f) ? 1.f : 0.f;
        float w = W[base + k];
        float oh = (w > 0.f ? w * whk : w * wlk) * mask;
        float ol = (w > 0.f ? w * wlk : w * whk) * mask;
        AH[base + k] = __float2half(oh);
        AL[base + k] = __float2half(ol);
        sh += fmaxf(w, 0.f) * mask * brk + oh * bjk;
        sl += fminf(w, 0.f) * mask * brk + ol * bjk;
        sx += w * xin[k];
    }
    blkred3(sh, sl, sx);
    if (threadIdx.x == 0) {
        float bb = bi[m];
        bh[m] = bb + sh;
        bl[m] = bb + sl;
        xout[m] = sx + bb;
        lowv[m] = 0.f;
        highv[m] = 0.f;
    }
}

// relu relaxation; optionally adds bias terms (addbh/addbl) to raw box sums
__global__ void relu_abs_k(float* __restrict__ x, const float* __restrict__ lowv,
                           const float* __restrict__ highv,
                           const float* __restrict__ addbh, const float* __restrict__ addbl,
                           float* __restrict__ wl, float* __restrict__ wh,
                           float* __restrict__ bhr, int n) {
    int i = blockIdx.x * blockDim.x + threadIdx.x;
    if (i >= n) return;
    float l = lowv[i] + (addbl ? addbl[i] : 0.f);
    float h = highv[i] + (addbh ? addbh[i] : 0.f);
    bool cr = (l < 0.f) && (h > 0.f);
    float denom = cr ? (h - l) : 1.f;
    float ubs = cr ? h / denom : 0.f;
    float ubi = cr ? -(l * h) / denom : 0.f;
    float lam = (l * l > h * h) ? 0.f : 1.f;
    float keep = (h <= 0.f) ? 0.f : 1.f;
    wh[i] = cr ? ubs : keep;
    wl[i] = cr ? lam : keep;
    bhr[i] = ubi;
    x[i] = fmaxf(x[i], 0.f);
}

__global__ void write_out_k(const float* x5, const float* lowv, const float* highv, float* out) {
    int i = threadIdx.x;
    if (i < NOUT) { out[i] = x5[i]; out[NOUT + i] = lowv[i]; out[2 * NOUT + i] = highv[i]; }
}

// single-launch transpose of all 4 weights to fp16 (z = weight index)
__global__ void wsplit4_k(const float* __restrict__ W0, const float* __restrict__ W1,
                          const float* __restrict__ W2, const float* __restrict__ W3,
                          __half* __restrict__ WT) {
    int z = blockIdx.z;
    const float* W = (z == 0) ? W0 : (z == 1) ? W1 : (z == 2) ? W2 : W3;
    int fi = (z == 0) ? NIN : NH;
    __half* Th = WT + (size_t)z * NHNH;
    int nb = blockIdx.x * 32;
    if (z == 0 && nb >= 896) return;   // only pad to 896 rows for W0
    __shared__ float t[32][33];
    int tx = threadIdx.x, ty = threadIdx.y;
    int kb = blockIdx.y * 32;
    #pragma unroll
    for (int i = 0; i < 4; ++i) {
        int k = kb + ty + i * 8, n = nb + tx;
        t[ty + i * 8][tx] = (n < fi) ? W[(size_t)k * fi + n] : 0.f;
    }
    __syncthreads();
    #pragma unroll
    for (int i = 0; i < 4; ++i) {
        int n = nb + ty + i * 8, k = kb + tx;
        Th[(size_t)n * NH + k] = __float2half(t[tx][ty + i * 8]);
    }
}

// ---------------- layer-4 fused skinny chain ----------------
__global__ void initb4_k(const float* __restrict__ b4, float* __restrict__ bh, float* __restrict__ bl) {
    int i = threadIdx.x;
    if (i < NOUT) { bh[i] = b4[i]; bl[i] = b4[i]; }
}

__global__ void __launch_bounds__(128) skfuse_k(
    const float* __restrict__ PinH, const float* __restrict__ PinL,
    const float* __restrict__ Wfirst,
    const float* __restrict__ wld, const float* __restrict__ whd,
    const float* __restrict__ bhrd, const float* __restrict__ bj,
    const float* __restrict__ Wj,
    float* __restrict__ PoutH, float* __restrict__ PoutL,
    float* __restrict__ bh, float* __restrict__ bl, int Ng)
{
    __shared__ float sH[NOUT][256], sL[NOUT][256];
    const int t = threadIdx.x;
    const int seg = blockIdx.y;
    const int k0 = seg * 256;
    const bool dobias = (blockIdx.x == 0);
    float bHp[NOUT], bLp[NOUT];
    #pragma unroll
    for (int m = 0; m < NOUT; ++m) { bHp[m] = 0.f; bLp[m] = 0.f; }

    #pragma unroll
    for (int h = 0; h < 2; ++h) {
        int kk = t + h * 128;
        int k = k0 + kk;
        float whk = whd[k], wlk = wld[k], brk = bhrd[k], bjk = bj[k];
        float mask = (whk != 0.f) ? 1.f : 0.f;
        #pragma unroll
        for (int m = 0; m < NOUT; ++m) {
            float aH, aL;
            if (Wfirst) {
                aH = Wfirst[(size_t)m * NH + k];
                aL = aH;
            } else {
                aH = 0.f; aL = 0.f;
                #pragma unroll
                for (int s = 0; s < 8; ++s) {
                    aH += PinH[(size_t)(s * NOUT + m) * NH + k];
                    aL += PinL[(size_t)(s * NOUT + m) * NH + k];
                }
            }
            float oh = (aH > 0.f ? aH * whk : aH * wlk) * mask;
            float ol = (aL > 0.f ? aL * wlk : aL * whk) * mask;
            sH[m][kk] = oh;
            sL[m][kk] = ol;
            if (dobias) {
                bHp[m] += fmaxf(aH, 0.f) * mask * brk + oh * bjk;
                bLp[m] += fminf(aL, 0.f) * mask * brk + ol * bjk;
            }
        }
    }
    __syncthreads();

    if (dobias) {
        #pragma unroll
        for (int m = 0; m < NOUT; ++m) {
            float vH = bHp[m], vL = bLp[m];
            #pragma unroll
            for (int o = 16; o > 0; o >>= 1) {
                vH += __shfl_down_sync(0xffffffffu, vH, o);
                vL += __shfl_down_sync(0xffffffffu, vL, o);
            }
            if ((t & 31) == 0) { atomicAdd(&bh[m], vH); atomicAdd(&bl[m], vL); }
        }
    }

    int n = blockIdx.x * 128 + t;
    if (n < Ng) {
        float aH[NOUT], aL[NOUT];
        #pragma unroll
        for (int m = 0; m < NOUT; ++m) { aH[m] = 0.f; aL[m] = 0.f; }
        for (int kk = 0; kk < 256; ++kk) {
            float w = Wj[(size_t)(k0 + kk) * Ng + n];
            #pragma unroll
            for (int m = 0; m < NOUT; ++m) { aH[m] += sH[m][kk] * w; aL[m] += sL[m][kk] * w; }
        }
        #pragma unroll
        for (int m = 0; m < NOUT; ++m) {
            PoutH[(size_t)(seg * NOUT + m) * NH + n] = aH[m];
            PoutL[(size_t)(seg * NOUT + m) * NH + n] = aL[m];
        }
    }
}

__global__ void boxp_k(const float* __restrict__ PH, const float* __restrict__ PL,
                       const float* __restrict__ bh, const float* __restrict__ bl,
                       const float* __restrict__ l0, const float* __restrict__ h0,
                       float* __restrict__ lowv, float* __restrict__ highv) {
    int m = blockIdx.x;
    float sh = 0.f, sl = 0.f, d = 0.f;
    for (int n = threadIdx.x; n < NIN; n += blockDim.x) {
        float ah = 0.f, al = 0.f;
        #pragma unroll
        for (int s = 0; s < 8; ++s) {
            ah += PH[(size_t)(s * NOUT + m) * NH + n];
            al += PL[(size_t)(s * NOUT + m) * NH + n];
        }
        float l = l0[n], h = h0[n];
        sh += (ah >= 0.f) ? ah * h : ah * l;
        sl += (al >= 0.f) ? al * l : al * h;
    }
    blkred3(sh, sl, d);
    if (threadIdx.x == 0) { highv[m] = bh[m] + sh; lowv[m] = bl[m] + sl; }
}

// ---------------- fused H/L fp16 GEMM with transform/box epilogue ----------------
// k-chunk 64, 2-stage cp.async double buffer, register-level fragment pipelining.
#define ROWB  144                    // 64 fp16 = 128B data + 16B pad (conflict-free ldsm phases)
#define MATB  (128 * ROWB)           // 18432
#define STAGE (3 * MATB)             // 55296 (AH, AL, B)
#define GSMEM (2 * STAGE)            // 110592

__device__ __forceinline__ void ldsm4(uint32_t* r, uint32_t addr) {
    asm volatile("ldmatrix.sync.aligned.m8n8.x4.shared.b16 {%0,%1,%2,%3}, [%4];"
                 : "=r"(r[0]), "=r"(r[1]), "=r"(r[2]), "=r"(r[3]) : "r"(addr));
}
__device__ __forceinline__ void mma16816(float* c, const uint32_t* a, const uint32_t* b) {
    asm volatile(
        "mma.sync.aligned.m16n8k16.row.col.f32.f16.f16.f32 "
        "{%0,%1,%2,%3}, {%4,%5,%6,%7}, {%8,%9}, {%0,%1,%2,%3};"
        : "+f"(c[0]), "+f"(c[1]), "+f"(c[2]), "+f"(c[3])
        : "r"(a[0]), "r"(a[1]), "r"(a[2]), "r"(a[3]), "r"(b[0]), "r"(b[1]));
}

__device__ __forceinline__ void issue_chunk(uint32_t sb, int slot,
                                            const __half* Af, const __half* B,
                                            int row0, int col0, int k0, int tid) {
    uint32_t sbase = sb + slot * STAGE;
    #pragma unroll
    for (int i = 0; i < 12; ++i) {
        int q = tid + (i << 8);
        int mat = q >> 10;           // 0: AH, 1: AL, 2: B  (1024 quads per matrix)
        int r = (q >> 3) & 127;
        int g = q & 7;               // 16B chunk within 128B row
        const __half* src;
        int grow;
        if (mat < 2) { src = Af + ((size_t)mat << 22); grow = row0 + r; }
        else         { src = B;                        grow = col0 + r; }
        const void* gp = src + (size_t)grow * NH + k0 + (g << 3);
        uint32_t sp = sbase + mat * MATB + r * ROWB + (g << 4);
        asm volatile("cp.async.cg.shared.global [%0], [%1], 16;" :: "r"(sp), "l"(gp));
    }
    asm volatile("cp.async.commit_group;" ::: "memory");
}

__global__ void __launch_bounds__(256, 1) hgemm_k(const __half* __restrict__ Af,
                                               const __half* __restrict__ B,
                                               __half* __restrict__ AoutH, __half* __restrict__ AoutL,
                                               const float* __restrict__ wld, const float* __restrict__ whd,
                                               const float* __restrict__ bhrd, const float* __restrict__ bjv,
                                               float* __restrict__ bh, float* __restrict__ bl,
                                               const float* __restrict__ l0, const float* __restrict__ h0,
                                               float* __restrict__ lowv, float* __restrict__ highv,
                                               int Ng, int mode) {
    extern __shared__ char smem[];
    const uint32_t sb = smem_u32(smem);
    const int tid = threadIdx.x, lane = tid & 31, wid = tid >> 5;
    const int row0 = blockIdx.y * 128, col0 = blockIdx.x * 128;
    const int half = wid >> 2, wq = wid & 3;
    const int warpM = (wq & 1) << 6, warpN = (wq >> 1) << 6;

    float acc[4][8][4];
    #pragma unroll
    for (int mi = 0; mi < 4; ++mi)
        #pragma unroll
        for (int ni = 0; ni < 8; ++ni)
            #pragma unroll
            for (int e = 0; e < 4; ++e) acc[mi][ni][e] = 0.f;

    issue_chunk(sb, 0, Af, B, row0, col0, 0, tid);

    const uint32_t aoff = (uint32_t)((lane & 15) * ROWB + ((lane >> 4) << 4));
    const uint32_t boff = (uint32_t)(((((lane >> 4) & 1) << 3) + (lane & 7)) * ROWB + (((lane >> 3) & 1) << 4));

    uint32_t A0[4][4], B0[4][4], A1[4][4], B1[4][4];

    const int CHUNKS = 32;
    for (int c = 0; c < CHUNKS; ++c) {
        asm volatile("cp.async.wait_group 0;" ::: "memory");
        __syncthreads();   // chunk c resident; all warps done with slot (c-1)&1
        if (c + 1 < CHUNKS)
            issue_chunk(sb, (c + 1) & 1, Af, B, row0, col0, (c + 1) * 64, tid);

        uint32_t st = sb + (c & 1) * STAGE;
        uint32_t sA = st + half * MATB + warpM * ROWB + aoff;
        uint32_t sB = st + 2 * MATB + warpN * ROWB + boff;

        #define LDF(Ab, Bb, ko) do { \
            _Pragma("unroll") \
            for (int mi = 0; mi < 4; ++mi) ldsm4(Ab[mi], sA + mi * (16 * ROWB) + (ko)); \
            _Pragma("unroll") \
            for (int pi = 0; pi < 4; ++pi) ldsm4(Bb[pi], sB + pi * (16 * ROWB) + (ko)); \
        } while (0)
        #define MMAF(Ab, Bb) do { \
            _Pragma("unroll") \
            for (int mi = 0; mi < 4; ++mi) \
                _Pragma("unroll") \
                for (int ni = 0; ni < 8; ++ni) \
                    mma16816(acc[mi][ni], Ab[mi], &Bb[ni >> 1][(ni & 1) << 1]); \
        } while (0)

        LDF(A0, B0, 0);
        LDF(A1, B1, 32);
        MMAF(A0, B0);
        LDF(A0, B0, 64);
        MMAF(A1, B1);
        LDF(A1, B1, 96);
        MMAF(A0, B0);
        MMAF(A1, B1);
        #undef LDF
        #undef MMAF
    }

    float rowsum[4][2];
    #pragma unroll
    for (int mi = 0; mi < 4; ++mi) { rowsum[mi][0] = 0.f; rowsum[mi][1] = 0.f; }

    if (mode == 1) {
        __half* Aout = half ? AoutL : AoutH;
        #pragma unroll
        for (int ni = 0; ni < 8; ++ni) {
            int gc = col0 + warpN + ni * 8 + ((lane & 3) << 1);
            float wh0 = whd[gc], wh1 = whd[gc + 1];
            float wl0 = wld[gc], wl1 = wld[gc + 1];
            float br0 = bhrd[gc], br1 = bhrd[gc + 1];
            float bj0 = bjv[gc], bj1 = bjv[gc + 1];
            float m0 = (wh0 != 0.f) ? 1.f : 0.f, m1 = (wh1 != 0.f) ? 1.f : 0.f;
            #pragma unroll
            for (int mi = 0; mi < 4; ++mi)
                #pragma unroll
                for (int e = 0; e < 2; ++e) {
                    float v0 = acc[mi][ni][2 * e], v1 = acc[mi][ni][2 * e + 1];
                    float t0, t1, s;
                    if (half == 0) {
                        t0 = (v0 > 0.f ? v0 * wh0 : v0 * wl0) * m0;
                        t1 = (v1 > 0.f ? v1 * wh1 : v1 * wl1) * m1;
                        s = fmaxf(v0, 0.f) * m0 * br0 + t0 * bj0 + fmaxf(v1, 0.f) * m1 * br1 + t1 * bj1;
                    } else {
                        t0 = (v0 > 0.f ? v0 * wl0 : v0 * wh0) * m0;
                        t1 = (v1 > 0.f ? v1 * wl1 : v1 * wh1) * m1;
                        s = fminf(v0, 0.f) * m0 * br0 + t0 * bj0 + fminf(v1, 0.f) * m1 * br1 + t1 * bj1;
                    }
                    rowsum[mi][e] += s;
                    int gr = row0 + warpM + mi * 16 + (lane >> 2) + e * 8;
                    *reinterpret_cast<__half2*>(Aout + (size_t)gr * NH + gc) = __floats2half2_rn(t0, t1);
                }
        }
        float* bacc = half ? bl : bh;
        #pragma unroll
        for (int mi = 0; mi < 4; ++mi)
            #pragma unroll
            for (int e = 0; e < 2; ++e) {
                float s = rowsum[mi][e];
                s += __shfl_xor_sync(0xffffffffu, s, 1);
                s += __shfl_xor_sync(0xffffffffu, s, 2);
                if ((lane & 3) == 0) {
                    int gr = row0 + warpM + mi * 16 + (lane >> 2) + e * 8;
                    atomicAdd(&bacc[gr], s);
                }
            }
    } else {
        #pragma unroll
        for (int ni = 0; ni < 8; ++ni) {
            int gc = col0 + warpN + ni * 8 + ((lane & 3) << 1);
            float L0 = (gc < Ng) ? l0[gc] : 0.f;
            float H0 = (gc < Ng) ? h0[gc] : 0.f;
            float L1 = (gc + 1 < Ng) ? l0[gc + 1] : 0.f;
            float H1 = (gc + 1 < Ng) ? h0[gc + 1] : 0.f;
            #pragma unroll
            for (int mi = 0; mi < 4; ++mi)
                #pragma unroll
                for (int e = 0; e < 2; ++e) {
                    float v0 = acc[mi][ni][2 * e], v1 = acc[mi][ni][2 * e + 1];
                    float s;
                    if (half == 0)
                        s = (v0 >= 0.f ? v0 * H0 : v0 * L0) + (v1 >= 0.f ? v1 * H1 : v1 * L1);
                    else
                        s = (v0 >= 0.f ? v0 * L0 : v0 * H0) + (v1 >= 0.f ? v1 * L1 : v1 * H1);
                    rowsum[mi][e] += s;
                }
        }
        float* outv = half ? lowv : highv;
        #pragma unroll
        for (int mi = 0; mi < 4; ++mi)
            #pragma unroll
            for (int e = 0; e < 2; ++e) {
                float s = rowsum[mi][e];
                s += __shfl_xor_sync(0xffffffffu, s, 1);
                s += __shfl_xor_sync(0xffffffffu, s, 2);
                if ((lane & 3) == 0) {
                    int gr = row0 + warpM + mi * 16 + (lane >> 2) + e * 8;
                    atomicAdd(&outv[gr], s);
                }
            }
    }
}

// ---------------- driver ----------------
extern "C" void kernel_launch(void* const* d_in, const int* in_sizes, int n_in,
                              void* d_out, int out_size) {
    const float* x  = (const float*)d_in[0];
    const float* lo = (const float*)d_in[1];
    const float* hi = (const float*)d_in[2];
    const float* W[5];
    const float* b[5];
    for (int i = 0; i < 5; ++i) { W[i] = (const float*)d_in[3 + 2 * i]; b[i] = (const float*)d_in[4 + 2 * i]; }
    float* out = (float*)d_out;

    cudaFuncSetAttribute(hgemm_k, cudaFuncAttributeMaxDynamicSharedMemorySize, GSMEM);

    void* p;
    __half *Af, *WT;
    cudaGetSymbolAddress(&p, g_Af); Af = (__half*)p;
    cudaGetSymbolAddress(&p, g_WT); WT = (__half*)p;
    float* P0;
    cudaGetSymbolAddress(&p, g_part); P0 = (float*)p;
    float* PH[2] = { P0,                      P0 + 2 * 8 * NOUT * NH };
    float* PL[2] = { P0 + 8 * NOUT * NH,      P0 + 3 * 8 * NOUT * NH };
    float *xa, *xb, *lowv, *highv, *wl, *wh, *bhr, *bh, *bl, *x0, *l0, *h0;
    cudaGetSymbolAddress(&p, g_xa);   xa = (float*)p;
    cudaGetSymbolAddress(&p, g_xb);   xb = (float*)p;
    cudaGetSymbolAddress(&p, g_low);  lowv = (float*)p;
    cudaGetSymbolAddress(&p, g_high); highv = (float*)p;
    cudaGetSymbolAddress(&p, g_wl);   wl = (float*)p;
    cudaGetSymbolAddress(&p, g_wh);   wh = (float*)p;
    cudaGetSymbolAddress(&p, g_bhr);  bhr = (float*)p;
    cudaGetSymbolAddress(&p, g_bh);   bh = (float*)p;
    cudaGetSymbolAddress(&p, g_bl);   bl = (float*)p;
    cudaGetSymbolAddress(&p, g_x0);   x0 = (float*)p;
    cudaGetSymbolAddress(&p, g_l0);   l0 = (float*)p;
    cudaGetSymbolAddress(&p, g_h0);   h0 = (float*)p;

    normalize_k<<<(NIN + 255) / 256, 256>>>(x, lo, hi, x0, l0, h0, NIN);

    // all weight transposes in one launch
    wsplit4_k<<<dim3(64, 64, 4), dim3(32, 8)>>>(W[0], W[1], W[2], W[3], WT);

    // layer 0: fused matvec + box
    box0_k<<<NH, 256>>>(W[0], x0, b[0], l0, h0, xa, lowv, highv);
    relu_abs_k<<<NH / 256, 256>>>(xa, lowv, highv, nullptr, nullptr, wl, wh, bhr, NH);

    float* xin = xa;
    float* xout = xb;
    // layers 1..3: fused tensor-core chains
    for (int i = 1; i < 4; ++i) {
        int cur = 0;
        relu_bs_first_k<<<NH, 256>>>(W[i], xin, b[i],
                                     wl + (i - 1) * NH, wh + (i - 1) * NH, bhr + (i - 1) * NH, b[i - 1],
                                     Af, Af + (size_t)NHNH, bh, bl, xout, lowv, highv);
        for (int j = i - 1; j >= 1; --j) {
            __half* Ain = Af + (size_t)cur * 2 * NHNH;
            __half* AoH = Af + (size_t)(cur ^ 1) * 2 * NHNH;
            hgemm_k<<<dim3(16, 16), 256, GSMEM>>>(Ain, WT + (size_t)j * NHNH,
                                                  AoH, AoH + (size_t)NHNH,
                                                  wl + (j - 1) * NH, wh + (j - 1) * NH,
                                                  bhr + (j - 1) * NH, b[j - 1],
                                                  bh, bl, nullptr, nullptr, nullptr, nullptr,
                                                  NH, 1);
            cur ^= 1;
        }
        {
            __half* Ain = Af + (size_t)cur * 2 * NHNH;
            hgemm_k<<<dim3(7, 16), 256, GSMEM>>>(Ain, WT,
                                                 nullptr, nullptr,
                                                 nullptr, nullptr, nullptr, nullptr,
                                                 nullptr, nullptr, l0, h0, lowv, highv,
                                                 NIN, 2);
        }
        relu_abs_k<<<NH / 256, 256>>>(xout, lowv, highv, bh, bl,
                                      wl + i * NH, wh + i * NH, bhr + i * NH, NH);
        float* t = xin; xin = xout; xout = t;
    }

    // layer 4 (M=10): fused fp32 skinny chain
    matvec_k<<<2, 256>>>(W[4], xin, b[4], xout, NOUT, NH);
    initb4_k<<<1, 32>>>(b[4], bh, bl);
    {
        int cur = 0;
        skfuse_k<<<dim3(16, 8), 128>>>(nullptr, nullptr, W[4],
                                       wl + 3 * NH, wh + 3 * NH, bhr + 3 * NH, b[3],
                                       W[3], PH[cur], PL[cur], bh, bl, NH);
        for (int j = 2; j >= 1; --j) {
            skfuse_k<<<dim3(16, 8), 128>>>(PH[cur], PL[cur], nullptr,
                                           wl + j * NH, wh + j * NH, bhr + j * NH, b[j],
                                           W[j], PH[cur ^ 1], PL[cur ^ 1], bh, bl, NH);
            cur ^= 1;
        }
        skfuse_k<<<dim3(7, 8), 128>>>(PH[cur], PL[cur], nullptr,
                                      wl, wh, bhr, b[0],
                                      W[0], PH[cur ^ 1], PL[cur ^ 1], bh, bl, NIN);
        cur ^= 1;
        boxp_k<<<NOUT, 256>>>(PH[cur], PL[cur], bh, bl, l0, h0, lowv, highv);
        write_out_k<<<1, 32>>>(xout, lowv, highv, out);
    }
    (void)in_sizes; (void)n_in; (void)out_size;
}

// round 10
// speedup vs baseline: 8.0794x; 1.0268x over previous
#include <cuda_runtime.h>
#include <cuda_fp16.h>
#include <cstdint>

#define MEANC 0.1307f
#define STDC  0.3081f
#define NIN   784
#define NH    2048
#define NOUT  10
#define NHNH  (NH * NH)

// ---------------- device scratch ----------------
__device__ __half g_Af[4][NHNH];     // buf0: AH,AL ; buf1: AH,AL
__device__ __half g_WT[4][NHNH];     // weight^T fp16
__device__ float g_part[4][8 * NOUT * NH];   // 2 ping-pong sets of (PH, PL)
__device__ float g_xa[NH], g_xb[NH], g_low[NH], g_high[NH];
__device__ float g_wl[4 * NH], g_wh[4 * NH], g_bhr[4 * NH];
__device__ float g_bh[NH], g_bl[NH];
__device__ float g_x0[NIN], g_l0[NIN], g_h0[NIN];

// ---------------- helpers ----------------
__device__ __forceinline__ uint32_t smem_u32(const void* p) {
    uint32_t a;
    asm("{ .reg .u64 t; cvta.to.shared.u64 t, %1; cvt.u32.u64 %0, t; }" : "=r"(a) : "l"(p));
    return a;
}

__device__ __forceinline__ void blkred3(float& a, float& b, float& c) {
    const unsigned F = 0xffffffffu;
    #pragma unroll
    for (int o = 16; o > 0; o >>= 1) {
        a += __shfl_down_sync(F, a, o);
        b += __shfl_down_sync(F, b, o);
        c += __shfl_down_sync(F, c, o);
    }
    __shared__ float sa[8], sb[8], sc[8];
    int w = threadIdx.x >> 5, lane = threadIdx.x & 31;
    if (lane == 0) { sa[w] = a; sb[w] = b; sc[w] = c; }
    __syncthreads();
    if (w == 0) {
        a = (lane < 8) ? sa[lane] : 0.f;
        b = (lane < 8) ? sb[lane] : 0.f;
        c = (lane < 8) ? sc[lane] : 0.f;
        #pragma unroll
        for (int o = 4; o > 0; o >>= 1) {
            a += __shfl_down_sync(F, a, o);
            b += __shfl_down_sync(F, b, o);
            c += __shfl_down_sync(F, c, o);
        }
    }
}

// ---------------- small kernels ----------------
__global__ void normalize_k(const float* x, const float* lo, const float* hi,
                            float* x0, float* l0, float* h0, int n) {
    int i = blockIdx.x * blockDim.x + threadIdx.x;
    if (i < n) {
        x0[i] = (x[i] - MEANC) / STDC;
        l0[i] = (lo[i] - MEANC) / STDC;
        h0[i] = (hi[i] - MEANC) / STDC;
    }
}

__global__ void matvec_k(const float* __restrict__ W, const float* __restrict__ xin,
                         const float* __restrict__ b, float* __restrict__ xout, int M, int K) {
    int row = blockIdx.x * (blockDim.x >> 5) + (threadIdx.x >> 5);
    if (row >= M) return;
    int lane = threadIdx.x & 31;
    float s = 0.f;
    const float* wr = W + (size_t)row * K;
    for (int k = lane; k < K; k += 32) s += wr[k] * xin[k];
    #pragma unroll
    for (int o = 16; o > 0; o >>= 1) s += __shfl_down_sync(0xffffffffu, s, o);
    if (lane == 0) xout[row] = s + b[row];
}

// layer 0 fused: matvec + interval box over W0 (single W0 read)
__global__ void box0_k(const float* __restrict__ W0, const float* __restrict__ x0,
                       const float* __restrict__ b0, const float* __restrict__ l0,
                       const float* __restrict__ h0, float* __restrict__ xa,
                       float* __restrict__ lowv, float* __restrict__ highv) {
    int m = blockIdx.x;
    size_t base = (size_t)m * NIN;
    float sx = 0.f, sh = 0.f, sl = 0.f;
    for (int k = threadIdx.x; k < NIN; k += blockDim.x) {
        float w = W0[base + k];
        float l = l0[k], h = h0[k];
        sx += w * x0[k];
        sh += (w >= 0.f) ? w * h : w * l;
        sl += (w >= 0.f) ? w * l : w * h;
    }
    blkred3(sx, sh, sl);
    if (threadIdx.x == 0) {
        float bb = b0[m];
        xa[m] = sx + bb;
        highv[m] = sh + bb;
        lowv[m] = sl + bb;
    }
}

// chain start: fused matvec + relu-backsub transform of W[i], fp16 A emission.
__global__ void relu_bs_first_k(const float* __restrict__ W, const float* __restrict__ xin,
                                const float* __restrict__ bi,
                                const float* __restrict__ wld, const float* __restrict__ whd,
                                const float* __restrict__ bhrd, const float* __restrict__ bj,
                                __half* __restrict__ AH, __half* __restrict__ AL,
                                float* __restrict__ bh, float* __restrict__ bl,
                                float* __restrict__ xout,
                                float* __restrict__ lowv, float* __restrict__ highv) {
    int m = blockIdx.x;
    size_t base = (size_t)m * NH;
    float sh = 0.f, sl = 0.f, sx = 0.f;
    for (int k = threadIdx.x; k < NH; k += blockDim.x) {
        float whk = whd[k], wlk = wld[k], brk = bhrd[k], bjk = bj[k];
        float mask = (whk != 0.f) ? 1.f : 0.f;
        float w = W[base + k];
        float oh = (w > 0.f ? w * whk : w * wlk) * mask;
        float ol = (w > 0.f ? w * wlk : w * whk) * mask;
        AH[base + k] = __float2half(oh);
        AL[base + k] = __float2half(ol);
        sh += fmaxf(w, 0.f) * mask * brk + oh * bjk;
        sl += fminf(w, 0.f) * mask * brk + ol * bjk;
        sx += w * xin[k];
    }
    blkred3(sh, sl, sx);
    if (threadIdx.x == 0) {
        float bb = bi[m];
        bh[m] = bb + sh;
        bl[m] = bb + sl;
        xout[m] = sx + bb;
        lowv[m] = 0.f;
        highv[m] = 0.f;
    }
}

// relu relaxation; optionally adds bias terms (addbh/addbl) to raw box sums
__global__ void relu_abs_k(float* __restrict__ x, const float* __restrict__ lowv,
                           const float* __restrict__ highv,
                           const float* __restrict__ addbh, const float* __restrict__ addbl,
                           float* __restrict__ wl, float* __restrict__ wh,
                           float* __restrict__ bhr, int n) {
    int i = blockIdx.x * blockDim.x + threadIdx.x;
    if (i >= n) return;
    float l = lowv[i] + (addbl ? addbl[i] : 0.f);
    float h = highv[i] + (addbh ? addbh[i] : 0.f);
    bool cr = (l < 0.f) && (h > 0.f);
    float denom = cr ? (h - l) : 1.f;
    float ubs = cr ? h / denom : 0.f;
    float ubi = cr ? -(l * h) / denom : 0.f;
    float lam = (l * l > h * h) ? 0.f : 1.f;
    float keep = (h <= 0.f) ? 0.f : 1.f;
    wh[i] = cr ? ubs : keep;
    wl[i] = cr ? lam : keep;
    bhr[i] = ubi;
    x[i] = fmaxf(x[i], 0.f);
}

__global__ void write_out_k(const float* x5, const float* lowv, const float* highv, float* out) {
    int i = threadIdx.x;
    if (i < NOUT) { out[i] = x5[i]; out[NOUT + i] = lowv[i]; out[2 * NOUT + i] = highv[i]; }
}

// single-launch transpose of all 4 weights to fp16 (z = weight index)
__global__ void wsplit4_k(const float* __restrict__ W0, const float* __restrict__ W1,
                          const float* __restrict__ W2, const float* __restrict__ W3,
                          __half* __restrict__ WT) {
    int z = blockIdx.z;
    const float* W = (z == 0) ? W0 : (z == 1) ? W1 : (z == 2) ? W2 : W3;
    int fi = (z == 0) ? NIN : NH;
    __half* Th = WT + (size_t)z * NHNH;
    int nb = blockIdx.x * 32;
    if (z == 0 && nb >= 896) return;   // only pad to 896 rows for W0
    __shared__ float t[32][33];
    int tx = threadIdx.x, ty = threadIdx.y;
    int kb = blockIdx.y * 32;
    #pragma unroll
    for (int i = 0; i < 4; ++i) {
        int k = kb + ty + i * 8, n = nb + tx;
        t[ty + i * 8][tx] = (n < fi) ? W[(size_t)k * fi + n] : 0.f;
    }
    __syncthreads();
    #pragma unroll
    for (int i = 0; i < 4; ++i) {
        int n = nb + ty + i * 8, k = kb + tx;
        Th[(size_t)n * NH + k] = __float2half(t[tx][ty + i * 8]);
    }
}

// ---------------- layer-4 fused skinny chain ----------------
__global__ void initb4_k(const float* __restrict__ b4, float* __restrict__ bh, float* __restrict__ bl) {
    int i = threadIdx.x;
    if (i < NOUT) { bh[i] = b4[i]; bl[i] = b4[i]; }
}

__global__ void __launch_bounds__(128) skfuse_k(
    const float* __restrict__ PinH, const float* __restrict__ PinL,
    const float* __restrict__ Wfirst,
    const float* __restrict__ wld, const float* __restrict__ whd,
    const float* __restrict__ bhrd, const float* __restrict__ bj,
    const float* __restrict__ Wj,
    float* __restrict__ PoutH, float* __restrict__ PoutL,
    float* __restrict__ bh, float* __restrict__ bl, int Ng)
{
    __shared__ float sH[NOUT][256], sL[NOUT][256];
    const int t = threadIdx.x;
    const int seg = blockIdx.y;
    const int k0 = seg * 256;
    const bool dobias = (blockIdx.x == 0);
    float bHp[NOUT], bLp[NOUT];
    #pragma unroll
    for (int m = 0; m < NOUT; ++m) { bHp[m] = 0.f; bLp[m] = 0.f; }

    #pragma unroll
    for (int h = 0; h < 2; ++h) {
        int kk = t + h * 128;
        int k = k0 + kk;
        float whk = whd[k], wlk = wld[k], brk = bhrd[k], bjk = bj[k];
        float mask = (whk != 0.f) ? 1.f : 0.f;
        #pragma unroll
        for (int m = 0; m < NOUT; ++m) {
            float aH, aL;
            if (Wfirst) {
                aH = Wfirst[(size_t)m * NH + k];
                aL = aH;
            } else {
                aH = 0.f; aL = 0.f;
                #pragma unroll
                for (int s = 0; s < 8; ++s) {
                    aH += PinH[(size_t)(s * NOUT + m) * NH + k];
                    aL += PinL[(size_t)(s * NOUT + m) * NH + k];
                }
            }
            float oh = (aH > 0.f ? aH * whk : aH * wlk) * mask;
            float ol = (aL > 0.f ? aL * wlk : aL * whk) * mask;
            sH[m][kk] = oh;
            sL[m][kk] = ol;
            if (dobias) {
                bHp[m] += fmaxf(aH, 0.f) * mask * brk + oh * bjk;
                bLp[m] += fminf(aL, 0.f) * mask * brk + ol * bjk;
            }
        }
    }
    __syncthreads();

    if (dobias) {
        #pragma unroll
        for (int m = 0; m < NOUT; ++m) {
            float vH = bHp[m], vL = bLp[m];
            #pragma unroll
            for (int o = 16; o > 0; o >>= 1) {
                vH += __shfl_down_sync(0xffffffffu, vH, o);
                vL += __shfl_down_sync(0xffffffffu, vL, o);
            }
            if ((t & 31) == 0) { atomicAdd(&bh[m], vH); atomicAdd(&bl[m], vL); }
        }
    }

    int n = blockIdx.x * 128 + t;
    if (n < Ng) {
        float aH[NOUT], aL[NOUT];
        #pragma unroll
        for (int m = 0; m < NOUT; ++m) { aH[m] = 0.f; aL[m] = 0.f; }
        for (int kk = 0; kk < 256; ++kk) {
            float w = Wj[(size_t)(k0 + kk) * Ng + n];
            #pragma unroll
            for (int m = 0; m < NOUT; ++m) { aH[m] += sH[m][kk] * w; aL[m] += sL[m][kk] * w; }
        }
        #pragma unroll
        for (int m = 0; m < NOUT; ++m) {
            PoutH[(size_t)(seg * NOUT + m) * NH + n] = aH[m];
            PoutL[(size_t)(seg * NOUT + m) * NH + n] = aL[m];
        }
    }
}

__global__ void boxp_k(const float* __restrict__ PH, const float* __restrict__ PL,
                       const float* __restrict__ bh, const float* __restrict__ bl,
                       const float* __restrict__ l0, const float* __restrict__ h0,
                       float* __restrict__ lowv, float* __restrict__ highv) {
    int m = blockIdx.x;
    float sh = 0.f, sl = 0.f, d = 0.f;
    for (int n = threadIdx.x; n < NIN; n += blockDim.x) {
        float ah = 0.f, al = 0.f;
        #pragma unroll
        for (int s = 0; s < 8; ++s) {
            ah += PH[(size_t)(s * NOUT + m) * NH + n];
            al += PL[(size_t)(s * NOUT + m) * NH + n];
        }
        float l = l0[n], h = h0[n];
        sh += (ah >= 0.f) ? ah * h : ah * l;
        sl += (al >= 0.f) ? al * l : al * h;
    }
    blkred3(sh, sl, d);
    if (threadIdx.x == 0) { highv[m] = bh[m] + sh; lowv[m] = bl[m] + sl; }
}

// ---------------- fused H/L fp16 GEMM with transform/box epilogue ----------------
// k-chunk 128, 2-stage cp.async double buffer, register-level fragment pipelining.
#define ROWB  272                    // 128 fp16 = 256B data + 16B pad (conflict-free ldsm phases)
#define MATB  (128 * ROWB)           // 34816
#define STAGE (3 * MATB)             // 104448 (AH, AL, B)
#define GSMEM (2 * STAGE)            // 208896

__device__ __forceinline__ void ldsm4(uint32_t* r, uint32_t addr) {
    asm volatile("ldmatrix.sync.aligned.m8n8.x4.shared.b16 {%0,%1,%2,%3}, [%4];"
                 : "=r"(r[0]), "=r"(r[1]), "=r"(r[2]), "=r"(r[3]) : "r"(addr));
}
__device__ __forceinline__ void mma16816(float* c, const uint32_t* a, const uint32_t* b) {
    asm volatile(
        "mma.sync.aligned.m16n8k16.row.col.f32.f16.f16.f32 "
        "{%0,%1,%2,%3}, {%4,%5,%6,%7}, {%8,%9}, {%0,%1,%2,%3};"
        : "+f"(c[0]), "+f"(c[1]), "+f"(c[2]), "+f"(c[3])
        : "r"(a[0]), "r"(a[1]), "r"(a[2]), "r"(a[3]), "r"(b[0]), "r"(b[1]));
}

__device__ __forceinline__ void issue_chunk(uint32_t sb, int slot,
                                            const __half* Af, const __half* B,
                                            int row0, int col0, int k0, int tid) {
    uint32_t sbase = sb + slot * STAGE;
    #pragma unroll
    for (int i = 0; i < 24; ++i) {
        int q = tid + (i << 8);
        int mat = q >> 11;           // 0: AH, 1: AL, 2: B  (2048 quads per matrix)
        int r = (q >> 4) & 127;      // row within tile (16 quads per row)
        int g = q & 15;              // 16B chunk within 256B row
        const __half* src;
        int grow;
        if (mat < 2) { src = Af + ((size_t)mat << 22); grow = row0 + r; }
        else         { src = B;                        grow = col0 + r; }
        const void* gp = src + (size_t)grow * NH + k0 + (g << 3);
        uint32_t sp = sbase + mat * MATB + r * ROWB + (g << 4);
        asm volatile("cp.async.cg.shared.global [%0], [%1], 16;" :: "r"(sp), "l"(gp));
    }
    asm volatile("cp.async.commit_group;" ::: "memory");
}

__global__ void __launch_bounds__(256, 1) hgemm_k(const __half* __restrict__ Af,
                                               const __half* __restrict__ B,
                                               __half* __restrict__ AoutH, __half* __restrict__ AoutL,
                                               const float* __restrict__ wld, const float* __restrict__ whd,
                                               const float* __restrict__ bhrd, const float* __restrict__ bjv,
                                               float* __restrict__ bh, float* __restrict__ bl,
                                               const float* __restrict__ l0, const float* __restrict__ h0,
                                               float* __restrict__ lowv, float* __restrict__ highv,
                                               int Ng, int mode) {
    extern __shared__ char smem[];
    const uint32_t sb = smem_u32(smem);
    const int tid = threadIdx.x, lane = tid & 31, wid = tid >> 5;
    const int row0 = blockIdx.y * 128, col0 = blockIdx.x * 128;
    const int half = wid >> 2, wq = wid & 3;
    const int warpM = (wq & 1) << 6, warpN = (wq >> 1) << 6;

    float acc[4][8][4];
    #pragma unroll
    for (int mi = 0; mi < 4; ++mi)
        #pragma unroll
        for (int ni = 0; ni < 8; ++ni)
            #pragma unroll
            for (int e = 0; e < 4; ++e) acc[mi][ni][e] = 0.f;

    issue_chunk(sb, 0, Af, B, row0, col0, 0, tid);

    const uint32_t aoff = (uint32_t)((lane & 15) * ROWB + ((lane >> 4) << 4));
    const uint32_t boff = (uint32_t)(((((lane >> 4) & 1) << 3) + (lane & 7)) * ROWB + (((lane >> 3) & 1) << 4));

    uint32_t A0[4][4], B0[4][4], A1[4][4], B1[4][4];

    const int CHUNKS = 16;
    for (int c = 0; c < CHUNKS; ++c) {
        asm volatile("cp.async.wait_group 0;" ::: "memory");
        __syncthreads();   // chunk c resident; all warps done with slot (c-1)&1
        if (c + 1 < CHUNKS)
            issue_chunk(sb, (c + 1) & 1, Af, B, row0, col0, (c + 1) * 128, tid);

        uint32_t st = sb + (c & 1) * STAGE;
        uint32_t sA = st + half * MATB + warpM * ROWB + aoff;
        uint32_t sB = st + 2 * MATB + warpN * ROWB + boff;

        #define LDF(Ab, Bb, ko) do { \
            _Pragma("unroll") \
            for (int mi = 0; mi < 4; ++mi) ldsm4(Ab[mi], sA + mi * (16 * ROWB) + (ko)); \
            _Pragma("unroll") \
            for (int pi = 0; pi < 4; ++pi) ldsm4(Bb[pi], sB + pi * (16 * ROWB) + (ko)); \
        } while (0)
        #define MMAF(Ab, Bb) do { \
            _Pragma("unroll") \
            for (int mi = 0; mi < 4; ++mi) \
                _Pragma("unroll") \
                for (int ni = 0; ni < 8; ++ni) \
                    mma16816(acc[mi][ni], Ab[mi], &Bb[ni >> 1][(ni & 1) << 1]); \
        } while (0)

        LDF(A0, B0, 0);
        LDF(A1, B1, 32);
        MMAF(A0, B0);
        LDF(A0, B0, 64);
        MMAF(A1, B1);
        LDF(A1, B1, 96);
        MMAF(A0, B0);
        LDF(A0, B0, 128);
        MMAF(A1, B1);
        LDF(A1, B1, 160);
        MMAF(A0, B0);
        LDF(A0, B0, 192);
        MMAF(A1, B1);
        LDF(A1, B1, 224);
        MMAF(A0, B0);
        MMAF(A1, B1);
        #undef LDF
        #undef MMAF
    }

    float rowsum[4][2];
    #pragma unroll
    for (int mi = 0; mi < 4; ++mi) { rowsum[mi][0] = 0.f; rowsum[mi][1] = 0.f; }

    if (mode == 1) {
        __half* Aout = half ? AoutL : AoutH;
        #pragma unroll
        for (int ni = 0; ni < 8; ++ni) {
            int gc = col0 + warpN + ni * 8 + ((lane & 3) << 1);
            float wh0 = whd[gc], wh1 = whd[gc + 1];
            float wl0 = wld[gc], wl1 = wld[gc + 1];
            float br0 = bhrd[gc], br1 = bhrd[gc + 1];
            float bj0 = bjv[gc], bj1 = bjv[gc + 1];
            float m0 = (wh0 != 0.f) ? 1.f : 0.f, m1 = (wh1 != 0.f) ? 1.f : 0.f;
            #pragma unroll
            for (int mi = 0; mi < 4; ++mi)
                #pragma unroll
                for (int e = 0; e < 2; ++e) {
                    float v0 = acc[mi][ni][2 * e], v1 = acc[mi][ni][2 * e + 1];
                    float t0, t1, s;
                    if (half == 0) {
                        t0 = (v0 > 0.f ? v0 * wh0 : v0 * wl0) * m0;
                        t1 = (v1 > 0.f ? v1 * wh1 : v1 * wl1) * m1;
                        s = fmaxf(v0, 0.f) * m0 * br0 + t0 * bj0 + fmaxf(v1, 0.f) * m1 * br1 + t1 * bj1;
                    } else {
                        t0 = (v0 > 0.f ? v0 * wl0 : v0 * wh0) * m0;
                        t1 = (v1 > 0.f ? v1 * wl1 : v1 * wh1) * m1;
                        s = fminf(v0, 0.f) * m0 * br0 + t0 * bj0 + fminf(v1, 0.f) * m1 * br1 + t1 * bj1;
                    }
                    rowsum[mi][e] += s;
                    int gr = row0 + warpM + mi * 16 + (lane >> 2) + e * 8;
                    *reinterpret_cast<__half2*>(Aout + (size_t)gr * NH + gc) = __floats2half2_rn(t0, t1);
                }
        }
        float* bacc = half ? bl : bh;
        #pragma unroll
        for (int mi = 0; mi < 4; ++mi)
            #pragma unroll
            for (int e = 0; e < 2; ++e) {
                float s = rowsum[mi][e];
                s += __shfl_xor_sync(0xffffffffu, s, 1);
                s += __shfl_xor_sync(0xffffffffu, s, 2);
                if ((lane & 3) == 0) {
                    int gr = row0 + warpM + mi * 16 + (lane >> 2) + e * 8;
                    atomicAdd(&bacc[gr], s);
                }
            }
    } else {
        #pragma unroll
        for (int ni = 0; ni < 8; ++ni) {
            int gc = col0 + warpN + ni * 8 + ((lane & 3) << 1);
            float L0 = (gc < Ng) ? l0[gc] : 0.f;
            float H0 = (gc < Ng) ? h0[gc] : 0.f;
            float L1 = (gc + 1 < Ng) ? l0[gc + 1] : 0.f;
            float H1 = (gc + 1 < Ng) ? h0[gc + 1] : 0.f;
            #pragma unroll
            for (int mi = 0; mi < 4; ++mi)
                #pragma unroll
                for (int e = 0; e < 2; ++e) {
                    float v0 = acc[mi][ni][2 * e], v1 = acc[mi][ni][2 * e + 1];
                    float s;
                    if (half == 0)
                        s = (v0 >= 0.f ? v0 * H0 : v0 * L0) + (v1 >= 0.f ? v1 * H1 : v1 * L1);
                    else
                        s = (v0 >= 0.f ? v0 * L0 : v0 * H0) + (v1 >= 0.f ? v1 * L1 : v1 * H1);
                    rowsum[mi][e] += s;
                }
        }
        float* outv = half ? lowv : highv;
        #pragma unroll
        for (int mi = 0; mi < 4; ++mi)
            #pragma unroll
            for (int e = 0; e < 2; ++e) {
                float s = rowsum[mi][e];
                s += __shfl_xor_sync(0xffffffffu, s, 1);
                s += __shfl_xor_sync(0xffffffffu, s, 2);
                if ((lane & 3) == 0) {
                    int gr = row0 + warpM + mi * 16 + (lane >> 2) + e * 8;
                    atomicAdd(&outv[gr], s);
                }
            }
    }
}

// ---------------- driver ----------------
extern "C" void kernel_launch(void* const* d_in, const int* in_sizes, int n_in,
                              void* d_out, int out_size) {
    const float* x  = (const float*)d_in[0];
    const float* lo = (const float*)d_in[1];
    const float* hi = (const float*)d_in[2];
    const float* W[5];
    const float* b[5];
    for (int i = 0; i < 5; ++i) { W[i] = (const float*)d_in[3 + 2 * i]; b[i] = (const float*)d_in[4 + 2 * i]; }
    float* out = (float*)d_out;

    cudaFuncSetAttribute(hgemm_k, cudaFuncAttributeMaxDynamicSharedMemorySize, GSMEM);

    void* p;
    __half *Af, *WT;
    cudaGetSymbolAddress(&p, g_Af); Af = (__half*)p;
    cudaGetSymbolAddress(&p, g_WT); WT = (__half*)p;
    float* P0;
    cudaGetSymbolAddress(&p, g_part); P0 = (float*)p;
    float* PH[2] = { P0,                      P0 + 2 * 8 * NOUT * NH };
    float* PL[2] = { P0 + 8 * NOUT * NH,      P0 + 3 * 8 * NOUT * NH };
    float *xa, *xb, *lowv, *highv, *wl, *wh, *bhr, *bh, *bl, *x0, *l0, *h0;
    cudaGetSymbolAddress(&p, g_xa);   xa = (float*)p;
    cudaGetSymbolAddress(&p, g_xb);   xb = (float*)p;
    cudaGetSymbolAddress(&p, g_low);  lowv = (float*)p;
    cudaGetSymbolAddress(&p, g_high); highv = (float*)p;
    cudaGetSymbolAddress(&p, g_wl);   wl = (float*)p;
    cudaGetSymbolAddress(&p, g_wh);   wh = (float*)p;
    cudaGetSymbolAddress(&p, g_bhr);  bhr = (float*)p;
    cudaGetSymbolAddress(&p, g_bh);   bh = (float*)p;
    cudaGetSymbolAddress(&p, g_bl);   bl = (float*)p;
    cudaGetSymbolAddress(&p, g_x0);   x0 = (float*)p;
    cudaGetSymbolAddress(&p, g_l0);   l0 = (float*)p;
    cudaGetSymbolAddress(&p, g_h0);   h0 = (float*)p;

    normalize_k<<<(NIN + 255) / 256, 256>>>(x, lo, hi, x0, l0, h0, NIN);

    // all weight transposes in one launch
    wsplit4_k<<<dim3(64, 64, 4), dim3(32, 8)>>>(W[0], W[1], W[2], W[3], WT);

    // layer 0: fused matvec + box
    box0_k<<<NH, 256>>>(W[0], x0, b[0], l0, h0, xa, lowv, highv);
    relu_abs_k<<<NH / 256, 256>>>(xa, lowv, highv, nullptr, nullptr, wl, wh, bhr, NH);

    float* xin = xa;
    float* xout = xb;
    // layers 1..3: fused tensor-core chains
    for (int i = 1; i < 4; ++i) {
        int cur = 0;
        relu_bs_first_k<<<NH, 256>>>(W[i], xin, b[i],
                                     wl + (i - 1) * NH, wh + (i - 1) * NH, bhr + (i - 1) * NH, b[i - 1],
                                     Af, Af + (size_t)NHNH, bh, bl, xout, lowv, highv);
        for (int j = i - 1; j >= 1; --j) {
            __half* Ain = Af + (size_t)cur * 2 * NHNH;
            __half* AoH = Af + (size_t)(cur ^ 1) * 2 * NHNH;
            hgemm_k<<<dim3(16, 16), 256, GSMEM>>>(Ain, WT + (size_t)j * NHNH,
                                                  AoH, AoH + (size_t)NHNH,
                                                  wl + (j - 1) * NH, wh + (j - 1) * NH,
                                                  bhr + (j - 1) * NH, b[j - 1],
                                                  bh, bl, nullptr, nullptr, nullptr, nullptr,
                                                  NH, 1);
            cur ^= 1;
        }
        {
            __half* Ain = Af + (size_t)cur * 2 * NHNH;
            hgemm_k<<<dim3(7, 16), 256, GSMEM>>>(Ain, WT,
                                                 nullptr, nullptr,
                                                 nullptr, nullptr, nullptr, nullptr,
                                                 nullptr, nullptr, l0, h0, lowv, highv,
                                                 NIN, 2);
        }
        relu_abs_k<<<NH / 256, 256>>>(xout, lowv, highv, bh, bl,
                                      wl + i * NH, wh + i * NH, bhr + i * NH, NH);
        float* t = xin; xin = xout; xout = t;
    }

    // layer 4 (M=10): fused fp32 skinny chain
    matvec_k<<<2, 256>>>(W[4], xin, b[4], xout, NOUT, NH);
    initb4_k<<<1, 32>>>(b[4], bh, bl);
    {
        int cur = 0;
        skfuse_k<<<dim3(16, 8), 128>>>(nullptr, nullptr, W[4],
                                       wl + 3 * NH, wh + 3 * NH, bhr + 3 * NH, b[3],
                                       W[3], PH[cur], PL[cur], bh, bl, NH);
        for (int j = 2; j >= 1; --j) {
            skfuse_k<<<dim3(16, 8), 128>>>(PH[cur], PL[cur], nullptr,
                                           wl + j * NH, wh + j * NH, bhr + j * NH, b[j],
                                           W[j], PH[cur ^ 1], PL[cur ^ 1], bh, bl, NH);
            cur ^= 1;
        }
        skfuse_k<<<dim3(7, 8), 128>>>(PH[cur], PL[cur], nullptr,
                                      wl, wh, bhr, b[0],
                                      W[0], PH[cur ^ 1], PL[cur ^ 1], bh, bl, NIN);
        cur ^= 1;
        boxp_k<<<NOUT, 256>>>(PH[cur], PL[cur], bh, bl, l0, h0, lowv, highv);
        write_out_k<<<1, 32>>>(xout, lowv, highv, out);
    }
    (void)in_sizes; (void)n_in; (void)out_size;
}

// round 11
// speedup vs baseline: 9.4130x; 1.1651x over previous
#include <cuda_runtime.h>
#include <cuda_fp16.h>
#include <cstdint>

#define MEANC 0.1307f
#define STDC  0.3081f
#define NIN   784
#define NH    2048
#define NOUT  10
#define NHNH  (NH * NH)
#define NSEG  16

// ---------------- device scratch ----------------
__device__ __half g_Af[4][NHNH];     // buf0: AH,AL ; buf1: AH,AL
__device__ __half g_WT[4][NHNH];     // weight^T fp16
__device__ float g_part[2][NSEG * NOUT * NH];
__device__ float g_xa[NH], g_xb[NH], g_low[NH], g_high[NH];
__device__ float g_wl[4 * NH], g_wh[4 * NH], g_bhr[4 * NH];
__device__ float g_bh[NH], g_bl[NH];
__device__ float g_x0[NIN], g_l0[NIN], g_h0[NIN];
__device__ float g_x5[NOUT];
__device__ int   g_cnt;

// ---------------- helpers ----------------
__device__ __forceinline__ uint32_t smem_u32(const void* p) {
    uint32_t a;
    asm("{ .reg .u64 t; cvta.to.shared.u64 t, %1; cvt.u32.u64 %0, t; }" : "=r"(a) : "l"(p));
    return a;
}

__device__ __forceinline__ void blkred3(float& a, float& b, float& c) {
    const unsigned F = 0xffffffffu;
    #pragma unroll
    for (int o = 16; o > 0; o >>= 1) {
        a += __shfl_down_sync(F, a, o);
        b += __shfl_down_sync(F, b, o);
        c += __shfl_down_sync(F, c, o);
    }
    __shared__ float sa[8], sb[8], sc[8];
    int w = threadIdx.x >> 5, lane = threadIdx.x & 31;
    if (lane == 0) { sa[w] = a; sb[w] = b; sc[w] = c; }
    __syncthreads();
    if (w == 0) {
        a = (lane < 8) ? sa[lane] : 0.f;
        b = (lane < 8) ? sb[lane] : 0.f;
        c = (lane < 8) ? sc[lane] : 0.f;
        #pragma unroll
        for (int o = 4; o > 0; o >>= 1) {
            a += __shfl_down_sync(F, a, o);
            b += __shfl_down_sync(F, b, o);
            c += __shfl_down_sync(F, c, o);
        }
    }
}

// DeepPoly relu diag from bounds
__device__ __forceinline__ void mk_diag(float l, float h, float& wlv, float& whv, float& brv) {
    bool cr = (l < 0.f) && (h > 0.f);
    float denom = cr ? (h - l) : 1.f;
    float ubs = cr ? h / denom : 0.f;
    float ubi = cr ? -(l * h) / denom : 0.f;
    float lam = (l * l > h * h) ? 0.f : 1.f;
    float keep = (h <= 0.f) ? 0.f : 1.f;
    whv = cr ? ubs : keep;
    wlv = cr ? lam : keep;
    brv = ubi;
}

// ---------------- small kernels ----------------
__global__ void normalize_k(const float* x, const float* lo, const float* hi,
                            float* x0, float* l0, float* h0, int n) {
    int i = blockIdx.x * blockDim.x + threadIdx.x;
    if (i < n) {
        x0[i] = (x[i] - MEANC) / STDC;
        l0[i] = (lo[i] - MEANC) / STDC;
        h0[i] = (hi[i] - MEANC) / STDC;
    }
}

// layer 0 fused: matvec + interval box + relu-diag + x relu (single W0 read)
__global__ void box0_k(const float* __restrict__ W0, const float* __restrict__ x0,
                       const float* __restrict__ b0, const float* __restrict__ l0,
                       const float* __restrict__ h0, float* __restrict__ xa,
                       float* __restrict__ wl, float* __restrict__ wh,
                       float* __restrict__ bhr) {
    int m = blockIdx.x;
    size_t base = (size_t)m * NIN;
    float sx = 0.f, sh = 0.f, sl = 0.f;
    for (int k = threadIdx.x; k < NIN; k += blockDim.x) {
        float w = W0[base + k];
        float l = l0[k], h = h0[k];
        sx += w * x0[k];
        sh += (w >= 0.f) ? w * h : w * l;
        sl += (w >= 0.f) ? w * l : w * h;
    }
    blkred3(sx, sh, sl);
    if (threadIdx.x == 0) {
        float bb = b0[m];
        float l = sl + bb, h = sh + bb;
        float wlv, whv, brv;
        mk_diag(l, h, wlv, whv, brv);
        wl[m] = wlv; wh[m] = whv; bhr[m] = brv;
        xa[m] = fmaxf(sx + bb, 0.f);
    }
}

// chain start: fused matvec + relu-backsub transform of W[i], fp16 A emission.
// Zeroes lowv/highv for the box atomics, resets the completion counter.
__global__ void relu_bs_first_k(const float* __restrict__ W, const float* __restrict__ xin,
                                const float* __restrict__ bi,
                                const float* __restrict__ wld, const float* __restrict__ whd,
                                const float* __restrict__ bhrd, const float* __restrict__ bj,
                                __half* __restrict__ AH, __half* __restrict__ AL,
                                float* __restrict__ bh, float* __restrict__ bl,
                                float* __restrict__ xout,
                                float* __restrict__ lowv, float* __restrict__ highv,
                                int* __restrict__ cnt) {
    int m = blockIdx.x;
    size_t base = (size_t)m * NH;
    float sh = 0.f, sl = 0.f, sx = 0.f;
    for (int k = threadIdx.x; k < NH; k += blockDim.x) {
        float whk = whd[k], wlk = wld[k], brk = bhrd[k], bjk = bj[k];
        float mask = (whk != 0.f) ? 1.f : 0.f;
        float w = W[base + k];
        float oh = (w > 0.f ? w * whk : w * wlk) * mask;
        float ol = (w > 0.f ? w * wlk : w * whk) * mask;
        AH[base + k] = __float2half(oh);
        AL[base + k] = __float2half(ol);
        sh += fmaxf(w, 0.f) * mask * brk + oh * bjk;
        sl += fminf(w, 0.f) * mask * brk + ol * bjk;
        sx += w * xin[k];
    }
    blkred3(sh, sl, sx);
    if (threadIdx.x == 0) {
        float bb = bi[m];
        bh[m] = bb + sh;
        bl[m] = bb + sl;
        xout[m] = sx + bb;
        lowv[m] = 0.f;
        highv[m] = 0.f;
        if (m == 0) *cnt = 0;
    }
}

// single-launch transpose of all 4 weights to fp16 (z = weight index)
__global__ void wsplit4_k(const float* __restrict__ W0, const float* __restrict__ W1,
                          const float* __restrict__ W2, const float* __restrict__ W3,
                          __half* __restrict__ WT) {
    int z = blockIdx.z;
    const float* W = (z == 0) ? W0 : (z == 1) ? W1 : (z == 2) ? W2 : W3;
    int fi = (z == 0) ? NIN : NH;
    __half* Th = WT + (size_t)z * NHNH;
    int nb = blockIdx.x * 32;
    if (z == 0 && nb >= 896) return;   // only pad to 896 rows for W0
    __shared__ float t[32][33];
    int tx = threadIdx.x, ty = threadIdx.y;
    int kb = blockIdx.y * 32;
    #pragma unroll
    for (int i = 0; i < 4; ++i) {
        int k = kb + ty + i * 8, n = nb + tx;
        t[ty + i * 8][tx] = (n < fi) ? W[(size_t)k * fi + n] : 0.f;
    }
    __syncthreads();
    #pragma unroll
    for (int i = 0; i < 4; ++i) {
        int n = nb + ty + i * 8, k = kb + tx;
        Th[(size_t)n * NH + k] = __float2half(t[tx][ty + i * 8]);
    }
}

// ---------------- layer-4 fused skinny chain ----------------
// One backsub step: reads prev NSEG-seg partials (or W4 direct), relu transform,
// bias atomics (+ layer-4 x-dot when Wfirst), GEMM vs W[j], writes new partials.
__global__ void __launch_bounds__(128) skfuse_k(
    const float* __restrict__ PinH, const float* __restrict__ PinL,
    const float* __restrict__ Wfirst, const float* __restrict__ xq,
    const float* __restrict__ wld, const float* __restrict__ whd,
    const float* __restrict__ bhrd, const float* __restrict__ bj,
    const float* __restrict__ Wj,
    float* __restrict__ PoutH, float* __restrict__ PoutL,
    float* __restrict__ bh, float* __restrict__ bl, float* __restrict__ x5, int Ng)
{
    __shared__ float sH[NOUT][128], sL[NOUT][128];
    const int t = threadIdx.x;
    const int seg = blockIdx.y;
    const int k0 = seg * 128;
    const bool dobias = (blockIdx.x == 0);
    float bHp[NOUT], bLp[NOUT], bXp[NOUT];
    #pragma unroll
    for (int m = 0; m < NOUT; ++m) { bHp[m] = 0.f; bLp[m] = 0.f; bXp[m] = 0.f; }

    {
        int k = k0 + t;
        float whk = whd[k], wlk = wld[k], brk = bhrd[k], bjk = bj[k];
        float mask = (whk != 0.f) ? 1.f : 0.f;
        float xqk = (Wfirst && dobias) ? xq[k] : 0.f;
        #pragma unroll
        for (int m = 0; m < NOUT; ++m) {
            float aH, aL;
            if (Wfirst) {
                aH = Wfirst[(size_t)m * NH + k];
                aL = aH;
            } else {
                aH = 0.f; aL = 0.f;
                #pragma unroll
                for (int s = 0; s < NSEG; ++s) {
                    aH += PinH[(size_t)(s * NOUT + m) * NH + k];
                    aL += PinL[(size_t)(s * NOUT + m) * NH + k];
                }
            }
            float oh = (aH > 0.f ? aH * whk : aH * wlk) * mask;
            float ol = (aL > 0.f ? aL * wlk : aL * whk) * mask;
            sH[m][t] = oh;
            sL[m][t] = ol;
            if (dobias) {
                bHp[m] += fmaxf(aH, 0.f) * mask * brk + oh * bjk;
                bLp[m] += fminf(aL, 0.f) * mask * brk + ol * bjk;
                if (Wfirst) bXp[m] += aH * xqk;
            }
        }
    }
    __syncthreads();

    if (dobias) {
        #pragma unroll
        for (int m = 0; m < NOUT; ++m) {
            float vH = bHp[m], vL = bLp[m], vX = bXp[m];
            #pragma unroll
            for (int o = 16; o > 0; o >>= 1) {
                vH += __shfl_down_sync(0xffffffffu, vH, o);
                vL += __shfl_down_sync(0xffffffffu, vL, o);
                vX += __shfl_down_sync(0xffffffffu, vX, o);
            }
            if ((t & 31) == 0) {
                atomicAdd(&bh[m], vH);
                atomicAdd(&bl[m], vL);
                if (Wfirst) atomicAdd(&x5[m], vX);
            }
        }
    }

    int n = blockIdx.x * 128 + t;
    if (n < Ng) {
        float aH[NOUT], aL[NOUT];
        #pragma unroll
        for (int m = 0; m < NOUT; ++m) { aH[m] = 0.f; aL[m] = 0.f; }
        for (int kk = 0; kk < 128; ++kk) {
            float w = Wj[(size_t)(k0 + kk) * Ng + n];
            #pragma unroll
            for (int m = 0; m < NOUT; ++m) { aH[m] += sH[m][kk] * w; aL[m] += sL[m][kk] * w; }
        }
        #pragma unroll
        for (int m = 0; m < NOUT; ++m) {
            PoutH[(size_t)(seg * NOUT + m) * NH + n] = aH[m];
            PoutL[(size_t)(seg * NOUT + m) * NH + n] = aL[m];
        }
    }
}

// final interval box over the NSEG partials; writes d_out directly
__global__ void boxp_k(const float* __restrict__ PH, const float* __restrict__ PL,
                       const float* __restrict__ bh, const float* __restrict__ bl,
                       const float* __restrict__ l0, const float* __restrict__ h0,
                       const float* __restrict__ x5, float* __restrict__ out) {
    int m = blockIdx.x;
    float sh = 0.f, sl = 0.f, d = 0.f;
    for (int n = threadIdx.x; n < NIN; n += blockDim.x) {
        float ah = 0.f, al = 0.f;
        #pragma unroll
        for (int s = 0; s < NSEG; ++s) {
            ah += PH[(size_t)(s * NOUT + m) * NH + n];
            al += PL[(size_t)(s * NOUT + m) * NH + n];
        }
        float l = l0[n], h = h0[n];
        sh += (ah >= 0.f) ? ah * h : ah * l;
        sl += (al >= 0.f) ? al * l : al * h;
    }
    blkred3(sh, sl, d);
    if (threadIdx.x == 0) {
        out[m] = x5[m];
        out[NOUT + m] = bl[m] + sl;
        out[2 * NOUT + m] = bh[m] + sh;
    }
}

// ---------------- fused H/L fp16 GEMM with transform/box epilogue ----------------
// k-chunk 128, 2-stage cp.async double buffer, register-level fragment pipelining.
#define ROWB  272
#define MATB  (128 * ROWB)
#define STAGE (3 * MATB)
#define GSMEM (2 * STAGE)

__device__ __forceinline__ void ldsm4(uint32_t* r, uint32_t addr) {
    asm volatile("ldmatrix.sync.aligned.m8n8.x4.shared.b16 {%0,%1,%2,%3}, [%4];"
                 : "=r"(r[0]), "=r"(r[1]), "=r"(r[2]), "=r"(r[3]) : "r"(addr));
}
__device__ __forceinline__ void mma16816(float* c, const uint32_t* a, const uint32_t* b) {
    asm volatile(
        "mma.sync.aligned.m16n8k16.row.col.f32.f16.f16.f32 "
        "{%0,%1,%2,%3}, {%4,%5,%6,%7}, {%8,%9}, {%0,%1,%2,%3};"
        : "+f"(c[0]), "+f"(c[1]), "+f"(c[2]), "+f"(c[3])
        : "r"(a[0]), "r"(a[1]), "r"(a[2]), "r"(a[3]), "r"(b[0]), "r"(b[1]));
}

__device__ __forceinline__ void issue_chunk(uint32_t sb, int slot,
                                            const __half* Af, const __half* B,
                                            int row0, int col0, int k0, int tid) {
    uint32_t sbase = sb + slot * STAGE;
    #pragma unroll
    for (int i = 0; i < 24; ++i) {
        int q = tid + (i << 8);
        int mat = q >> 11;
        int r = (q >> 4) & 127;
        int g = q & 15;
        const __half* src;
        int grow;
        if (mat < 2) { src = Af + ((size_t)mat << 22); grow = row0 + r; }
        else         { src = B;                        grow = col0 + r; }
        const void* gp = src + (size_t)grow * NH + k0 + (g << 3);
        uint32_t sp = sbase + mat * MATB + r * ROWB + (g << 4);
        asm volatile("cp.async.cg.shared.global [%0], [%1], 16;" :: "r"(sp), "l"(gp));
    }
    asm volatile("cp.async.commit_group;" ::: "memory");
}

__global__ void __launch_bounds__(256, 1) hgemm_k(const __half* __restrict__ Af,
                                               const __half* __restrict__ B,
                                               __half* __restrict__ AoutH, __half* __restrict__ AoutL,
                                               const float* __restrict__ wld, const float* __restrict__ whd,
                                               const float* __restrict__ bhrd, const float* __restrict__ bjv,
                                               float* __restrict__ bh, float* __restrict__ bl,
                                               const float* __restrict__ l0, const float* __restrict__ h0,
                                               float* __restrict__ lowv, float* __restrict__ highv,
                                               int Ng, int mode,
                                               float* __restrict__ dwl, float* __restrict__ dwh,
                                               float* __restrict__ dbhr, float* __restrict__ xvec,
                                               const float* __restrict__ b4v, float* __restrict__ x5v,
                                               int* __restrict__ cnt) {
    extern __shared__ char smem[];
    const uint32_t sb = smem_u32(smem);
    const int tid = threadIdx.x, lane = tid & 31, wid = tid >> 5;
    const int row0 = blockIdx.y * 128, col0 = blockIdx.x * 128;
    const int half = wid >> 2, wq = wid & 3;
    const int warpM = (wq & 1) << 6, warpN = (wq >> 1) << 6;

    float acc[4][8][4];
    #pragma unroll
    for (int mi = 0; mi < 4; ++mi)
        #pragma unroll
        for (int ni = 0; ni < 8; ++ni)
            #pragma unroll
            for (int e = 0; e < 4; ++e) acc[mi][ni][e] = 0.f;

    issue_chunk(sb, 0, Af, B, row0, col0, 0, tid);

    const uint32_t aoff = (uint32_t)((lane & 15) * ROWB + ((lane >> 4) << 4));
    const uint32_t boff = (uint32_t)(((((lane >> 4) & 1) << 3) + (lane & 7)) * ROWB + (((lane >> 3) & 1) << 4));

    uint32_t A0[4][4], B0[4][4], A1[4][4], B1[4][4];

    const int CHUNKS = 16;
    for (int c = 0; c < CHUNKS; ++c) {
        asm volatile("cp.async.wait_group 0;" ::: "memory");
        __syncthreads();
        if (c + 1 < CHUNKS)
            issue_chunk(sb, (c + 1) & 1, Af, B, row0, col0, (c + 1) * 128, tid);

        uint32_t st = sb + (c & 1) * STAGE;
        uint32_t sA = st + half * MATB + warpM * ROWB + aoff;
        uint32_t sB = st + 2 * MATB + warpN * ROWB + boff;

        #define LDF(Ab, Bb, ko) do { \
            _Pragma("unroll") \
            for (int mi = 0; mi < 4; ++mi) ldsm4(Ab[mi], sA + mi * (16 * ROWB) + (ko)); \
            _Pragma("unroll") \
            for (int pi = 0; pi < 4; ++pi) ldsm4(Bb[pi], sB + pi * (16 * ROWB) + (ko)); \
        } while (0)
        #define MMAF(Ab, Bb) do { \
            _Pragma("unroll") \
            for (int mi = 0; mi < 4; ++mi) \
                _Pragma("unroll") \
                for (int ni = 0; ni < 8; ++ni) \
                    mma16816(acc[mi][ni], Ab[mi], &Bb[ni >> 1][(ni & 1) << 1]); \
        } while (0)

        LDF(A0, B0, 0);
        LDF(A1, B1, 32);
        MMAF(A0, B0);
        LDF(A0, B0, 64);
        MMAF(A1, B1);
        LDF(A1, B1, 96);
        MMAF(A0, B0);
        LDF(A0, B0, 128);
        MMAF(A1, B1);
        LDF(A1, B1, 160);
        MMAF(A0, B0);
        LDF(A0, B0, 192);
        MMAF(A1, B1);
        LDF(A1, B1, 224);
        MMAF(A0, B0);
        MMAF(A1, B1);
        #undef LDF
        #undef MMAF
    }

    float rowsum[4][2];
    #pragma unroll
    for (int mi = 0; mi < 4; ++mi) { rowsum[mi][0] = 0.f; rowsum[mi][1] = 0.f; }

    if (mode == 1) {
        __half* Aout = half ? AoutL : AoutH;
        #pragma unroll
        for (int ni = 0; ni < 8; ++ni) {
            int gc = col0 + warpN + ni * 8 + ((lane & 3) << 1);
            float wh0 = whd[gc], wh1 = whd[gc + 1];
            float wl0 = wld[gc], wl1 = wld[gc + 1];
            float br0 = bhrd[gc], br1 = bhrd[gc + 1];
            float bj0 = bjv[gc], bj1 = bjv[gc + 1];
            float m0 = (wh0 != 0.f) ? 1.f : 0.f, m1 = (wh1 != 0.f) ? 1.f : 0.f;
            #pragma unroll
            for (int mi = 0; mi < 4; ++mi)
                #pragma unroll
                for (int e = 0; e < 2; ++e) {
                    float v0 = acc[mi][ni][2 * e], v1 = acc[mi][ni][2 * e + 1];
                    float t0, t1, s;
                    if (half == 0) {
                        t0 = (v0 > 0.f ? v0 * wh0 : v0 * wl0) * m0;
                        t1 = (v1 > 0.f ? v1 * wh1 : v1 * wl1) * m1;
                        s = fmaxf(v0, 0.f) * m0 * br0 + t0 * bj0 + fmaxf(v1, 0.f) * m1 * br1 + t1 * bj1;
                    } else {
                        t0 = (v0 > 0.f ? v0 * wl0 : v0 * wh0) * m0;
                        t1 = (v1 > 0.f ? v1 * wl1 : v1 * wh1) * m1;
                        s = fminf(v0, 0.f) * m0 * br0 + t0 * bj0 + fminf(v1, 0.f) * m1 * br1 + t1 * bj1;
                    }
                    rowsum[mi][e] += s;
                    int gr = row0 + warpM + mi * 16 + (lane >> 2) + e * 8;
                    *reinterpret_cast<__half2*>(Aout + (size_t)gr * NH + gc) = __floats2half2_rn(t0, t1);
                }
        }
        float* bacc = half ? bl : bh;
        #pragma unroll
        for (int mi = 0; mi < 4; ++mi)
            #pragma unroll
            for (int e = 0; e < 2; ++e) {
                float s = rowsum[mi][e];
                s += __shfl_xor_sync(0xffffffffu, s, 1);
                s += __shfl_xor_sync(0xffffffffu, s, 2);
                if ((lane & 3) == 0) {
                    int gr = row0 + warpM + mi * 16 + (lane >> 2) + e * 8;
                    atomicAdd(&bacc[gr], s);
                }
            }
    } else {
        #pragma unroll
        for (int ni = 0; ni < 8; ++ni) {
            int gc = col0 + warpN + ni * 8 + ((lane & 3) << 1);
            float L0 = (gc < Ng) ? l0[gc] : 0.f;
            float H0 = (gc < Ng) ? h0[gc] : 0.f;
            float L1 = (gc + 1 < Ng) ? l0[gc + 1] : 0.f;
            float H1 = (gc + 1 < Ng) ? h0[gc + 1] : 0.f;
            #pragma unroll
            for (int mi = 0; mi < 4; ++mi)
                #pragma unroll
                for (int e = 0; e < 2; ++e) {
                    float v0 = acc[mi][ni][2 * e], v1 = acc[mi][ni][2 * e + 1];
                    float s;
                    if (half == 0)
                        s = (v0 >= 0.f ? v0 * H0 : v0 * L0) + (v1 >= 0.f ? v1 * H1 : v1 * L1);
                    else
                        s = (v0 >= 0.f ? v0 * L0 : v0 * H0) + (v1 >= 0.f ? v1 * L1 : v1 * H1);
                    rowsum[mi][e] += s;
                }
        }
        float* outv = half ? lowv : highv;
        #pragma unroll
        for (int mi = 0; mi < 4; ++mi)
            #pragma unroll
            for (int e = 0; e < 2; ++e) {
                float s = rowsum[mi][e];
                s += __shfl_xor_sync(0xffffffffu, s, 1);
                s += __shfl_xor_sync(0xffffffffu, s, 2);
                if ((lane & 3) == 0) {
                    int gr = row0 + warpM + mi * 16 + (lane >> 2) + e * 8;
                    atomicAdd(&outv[gr], s);
                }
            }

        // ---- last-CTA tail: compute relu diag for this layer, relu x, seed layer-4 state ----
        __threadfence();
        __shared__ int lastf;
        if (tid == 0)
            lastf = (atomicAdd(cnt, 1) == (int)(gridDim.x * gridDim.y - 1)) ? 1 : 0;
        __syncthreads();
        if (lastf) {
            __threadfence();
            for (int k = tid; k < NH; k += 256) {
                float l = lowv[k] + bl[k];
                float h = highv[k] + bh[k];
                float wlv, whv, brv;
                mk_diag(l, h, wlv, whv, brv);
                dwl[k] = wlv; dwh[k] = whv; dbhr[k] = brv;
                xvec[k] = fmaxf(xvec[k], 0.f);
            }
            if (b4v) {
                __syncthreads();
                if (tid < NOUT) {
                    bh[tid] = b4v[tid];
                    bl[tid] = b4v[tid];
                    x5v[tid] = b4v[tid];
                }
            }
        }
    }
}

// ---------------- driver ----------------
extern "C" void kernel_launch(void* const* d_in, const int* in_sizes, int n_in,
                              void* d_out, int out_size) {
    const float* x  = (const float*)d_in[0];
    const float* lo = (const float*)d_in[1];
    const float* hi = (const float*)d_in[2];
    const float* W[5];
    const float* b[5];
    for (int i = 0; i < 5; ++i) { W[i] = (const float*)d_in[3 + 2 * i]; b[i] = (const float*)d_in[4 + 2 * i]; }
    float* out = (float*)d_out;

    cudaFuncSetAttribute(hgemm_k, cudaFuncAttributeMaxDynamicSharedMemorySize, GSMEM);

    void* p;
    __half *Af, *WT;
    cudaGetSymbolAddress(&p, g_Af); Af = (__half*)p;
    cudaGetSymbolAddress(&p, g_WT); WT = (__half*)p;
    float* P0;
    cudaGetSymbolAddress(&p, g_part); P0 = (float*)p;
    // two ping-pong sets; each set is NSEG*NOUT*NH for H and L (split the set in halves)
    float* PH[2] = { P0,                             P0 + (size_t)NSEG * NOUT * NH };
    float* PL[2] = { P0 + (size_t)NSEG * NOUT * NH / 2, P0 + (size_t)NSEG * NOUT * NH + (size_t)NSEG * NOUT * NH / 2 };
    // NOTE: PH/PL layout must not overlap: recompute cleanly below
    PH[0] = P0;
    PL[0] = P0 + (size_t)(NSEG / 2) * NOUT * NH;  // placeholder, fixed below
    // use simple quarters of g_part[2][NSEG*NOUT*NH]:
    {
        size_t q = (size_t)NSEG * NOUT * NH;  // one full set (H or L)
        // g_part has 2*q floats total -> need 4 regions of q/... adjust: use halves of each set
        // Each P region needs NSEG*NOUT*NH floats; g_part total = 2*q. So ping-pong H/L share:
        // set0: PH[0]=P0[0..q/2), PL[0]=P0[q/2..q) is too small. Instead alias with g_Af (unused during skinny).
        PH[0] = P0;
        PL[0] = P0 + q;
        PH[1] = (float*)Af;                 // g_Af is 64 MB, free during layer-4 chain
        PL[1] = (float*)Af + q;
    }
    float *xa, *xb, *lowv, *highv, *wl, *wh, *bhr, *bh, *bl, *x0, *l0, *h0, *x5;
    int* cnt;
    cudaGetSymbolAddress(&p, g_xa);   xa = (float*)p;
    cudaGetSymbolAddress(&p, g_xb);   xb = (float*)p;
    cudaGetSymbolAddress(&p, g_low);  lowv = (float*)p;
    cudaGetSymbolAddress(&p, g_high); highv = (float*)p;
    cudaGetSymbolAddress(&p, g_wl);   wl = (float*)p;
    cudaGetSymbolAddress(&p, g_wh);   wh = (float*)p;
    cudaGetSymbolAddress(&p, g_bhr);  bhr = (float*)p;
    cudaGetSymbolAddress(&p, g_bh);   bh = (float*)p;
    cudaGetSymbolAddress(&p, g_bl);   bl = (float*)p;
    cudaGetSymbolAddress(&p, g_x0);   x0 = (float*)p;
    cudaGetSymbolAddress(&p, g_l0);   l0 = (float*)p;
    cudaGetSymbolAddress(&p, g_h0);   h0 = (float*)p;
    cudaGetSymbolAddress(&p, g_x5);   x5 = (float*)p;
    cudaGetSymbolAddress(&p, g_cnt);  cnt = (int*)p;

    normalize_k<<<(NIN + 255) / 256, 256>>>(x, lo, hi, x0, l0, h0, NIN);
    wsplit4_k<<<dim3(64, 64, 4), dim3(32, 8)>>>(W[0], W[1], W[2], W[3], WT);

    // layer 0: fused matvec + box + diag0 + relu(x)
    box0_k<<<NH, 256>>>(W[0], x0, b[0], l0, h0, xa, wl, wh, bhr);

    float* xin = xa;
    float* xout = xb;
    // layers 1..3: fused tensor-core chains; box GEMM tail computes diag(i) + relu(x)
    for (int i = 1; i < 4; ++i) {
        int cur = 0;
        relu_bs_first_k<<<NH, 256>>>(W[i], xin, b[i],
                                     wl + (i - 1) * NH, wh + (i - 1) * NH, bhr + (i - 1) * NH, b[i - 1],
                                     Af, Af + (size_t)NHNH, bh, bl, xout, lowv, highv, cnt);
        for (int j = i - 1; j >= 1; --j) {
            __half* Ain = Af + (size_t)cur * 2 * NHNH;
            __half* AoH = Af + (size_t)(cur ^ 1) * 2 * NHNH;
            hgemm_k<<<dim3(16, 16), 256, GSMEM>>>(Ain, WT + (size_t)j * NHNH,
                                                  AoH, AoH + (size_t)NHNH,
                                                  wl + (j - 1) * NH, wh + (j - 1) * NH,
                                                  bhr + (j - 1) * NH, b[j - 1],
                                                  bh, bl, nullptr, nullptr, nullptr, nullptr,
                                                  NH, 1,
                                                  nullptr, nullptr, nullptr, nullptr,
                                                  nullptr, nullptr, nullptr);
            cur ^= 1;
        }
        {
            __half* Ain = Af + (size_t)cur * 2 * NHNH;
            hgemm_k<<<dim3(7, 16), 256, GSMEM>>>(Ain, WT,
                                                 nullptr, nullptr,
                                                 nullptr, nullptr, nullptr, nullptr,
                                                 bh, bl, l0, h0, lowv, highv,
                                                 NIN, 2,
                                                 wl + i * NH, wh + i * NH, bhr + i * NH, xout,
                                                 (i == 3) ? b[4] : nullptr, x5, cnt);
        }
        float* t = xin; xin = xout; xout = t;
    }

    // layer 4 (M=10): fused fp32 skinny chain (bh/bl/x5 seeded by chain-3 box tail)
    {
        int cur = 0;
        skfuse_k<<<dim3(16, NSEG), 128>>>(nullptr, nullptr, W[4], xin,
                                          wl + 3 * NH, wh + 3 * NH, bhr + 3 * NH, b[3],
                                          W[3], PH[cur], PL[cur], bh, bl, x5, NH);
        for (int j = 2; j >= 1; --j) {
            skfuse_k<<<dim3(16, NSEG), 128>>>(PH[cur], PL[cur], nullptr, nullptr,
                                              wl + j * NH, wh + j * NH, bhr + j * NH, b[j],
                                              W[j], PH[cur ^ 1], PL[cur ^ 1], bh, bl, x5, NH);
            cur ^= 1;
        }
        skfuse_k<<<dim3(7, NSEG), 128>>>(PH[cur], PL[cur], nullptr, nullptr,
                                         wl, wh, bhr, b[0],
                                         W[0], PH[cur ^ 1], PL[cur ^ 1], bh, bl, x5, NIN);
        cur ^= 1;
        boxp_k<<<NOUT, 256>>>(PH[cur], PL[cur], bh, bl, l0, h0, x5, out);
    }
    (void)in_sizes; (void)n_in; (void)out_size;
}